// round 1
// baseline (speedup 1.0000x reference)
#include <cuda_runtime.h>
#include <math.h>

// Problem constants (EncoderLayer: B=2, S=2048, D=768, H=3072, 12 heads x 64)
#define BATCH 2
#define SEQ 2048
#define NTOK (BATCH * SEQ)          // 4096
#define DMODEL 768
#define DHID 3072
#define NHEADS 12
#define DHEAD 64
#define LN_EPS 1e-7f

// ---------------- scratch (no allocations allowed) ----------------
__device__ float g_h[NTOK * DMODEL];     // ln1 output
__device__ float g_q[NTOK * DMODEL];
__device__ float g_k[NTOK * DMODEL];
__device__ float g_v[NTOK * DMODEL];
__device__ float g_ctx[NTOK * DMODEL];
__device__ float g_res1[NTOK * DMODEL];  // x + attn_out
__device__ float g_h2[NTOK * DMODEL];    // ln2 output
__device__ float g_mid[NTOK * DHID];     // relu(h2 @ W1)

// ---------------- LayerNorm (ddof=1, (x-mean)/(std+eps)) ----------------
__global__ void layernorm_kernel(const float* __restrict__ x,
                                 const float* __restrict__ gamma,
                                 const float* __restrict__ beta,
                                 float* __restrict__ y) {
    // one block (256 threads) per row of 768
    int row = blockIdx.x;
    int tid = threadIdx.x;
    const float* xr = x + (size_t)row * DMODEL;

    float v0 = xr[tid];
    float v1 = xr[tid + 256];
    float v2 = xr[tid + 512];

    float sum = v0 + v1 + v2;
    float ss  = v0 * v0 + v1 * v1 + v2 * v2;

    #pragma unroll
    for (int o = 16; o > 0; o >>= 1) {
        sum += __shfl_xor_sync(0xffffffffu, sum, o);
        ss  += __shfl_xor_sync(0xffffffffu, ss, o);
    }
    __shared__ float wsum[8], wss[8];
    int warp = tid >> 5, lane = tid & 31;
    if (lane == 0) { wsum[warp] = sum; wss[warp] = ss; }
    __syncthreads();
    float tot = 0.f, tots = 0.f;
    #pragma unroll
    for (int w = 0; w < 8; w++) { tot += wsum[w]; tots += wss[w]; }

    float mean = tot * (1.0f / DMODEL);
    float var  = (tots - tot * tot * (1.0f / DMODEL)) * (1.0f / (DMODEL - 1));
    var = fmaxf(var, 0.0f);
    float inv = 1.0f / (sqrtf(var) + LN_EPS);

    float* yr = y + (size_t)row * DMODEL;
    yr[tid]       = gamma[tid]       * (v0 - mean) * inv + beta[tid];
    yr[tid + 256] = gamma[tid + 256] * (v1 - mean) * inv + beta[tid + 256];
    yr[tid + 512] = gamma[tid + 512] * (v2 - mean) * inv + beta[tid + 512];
}

// ---------------- Tiled fp32 GEMM: C = op(A@B [+ Cadd]) ----------------
// A: MxK row-major, B: KxN row-major. BM=BN=64, BK=16, 256 threads, 4x4 microtile.
template <bool RELU, bool ADD>
__global__ void gemm_kernel(const float* __restrict__ A, const float* __restrict__ B,
                            const float* __restrict__ Cadd, float* __restrict__ C,
                            int M, int N, int K) {
    const int BM = 64, BN = 64, BK = 16;
    __shared__ float As[BM][BK];
    __shared__ float Bs[BK][BN];

    int tid = threadIdx.x;              // 256
    int tx = tid & 15;                  // N direction (16)
    int ty = tid >> 4;                  // M direction (16)
    int m0 = blockIdx.y * BM;
    int n0 = blockIdx.x * BN;

    float acc[4][4] = {};

    for (int k0 = 0; k0 < K; k0 += BK) {
        #pragma unroll
        for (int i = 0; i < 4; i++) {
            int l = tid + 256 * i;          // 0..1023
            int m = l >> 4, kk = l & 15;
            As[m][kk] = A[(size_t)(m0 + m) * K + k0 + kk];
        }
        #pragma unroll
        for (int i = 0; i < 4; i++) {
            int l = tid + 256 * i;
            int kk = l >> 6, n = l & 63;
            Bs[kk][n] = B[(size_t)(k0 + kk) * N + n0 + n];
        }
        __syncthreads();

        #pragma unroll
        for (int kk = 0; kk < BK; kk++) {
            float a0 = As[ty * 4 + 0][kk];
            float a1 = As[ty * 4 + 1][kk];
            float a2 = As[ty * 4 + 2][kk];
            float a3 = As[ty * 4 + 3][kk];
            float4 bv = *(const float4*)&Bs[kk][tx * 4];
            acc[0][0] += a0 * bv.x; acc[0][1] += a0 * bv.y; acc[0][2] += a0 * bv.z; acc[0][3] += a0 * bv.w;
            acc[1][0] += a1 * bv.x; acc[1][1] += a1 * bv.y; acc[1][2] += a1 * bv.z; acc[1][3] += a1 * bv.w;
            acc[2][0] += a2 * bv.x; acc[2][1] += a2 * bv.y; acc[2][2] += a2 * bv.z; acc[2][3] += a2 * bv.w;
            acc[3][0] += a3 * bv.x; acc[3][1] += a3 * bv.y; acc[3][2] += a3 * bv.z; acc[3][3] += a3 * bv.w;
        }
        __syncthreads();
    }

    #pragma unroll
    for (int i = 0; i < 4; i++) {
        size_t off = (size_t)(m0 + ty * 4 + i) * N + n0 + tx * 4;
        float4 c = make_float4(acc[i][0], acc[i][1], acc[i][2], acc[i][3]);
        if (ADD) {
            float4 r = *(const float4*)&Cadd[off];
            c.x += r.x; c.y += r.y; c.z += r.z; c.w += r.w;
        }
        if (RELU) {
            c.x = fmaxf(c.x, 0.f); c.y = fmaxf(c.y, 0.f);
            c.z = fmaxf(c.z, 0.f); c.w = fmaxf(c.w, 0.f);
        }
        *(float4*)&C[off] = c;
    }
}

// ---------------- Flash attention (fp32, online softmax) ----------------
// grid (SEQ/64, NHEADS, BATCH), 256 threads. Each block: 64 q rows of one (b,h).
// Thread (r = tid/4, c = tid%4): owns q-row r; keys c+4t (t<16) in stage 1,
// output dims c+4j (j<16) in stage 2.
#define ATT_STRIDE 65
__global__ void attn_kernel(const float* __restrict__ Q, const float* __restrict__ K,
                            const float* __restrict__ V, float* __restrict__ O) {
    extern __shared__ float sm[];
    float* Qs = sm;                     // 64 x 65
    float* Ks = sm + 64 * ATT_STRIDE;
    float* Vs = sm + 2 * 64 * ATT_STRIDE;
    float* Ps = sm + 3 * 64 * ATT_STRIDE;

    int tid = threadIdx.x;
    int b = blockIdx.z, h = blockIdx.y;
    int q0 = blockIdx.x * 64;

    const float* qbase = Q + (size_t)b * SEQ * DMODEL + h * DHEAD;
    const float* kbase = K + (size_t)b * SEQ * DMODEL + h * DHEAD;
    const float* vbase = V + (size_t)b * SEQ * DMODEL + h * DHEAD;

    for (int l = tid; l < 64 * 64; l += 256) {
        int r = l >> 6, d = l & 63;
        Qs[r * ATT_STRIDE + d] = qbase[(size_t)(q0 + r) * DMODEL + d];
    }

    int r = tid >> 2, c = tid & 3;
    float m = -1e30f, lsum = 0.f;
    float o[16];
    #pragma unroll
    for (int j = 0; j < 16; j++) o[j] = 0.f;

    for (int j0 = 0; j0 < SEQ; j0 += 64) {
        __syncthreads();   // prior-iter Vs/Ps reads done; Qs ready on iter 0
        for (int l = tid; l < 64 * 64; l += 256) {
            int rr = l >> 6, d = l & 63;
            Ks[rr * ATT_STRIDE + d] = kbase[(size_t)(j0 + rr) * DMODEL + d];
            Vs[rr * ATT_STRIDE + d] = vbase[(size_t)(j0 + rr) * DMODEL + d];
        }
        __syncthreads();

        // stage 1: scores for keys c+4t
        float s[16];
        #pragma unroll
        for (int t = 0; t < 16; t++) s[t] = 0.f;
        for (int d = 0; d < 64; d++) {
            float qd = Qs[r * ATT_STRIDE + d];
            #pragma unroll
            for (int t = 0; t < 16; t++)
                s[t] += qd * Ks[(c + 4 * t) * ATT_STRIDE + d];
        }
        float mt = -1e30f;
        #pragma unroll
        for (int t = 0; t < 16; t++) { s[t] *= 0.125f; mt = fmaxf(mt, s[t]); }
        mt = fmaxf(mt, __shfl_xor_sync(0xffffffffu, mt, 1));
        mt = fmaxf(mt, __shfl_xor_sync(0xffffffffu, mt, 2));
        float mnew = fmaxf(m, mt);
        float alpha = __expf(m - mnew);

        float ls = 0.f;
        #pragma unroll
        for (int t = 0; t < 16; t++) {
            float p = __expf(s[t] - mnew);
            ls += p;
            Ps[r * ATT_STRIDE + c + 4 * t] = p;
        }
        ls += __shfl_xor_sync(0xffffffffu, ls, 1);
        ls += __shfl_xor_sync(0xffffffffu, ls, 2);
        lsum = lsum * alpha + ls;
        m = mnew;
        #pragma unroll
        for (int j = 0; j < 16; j++) o[j] *= alpha;

        __syncthreads();   // Ps written by all threads

        // stage 2: o[d] += sum_k P[r][k] * V[k][d], dims d = c+4j
        for (int kk = 0; kk < 64; kk++) {
            float p = Ps[r * ATT_STRIDE + kk];
            #pragma unroll
            for (int j = 0; j < 16; j++)
                o[j] += p * Vs[kk * ATT_STRIDE + c + 4 * j];
        }
    }

    float inv = 1.0f / lsum;
    float* obase = O + ((size_t)b * SEQ + q0 + r) * DMODEL + h * DHEAD;
    #pragma unroll
    for (int j = 0; j < 16; j++) obase[c + 4 * j] = o[j] * inv;
}

// ---------------- launch ----------------
extern "C" void kernel_launch(void* const* d_in, const int* in_sizes, int n_in,
                              void* d_out, int out_size) {
    const float* x      = (const float*)d_in[0];
    const float* Wq     = (const float*)d_in[1];
    const float* Wk     = (const float*)d_in[2];
    const float* Wv     = (const float*)d_in[3];
    const float* Wo     = (const float*)d_in[4];
    const float* W1     = (const float*)d_in[5];
    const float* W2     = (const float*)d_in[6];
    const float* gamma1 = (const float*)d_in[7];
    const float* beta1  = (const float*)d_in[8];
    const float* gamma2 = (const float*)d_in[9];
    const float* beta2  = (const float*)d_in[10];
    float* out = (float*)d_out;

    float *h, *q, *k, *v, *ctx, *res1, *h2, *mid;
    cudaGetSymbolAddress((void**)&h,    g_h);
    cudaGetSymbolAddress((void**)&q,    g_q);
    cudaGetSymbolAddress((void**)&k,    g_k);
    cudaGetSymbolAddress((void**)&v,    g_v);
    cudaGetSymbolAddress((void**)&ctx,  g_ctx);
    cudaGetSymbolAddress((void**)&res1, g_res1);
    cudaGetSymbolAddress((void**)&h2,   g_h2);
    cudaGetSymbolAddress((void**)&mid,  g_mid);

    const int attn_smem = 4 * 64 * ATT_STRIDE * sizeof(float);  // 66560 B
    cudaFuncSetAttribute(attn_kernel, cudaFuncAttributeMaxDynamicSharedMemorySize, attn_smem);

    // 1. LN1
    layernorm_kernel<<<NTOK, 256>>>(x, gamma1, beta1, h);

    // 2. Q, K, V projections
    dim3 gDD(DMODEL / 64, NTOK / 64);
    gemm_kernel<false, false><<<gDD, 256>>>(h, Wq, nullptr, q, NTOK, DMODEL, DMODEL);
    gemm_kernel<false, false><<<gDD, 256>>>(h, Wk, nullptr, k, NTOK, DMODEL, DMODEL);
    gemm_kernel<false, false><<<gDD, 256>>>(h, Wv, nullptr, v, NTOK, DMODEL, DMODEL);

    // 3. attention
    attn_kernel<<<dim3(SEQ / 64, NHEADS, BATCH), 256, attn_smem>>>(q, k, v, ctx);

    // 4. output projection + residual: res1 = x + ctx @ Wo
    gemm_kernel<false, true><<<gDD, 256>>>(ctx, Wo, x, res1, NTOK, DMODEL, DMODEL);

    // 5. LN2
    layernorm_kernel<<<NTOK, 256>>>(res1, gamma2, beta2, h2);

    // 6. FFN
    gemm_kernel<true, false><<<dim3(DHID / 64, NTOK / 64), 256>>>(h2, W1, nullptr, mid, NTOK, DHID, DMODEL);
    gemm_kernel<false, true><<<gDD, 256>>>(mid, W2, res1, out, NTOK, DMODEL, DHID);
}

// round 2
// speedup vs baseline: 1.4148x; 1.4148x over previous
#include <cuda_runtime.h>
#include <math.h>
#include <stdint.h>

// Problem constants (EncoderLayer: B=2, S=2048, D=768, H=3072, 12 heads x 64)
#define BATCH 2
#define SEQ 2048
#define NTOK (BATCH * SEQ)          // 4096
#define DMODEL 768
#define DHID 3072
#define NHEADS 12
#define DHEAD 64
#define LN_EPS 1e-7f

// ---------------- scratch (no allocations allowed) ----------------
__device__ float g_h[NTOK * DMODEL];     // ln1 output
__device__ float g_q[NTOK * DMODEL];
__device__ float g_k[NTOK * DMODEL];
__device__ float g_v[NTOK * DMODEL];
__device__ float g_ctx[NTOK * DMODEL];
__device__ float g_res1[NTOK * DMODEL];  // x + attn_out
__device__ float g_h2[NTOK * DMODEL];    // ln2 output
__device__ float g_mid[NTOK * DHID];     // relu(h2 @ W1)

// ---------------- LayerNorm (ddof=1, (x-mean)/(std+eps)) ----------------
__global__ void layernorm_kernel(const float* __restrict__ x,
                                 const float* __restrict__ gamma,
                                 const float* __restrict__ beta,
                                 float* __restrict__ y) {
    int row = blockIdx.x;
    int tid = threadIdx.x;
    const float* xr = x + (size_t)row * DMODEL;

    float v0 = xr[tid];
    float v1 = xr[tid + 256];
    float v2 = xr[tid + 512];

    float sum = v0 + v1 + v2;
    float ss  = v0 * v0 + v1 * v1 + v2 * v2;

    #pragma unroll
    for (int o = 16; o > 0; o >>= 1) {
        sum += __shfl_xor_sync(0xffffffffu, sum, o);
        ss  += __shfl_xor_sync(0xffffffffu, ss, o);
    }
    __shared__ float wsum[8], wss[8];
    int warp = tid >> 5, lane = tid & 31;
    if (lane == 0) { wsum[warp] = sum; wss[warp] = ss; }
    __syncthreads();
    float tot = 0.f, tots = 0.f;
    #pragma unroll
    for (int w = 0; w < 8; w++) { tot += wsum[w]; tots += wss[w]; }

    float mean = tot * (1.0f / DMODEL);
    float var  = (tots - tot * tot * (1.0f / DMODEL)) * (1.0f / (DMODEL - 1));
    var = fmaxf(var, 0.0f);
    float inv = 1.0f / (sqrtf(var) + LN_EPS);

    float* yr = y + (size_t)row * DMODEL;
    yr[tid]       = gamma[tid]       * (v0 - mean) * inv + beta[tid];
    yr[tid + 256] = gamma[tid + 256] * (v1 - mean) * inv + beta[tid + 256];
    yr[tid + 512] = gamma[tid + 512] * (v2 - mean) * inv + beta[tid + 512];
}

// ---------------- tf32 tensor-core GEMM ----------------
// C[M,N] = op(A[M,K] @ B[K,N] [+ Cadd]), all row-major fp32 in gmem.
// BM=BN=128, BK=32. 256 threads = 8 warps (4 x 2), warp tile 32x64.
// mma.sync.m16n8k8 tf32, fp32 accumulate. cp.async double-buffered smem.
#define GEMM_SA 36          // A smem row stride (words): (4*row+k)%32 conflict-free
#define GEMM_SB 136         // B smem row stride (words): (8*k+n)%32 conflict-free
#define GEMM_SMEM_WORDS (128 * GEMM_SA + 32 * GEMM_SB)
#define GEMM_SMEM_BYTES (2 * GEMM_SMEM_WORDS * 4)   // 71680

__device__ __forceinline__ uint32_t tf32cvt(float f) {
    uint32_t r;
    asm("cvt.rna.tf32.f32 %0, %1;" : "=r"(r) : "f"(f));
    return r;
}

__device__ __forceinline__ void mma_tf32(float* c, const uint32_t* a, const uint32_t* b) {
    asm volatile(
        "mma.sync.aligned.m16n8k8.row.col.f32.tf32.tf32.f32 "
        "{%0,%1,%2,%3}, {%4,%5,%6,%7}, {%8,%9}, {%0,%1,%2,%3};"
        : "+f"(c[0]), "+f"(c[1]), "+f"(c[2]), "+f"(c[3])
        : "r"(a[0]), "r"(a[1]), "r"(a[2]), "r"(a[3]), "r"(b[0]), "r"(b[1]));
}

#define CP_ASYNC16(dst, src) \
    asm volatile("cp.async.cg.shared.global [%0], [%1], 16;\n" :: "r"(dst), "l"(src))
#define CP_COMMIT() asm volatile("cp.async.commit_group;\n" ::)
#define CP_WAIT(n)  asm volatile("cp.async.wait_group %0;\n" :: "n"(n))

template <bool RELU, bool ADD>
__global__ __launch_bounds__(256, 2)
void gemm_tc(const float* __restrict__ A, const float* __restrict__ B,
             const float* __restrict__ Cadd, float* __restrict__ C,
             int M, int N, int K) {
    extern __shared__ float sm[];
    float* As[2] = { sm, sm + GEMM_SMEM_WORDS };
    float* Bs[2] = { sm + 128 * GEMM_SA, sm + GEMM_SMEM_WORDS + 128 * GEMM_SA };

    int tid = threadIdx.x;
    int m0 = blockIdx.y * 128, n0 = blockIdx.x * 128;
    int warp = tid >> 5, lane = tid & 31;
    int gid = lane >> 2, tig = lane & 3;
    int wm = (warp & 3) * 32, wn = (warp >> 2) * 64;

    float acc[2][8][4] = {};

    // tile loaders (16B cp.async)
    auto load_tiles = [&](float* as, float* bs, int k0) {
        #pragma unroll
        for (int i = 0; i < 4; i++) {
            int c = tid + 256 * i;              // A: 128 rows x 8 chunks
            int row = c >> 3, col = (c & 7) * 4;
            uint32_t dst = (uint32_t)__cvta_generic_to_shared(&as[row * GEMM_SA + col]);
            CP_ASYNC16(dst, A + (size_t)(m0 + row) * K + k0 + col);
        }
        #pragma unroll
        for (int i = 0; i < 4; i++) {
            int c = tid + 256 * i;              // B: 32 rows x 32 chunks
            int row = c >> 5, col = (c & 31) * 4;
            uint32_t dst = (uint32_t)__cvta_generic_to_shared(&bs[row * GEMM_SB + col]);
            CP_ASYNC16(dst, B + (size_t)(k0 + row) * N + n0 + col);
        }
    };

    load_tiles(As[0], Bs[0], 0);
    CP_COMMIT();

    int nIter = K >> 5;
    int cur = 0;
    for (int it = 0; it < nIter; it++) {
        if (it + 1 < nIter) {
            load_tiles(As[cur ^ 1], Bs[cur ^ 1], (it + 1) * 32);
            CP_COMMIT();
            CP_WAIT(1);
        } else {
            CP_WAIT(0);
        }
        __syncthreads();

        const float* as = As[cur];
        const float* bs = Bs[cur];
        #pragma unroll
        for (int kk = 0; kk < 4; kk++) {
            int kb = kk * 8;
            uint32_t a[2][4], b[8][2];
            #pragma unroll
            for (int i = 0; i < 2; i++) {
                int r = wm + i * 16 + gid;
                a[i][0] = tf32cvt(as[r * GEMM_SA + kb + tig]);
                a[i][1] = tf32cvt(as[(r + 8) * GEMM_SA + kb + tig]);
                a[i][2] = tf32cvt(as[r * GEMM_SA + kb + tig + 4]);
                a[i][3] = tf32cvt(as[(r + 8) * GEMM_SA + kb + tig + 4]);
            }
            #pragma unroll
            for (int j = 0; j < 8; j++) {
                int nn = wn + j * 8 + gid;
                b[j][0] = tf32cvt(bs[(kb + tig) * GEMM_SB + nn]);
                b[j][1] = tf32cvt(bs[(kb + tig + 4) * GEMM_SB + nn]);
            }
            #pragma unroll
            for (int i = 0; i < 2; i++)
                #pragma unroll
                for (int j = 0; j < 8; j++)
                    mma_tf32(acc[i][j], a[i], b[j]);
        }
        __syncthreads();
        cur ^= 1;
    }

    // epilogue
    #pragma unroll
    for (int i = 0; i < 2; i++) {
        int r = m0 + wm + i * 16 + gid;
        #pragma unroll
        for (int j = 0; j < 8; j++) {
            int cc = n0 + wn + j * 8 + 2 * tig;
            size_t o0 = (size_t)r * N + cc;
            size_t o1 = (size_t)(r + 8) * N + cc;
            float2 v0 = make_float2(acc[i][j][0], acc[i][j][1]);
            float2 v1 = make_float2(acc[i][j][2], acc[i][j][3]);
            if (ADD) {
                float2 t0 = *(const float2*)&Cadd[o0];
                float2 t1 = *(const float2*)&Cadd[o1];
                v0.x += t0.x; v0.y += t0.y;
                v1.x += t1.x; v1.y += t1.y;
            }
            if (RELU) {
                v0.x = fmaxf(v0.x, 0.f); v0.y = fmaxf(v0.y, 0.f);
                v1.x = fmaxf(v1.x, 0.f); v1.y = fmaxf(v1.y, 0.f);
            }
            *(float2*)&C[o0] = v0;
            *(float2*)&C[o1] = v1;
        }
    }
}

// ---------------- Flash attention (fp32, online softmax) ----------------
#define ATT_STRIDE 65
__global__ void attn_kernel(const float* __restrict__ Q, const float* __restrict__ K,
                            const float* __restrict__ V, float* __restrict__ O) {
    extern __shared__ float smf[];
    float* Qs = smf;                     // 64 x 65
    float* Ks = smf + 64 * ATT_STRIDE;
    float* Vs = smf + 2 * 64 * ATT_STRIDE;
    float* Ps = smf + 3 * 64 * ATT_STRIDE;

    int tid = threadIdx.x;
    int b = blockIdx.z, h = blockIdx.y;
    int q0 = blockIdx.x * 64;

    const float* qbase = Q + (size_t)b * SEQ * DMODEL + h * DHEAD;
    const float* kbase = K + (size_t)b * SEQ * DMODEL + h * DHEAD;
    const float* vbase = V + (size_t)b * SEQ * DMODEL + h * DHEAD;

    for (int l = tid; l < 64 * 64; l += 256) {
        int r = l >> 6, d = l & 63;
        Qs[r * ATT_STRIDE + d] = qbase[(size_t)(q0 + r) * DMODEL + d];
    }

    int r = tid >> 2, c = tid & 3;
    float m = -1e30f, lsum = 0.f;
    float o[16];
    #pragma unroll
    for (int j = 0; j < 16; j++) o[j] = 0.f;

    for (int j0 = 0; j0 < SEQ; j0 += 64) {
        __syncthreads();
        for (int l = tid; l < 64 * 64; l += 256) {
            int rr = l >> 6, d = l & 63;
            Ks[rr * ATT_STRIDE + d] = kbase[(size_t)(j0 + rr) * DMODEL + d];
            Vs[rr * ATT_STRIDE + d] = vbase[(size_t)(j0 + rr) * DMODEL + d];
        }
        __syncthreads();

        float s[16];
        #pragma unroll
        for (int t = 0; t < 16; t++) s[t] = 0.f;
        for (int d = 0; d < 64; d++) {
            float qd = Qs[r * ATT_STRIDE + d];
            #pragma unroll
            for (int t = 0; t < 16; t++)
                s[t] += qd * Ks[(c + 4 * t) * ATT_STRIDE + d];
        }
        float mt = -1e30f;
        #pragma unroll
        for (int t = 0; t < 16; t++) { s[t] *= 0.125f; mt = fmaxf(mt, s[t]); }
        mt = fmaxf(mt, __shfl_xor_sync(0xffffffffu, mt, 1));
        mt = fmaxf(mt, __shfl_xor_sync(0xffffffffu, mt, 2));
        float mnew = fmaxf(m, mt);
        float alpha = __expf(m - mnew);

        float ls = 0.f;
        #pragma unroll
        for (int t = 0; t < 16; t++) {
            float p = __expf(s[t] - mnew);
            ls += p;
            Ps[r * ATT_STRIDE + c + 4 * t] = p;
        }
        ls += __shfl_xor_sync(0xffffffffu, ls, 1);
        ls += __shfl_xor_sync(0xffffffffu, ls, 2);
        lsum = lsum * alpha + ls;
        m = mnew;
        #pragma unroll
        for (int j = 0; j < 16; j++) o[j] *= alpha;

        __syncthreads();

        for (int kk = 0; kk < 64; kk++) {
            float p = Ps[r * ATT_STRIDE + kk];
            #pragma unroll
            for (int j = 0; j < 16; j++)
                o[j] += p * Vs[kk * ATT_STRIDE + c + 4 * j];
        }
    }

    float inv = 1.0f / lsum;
    float* obase = O + ((size_t)b * SEQ + q0 + r) * DMODEL + h * DHEAD;
    #pragma unroll
    for (int j = 0; j < 16; j++) obase[c + 4 * j] = o[j] * inv;
}

// ---------------- launch ----------------
extern "C" void kernel_launch(void* const* d_in, const int* in_sizes, int n_in,
                              void* d_out, int out_size) {
    const float* x      = (const float*)d_in[0];
    const float* Wq     = (const float*)d_in[1];
    const float* Wk     = (const float*)d_in[2];
    const float* Wv     = (const float*)d_in[3];
    const float* Wo     = (const float*)d_in[4];
    const float* W1     = (const float*)d_in[5];
    const float* W2     = (const float*)d_in[6];
    const float* gamma1 = (const float*)d_in[7];
    const float* beta1  = (const float*)d_in[8];
    const float* gamma2 = (const float*)d_in[9];
    const float* beta2  = (const float*)d_in[10];
    float* out = (float*)d_out;

    float *h, *q, *k, *v, *ctx, *res1, *h2, *mid;
    cudaGetSymbolAddress((void**)&h,    g_h);
    cudaGetSymbolAddress((void**)&q,    g_q);
    cudaGetSymbolAddress((void**)&k,    g_k);
    cudaGetSymbolAddress((void**)&v,    g_v);
    cudaGetSymbolAddress((void**)&ctx,  g_ctx);
    cudaGetSymbolAddress((void**)&res1, g_res1);
    cudaGetSymbolAddress((void**)&h2,   g_h2);
    cudaGetSymbolAddress((void**)&mid,  g_mid);

    const int attn_smem = 4 * 64 * ATT_STRIDE * sizeof(float);  // 66560 B
    cudaFuncSetAttribute(attn_kernel, cudaFuncAttributeMaxDynamicSharedMemorySize, attn_smem);
    cudaFuncSetAttribute(gemm_tc<false, false>, cudaFuncAttributeMaxDynamicSharedMemorySize, GEMM_SMEM_BYTES);
    cudaFuncSetAttribute(gemm_tc<false, true>,  cudaFuncAttributeMaxDynamicSharedMemorySize, GEMM_SMEM_BYTES);
    cudaFuncSetAttribute(gemm_tc<true, false>,  cudaFuncAttributeMaxDynamicSharedMemorySize, GEMM_SMEM_BYTES);

    // 1. LN1
    layernorm_kernel<<<NTOK, 256>>>(x, gamma1, beta1, h);

    // 2. Q, K, V projections
    dim3 gDD(DMODEL / 128, NTOK / 128);
    gemm_tc<false, false><<<gDD, 256, GEMM_SMEM_BYTES>>>(h, Wq, nullptr, q, NTOK, DMODEL, DMODEL);
    gemm_tc<false, false><<<gDD, 256, GEMM_SMEM_BYTES>>>(h, Wk, nullptr, k, NTOK, DMODEL, DMODEL);
    gemm_tc<false, false><<<gDD, 256, GEMM_SMEM_BYTES>>>(h, Wv, nullptr, v, NTOK, DMODEL, DMODEL);

    // 3. attention
    attn_kernel<<<dim3(SEQ / 64, NHEADS, BATCH), 256, attn_smem>>>(q, k, v, ctx);

    // 4. output projection + residual: res1 = x + ctx @ Wo
    gemm_tc<false, true><<<gDD, 256, GEMM_SMEM_BYTES>>>(ctx, Wo, x, res1, NTOK, DMODEL, DMODEL);

    // 5. LN2
    layernorm_kernel<<<NTOK, 256>>>(res1, gamma2, beta2, h2);

    // 6. FFN
    gemm_tc<true, false><<<dim3(DHID / 128, NTOK / 128), 256, GEMM_SMEM_BYTES>>>(h2, W1, nullptr, mid, NTOK, DHID, DMODEL);
    gemm_tc<false, true><<<gDD, 256, GEMM_SMEM_BYTES>>>(mid, W2, res1, out, NTOK, DMODEL, DHID);
}

// round 3
// speedup vs baseline: 3.6475x; 2.5781x over previous
#include <cuda_runtime.h>
#include <math.h>
#include <stdint.h>

// Problem constants (EncoderLayer: B=2, S=2048, D=768, H=3072, 12 heads x 64)
#define BATCH 2
#define SEQ 2048
#define NTOK (BATCH * SEQ)          // 4096
#define DMODEL 768
#define DHID 3072
#define NHEADS 12
#define DHEAD 64
#define LN_EPS 1e-7f

// ---------------- scratch (no allocations allowed) ----------------
__device__ float g_h[NTOK * DMODEL];     // ln1 output
__device__ float g_q[NTOK * DMODEL];
__device__ float g_k[NTOK * DMODEL];
__device__ float g_v[NTOK * DMODEL];
__device__ float g_ctx[NTOK * DMODEL];
__device__ float g_res1[NTOK * DMODEL];  // x + attn_out
__device__ float g_h2[NTOK * DMODEL];    // ln2 output
__device__ float g_mid[NTOK * DHID];     // relu(h2 @ W1)

// ---------------- common PTX helpers ----------------
__device__ __forceinline__ uint32_t tf32cvt(float f) {
    uint32_t r;
    asm("cvt.rna.tf32.f32 %0, %1;" : "=r"(r) : "f"(f));
    return r;
}
__device__ __forceinline__ void mma_tf32(float* c, const uint32_t* a, const uint32_t* b) {
    asm volatile(
        "mma.sync.aligned.m16n8k8.row.col.f32.tf32.tf32.f32 "
        "{%0,%1,%2,%3}, {%4,%5,%6,%7}, {%8,%9}, {%0,%1,%2,%3};"
        : "+f"(c[0]), "+f"(c[1]), "+f"(c[2]), "+f"(c[3])
        : "r"(a[0]), "r"(a[1]), "r"(a[2]), "r"(a[3]), "r"(b[0]), "r"(b[1]));
}
#define CP_ASYNC16(dst, src) \
    asm volatile("cp.async.cg.shared.global [%0], [%1], 16;\n" :: "r"(dst), "l"(src))
#define CP_COMMIT() asm volatile("cp.async.commit_group;\n" ::)
#define CP_WAIT(n)  asm volatile("cp.async.wait_group %0;\n" :: "n"(n))

// ---------------- LayerNorm (ddof=1, (x-mean)/(std+eps)) ----------------
__global__ void layernorm_kernel(const float* __restrict__ x,
                                 const float* __restrict__ gamma,
                                 const float* __restrict__ beta,
                                 float* __restrict__ y) {
    int row = blockIdx.x;
    int tid = threadIdx.x;
    const float* xr = x + (size_t)row * DMODEL;

    float v0 = xr[tid];
    float v1 = xr[tid + 256];
    float v2 = xr[tid + 512];

    float sum = v0 + v1 + v2;
    float ss  = v0 * v0 + v1 * v1 + v2 * v2;

    #pragma unroll
    for (int o = 16; o > 0; o >>= 1) {
        sum += __shfl_xor_sync(0xffffffffu, sum, o);
        ss  += __shfl_xor_sync(0xffffffffu, ss, o);
    }
    __shared__ float wsum[8], wss[8];
    int warp = tid >> 5, lane = tid & 31;
    if (lane == 0) { wsum[warp] = sum; wss[warp] = ss; }
    __syncthreads();
    float tot = 0.f, tots = 0.f;
    #pragma unroll
    for (int w = 0; w < 8; w++) { tot += wsum[w]; tots += wss[w]; }

    float mean = tot * (1.0f / DMODEL);
    float var  = (tots - tot * tot * (1.0f / DMODEL)) * (1.0f / (DMODEL - 1));
    var = fmaxf(var, 0.0f);
    float inv = 1.0f / (sqrtf(var) + LN_EPS);

    float* yr = y + (size_t)row * DMODEL;
    yr[tid]       = gamma[tid]       * (v0 - mean) * inv + beta[tid];
    yr[tid + 256] = gamma[tid + 256] * (v1 - mean) * inv + beta[tid + 256];
    yr[tid + 512] = gamma[tid + 512] * (v2 - mean) * inv + beta[tid + 512];
}

// ---------------- tf32 tensor-core GEMM core ----------------
// C[M,N] = op(A[M,K] @ B[K,N] [+ Cadd]) tile at (m0, n0). BM=BN=128, BK=32.
// 256 threads = 8 warps (4 x 2), warp tile 32x64. cp.async double-buffered.
#define GEMM_SA 36
#define GEMM_SB 136
#define GEMM_SMEM_WORDS (128 * GEMM_SA + 32 * GEMM_SB)
#define GEMM_SMEM_BYTES (2 * GEMM_SMEM_WORDS * 4)   // 71680

template <bool RELU, bool ADD>
__device__ __forceinline__
void gemm_core(const float* __restrict__ A, const float* __restrict__ B,
               const float* __restrict__ Cadd, float* __restrict__ C,
               int M, int N, int K, int m0, int n0) {
    extern __shared__ float sm[];
    float* As[2] = { sm, sm + GEMM_SMEM_WORDS };
    float* Bs[2] = { sm + 128 * GEMM_SA, sm + GEMM_SMEM_WORDS + 128 * GEMM_SA };

    int tid = threadIdx.x;
    int warp = tid >> 5, lane = tid & 31;
    int gid = lane >> 2, tig = lane & 3;
    int wm = (warp & 3) * 32, wn = (warp >> 2) * 64;

    float acc[2][8][4] = {};

    auto load_tiles = [&](float* as, float* bs, int k0) {
        #pragma unroll
        for (int i = 0; i < 4; i++) {
            int c = tid + 256 * i;
            int row = c >> 3, col = (c & 7) * 4;
            uint32_t dst = (uint32_t)__cvta_generic_to_shared(&as[row * GEMM_SA + col]);
            CP_ASYNC16(dst, A + (size_t)(m0 + row) * K + k0 + col);
        }
        #pragma unroll
        for (int i = 0; i < 4; i++) {
            int c = tid + 256 * i;
            int row = c >> 5, col = (c & 31) * 4;
            uint32_t dst = (uint32_t)__cvta_generic_to_shared(&bs[row * GEMM_SB + col]);
            CP_ASYNC16(dst, B + (size_t)(k0 + row) * N + n0 + col);
        }
    };

    load_tiles(As[0], Bs[0], 0);
    CP_COMMIT();

    int nIter = K >> 5;
    int cur = 0;
    for (int it = 0; it < nIter; it++) {
        if (it + 1 < nIter) {
            load_tiles(As[cur ^ 1], Bs[cur ^ 1], (it + 1) * 32);
            CP_COMMIT();
            CP_WAIT(1);
        } else {
            CP_WAIT(0);
        }
        __syncthreads();

        const float* as = As[cur];
        const float* bs = Bs[cur];
        #pragma unroll
        for (int kk = 0; kk < 4; kk++) {
            int kb = kk * 8;
            uint32_t a[2][4], b[8][2];
            #pragma unroll
            for (int i = 0; i < 2; i++) {
                int r = wm + i * 16 + gid;
                a[i][0] = tf32cvt(as[r * GEMM_SA + kb + tig]);
                a[i][1] = tf32cvt(as[(r + 8) * GEMM_SA + kb + tig]);
                a[i][2] = tf32cvt(as[r * GEMM_SA + kb + tig + 4]);
                a[i][3] = tf32cvt(as[(r + 8) * GEMM_SA + kb + tig + 4]);
            }
            #pragma unroll
            for (int j = 0; j < 8; j++) {
                int nn = wn + j * 8 + gid;
                b[j][0] = tf32cvt(bs[(kb + tig) * GEMM_SB + nn]);
                b[j][1] = tf32cvt(bs[(kb + tig + 4) * GEMM_SB + nn]);
            }
            #pragma unroll
            for (int i = 0; i < 2; i++)
                #pragma unroll
                for (int j = 0; j < 8; j++)
                    mma_tf32(acc[i][j], a[i], b[j]);
        }
        __syncthreads();
        cur ^= 1;
    }

    #pragma unroll
    for (int i = 0; i < 2; i++) {
        int r = m0 + wm + i * 16 + gid;
        #pragma unroll
        for (int j = 0; j < 8; j++) {
            int cc = n0 + wn + j * 8 + 2 * tig;
            size_t o0 = (size_t)r * N + cc;
            size_t o1 = (size_t)(r + 8) * N + cc;
            float2 v0 = make_float2(acc[i][j][0], acc[i][j][1]);
            float2 v1 = make_float2(acc[i][j][2], acc[i][j][3]);
            if (ADD) {
                float2 t0 = *(const float2*)&Cadd[o0];
                float2 t1 = *(const float2*)&Cadd[o1];
                v0.x += t0.x; v0.y += t0.y;
                v1.x += t1.x; v1.y += t1.y;
            }
            if (RELU) {
                v0.x = fmaxf(v0.x, 0.f); v0.y = fmaxf(v0.y, 0.f);
                v1.x = fmaxf(v1.x, 0.f); v1.y = fmaxf(v1.y, 0.f);
            }
            *(float2*)&C[o0] = v0;
            *(float2*)&C[o1] = v1;
        }
    }
}

template <bool RELU, bool ADD>
__global__ __launch_bounds__(256, 2)
void gemm_tc(const float* __restrict__ A, const float* __restrict__ B,
             const float* __restrict__ Cadd, float* __restrict__ C,
             int M, int N, int K) {
    gemm_core<RELU, ADD>(A, B, Cadd, C, M, N, K, blockIdx.y * 128, blockIdx.x * 128);
}

// Fused QKV: grid.x = 3 * (DMODEL/128); block picks its weight/output.
__global__ __launch_bounds__(256, 2)
void gemm_qkv(const float* __restrict__ A,
              const float* __restrict__ Wq, const float* __restrict__ Wk,
              const float* __restrict__ Wv,
              float* __restrict__ Cq, float* __restrict__ Ck, float* __restrict__ Cv) {
    int nblk = DMODEL / 128;                 // 6
    int which = blockIdx.x / nblk;
    int n0 = (blockIdx.x % nblk) * 128;
    const float* B = (which == 0) ? Wq : (which == 1) ? Wk : Wv;
    float* C = (which == 0) ? Cq : (which == 1) ? Ck : Cv;
    gemm_core<false, false>(A, B, nullptr, C, NTOK, DMODEL, DMODEL, blockIdx.y * 128, n0);
}

// ---------------- tf32 tensor-core flash attention ----------------
// grid (SEQ/64, NHEADS, BATCH), 128 threads = 4 warps; warp owns 16 q-rows.
// Per iteration: 64-key tile. mma.m16n8k8 tf32 for QK^T and P*V.
// Smem stride 68 words => all fragment access patterns bank-conflict-free.
#define AT_STR 68
#define AT_TILE (64 * AT_STR)
#define AT_SMEM_BYTES (5 * AT_TILE * 4)     // 2xK, 2xV, 1x(Q then P) = 87040

__global__ __launch_bounds__(128)
void attn_tc(const float* __restrict__ Q, const float* __restrict__ K,
             const float* __restrict__ V, float* __restrict__ O) {
    extern __shared__ float sma[];
    float* Ks[2] = { sma, sma + AT_TILE };
    float* Vs[2] = { sma + 2 * AT_TILE, sma + 3 * AT_TILE };
    float* QP = sma + 4 * AT_TILE;           // Q tile, then reused as P

    int tid = threadIdx.x;
    int b = blockIdx.z, h = blockIdx.y;
    int q0 = blockIdx.x * 64;
    int warp = tid >> 5, lane = tid & 31;
    int gid = lane >> 2, tig = lane & 3;
    int wm = warp * 16;

    const float* qbase = Q + (size_t)b * SEQ * DMODEL + h * DHEAD;
    const float* kbase = K + (size_t)b * SEQ * DMODEL + h * DHEAD;
    const float* vbase = V + (size_t)b * SEQ * DMODEL + h * DHEAD;

    // stage Q tile (64x64) into smem, then preload per-warp fragments
    for (int i = tid; i < 1024; i += 128) {
        int r = i >> 4, c4 = (i & 15) * 4;
        *(float4*)&QP[r * AT_STR + c4] = *(const float4*)&qbase[(size_t)(q0 + r) * DMODEL + c4];
    }
    // prefetch first K/V tile while Q settles
    auto loadKV = [&](int t, int buf) {
        int j0 = t * 64;
        #pragma unroll
        for (int i = 0; i < 8; i++) {
            int c = tid + 128 * i;
            int r = c >> 4, c4 = (c & 15) * 4;
            uint32_t dk = (uint32_t)__cvta_generic_to_shared(&Ks[buf][r * AT_STR + c4]);
            uint32_t dv = (uint32_t)__cvta_generic_to_shared(&Vs[buf][r * AT_STR + c4]);
            CP_ASYNC16(dk, kbase + (size_t)(j0 + r) * DMODEL + c4);
            CP_ASYNC16(dv, vbase + (size_t)(j0 + r) * DMODEL + c4);
        }
    };
    loadKV(0, 0);
    CP_COMMIT();
    __syncthreads();                          // Q tile visible to all

    uint32_t qf[8][4];
    #pragma unroll
    for (int kb = 0; kb < 8; kb++) {
        int kc = kb * 8;
        qf[kb][0] = tf32cvt(QP[(wm + gid) * AT_STR + kc + tig]);
        qf[kb][1] = tf32cvt(QP[(wm + gid + 8) * AT_STR + kc + tig]);
        qf[kb][2] = tf32cvt(QP[(wm + gid) * AT_STR + kc + tig + 4]);
        qf[kb][3] = tf32cvt(QP[(wm + gid + 8) * AT_STR + kc + tig + 4]);
    }
    // QP rows [wm, wm+16) now warp-private: safe to reuse as P without block sync

    float m0r = -1e30f, m1r = -1e30f, l0 = 0.f, l1 = 0.f;
    float o[8][4] = {};

    const int NT = SEQ / 64;
    int cur = 0;
    for (int t = 0; t < NT; t++) {
        if (t + 1 < NT) {
            loadKV(t + 1, cur ^ 1);
            CP_COMMIT();
            CP_WAIT(1);
        } else {
            CP_WAIT(0);
        }
        __syncthreads();

        const float* ks = Ks[cur];
        const float* vs = Vs[cur];

        // S = Q * K^T (per-warp 16x64)
        float s[8][4] = {};
        #pragma unroll
        for (int kb = 0; kb < 8; kb++) {
            int kc = kb * 8;
            #pragma unroll
            for (int j = 0; j < 8; j++) {
                int nr = j * 8 + gid;
                uint32_t bv[2] = { tf32cvt(ks[nr * AT_STR + kc + tig]),
                                   tf32cvt(ks[nr * AT_STR + kc + tig + 4]) };
                mma_tf32(s[j], qf[kb], bv);
            }
        }

        // scale + row-max (rows gid and gid+8)
        float mx0 = -1e30f, mx1 = -1e30f;
        #pragma unroll
        for (int j = 0; j < 8; j++) {
            s[j][0] *= 0.125f; s[j][1] *= 0.125f; s[j][2] *= 0.125f; s[j][3] *= 0.125f;
            mx0 = fmaxf(mx0, fmaxf(s[j][0], s[j][1]));
            mx1 = fmaxf(mx1, fmaxf(s[j][2], s[j][3]));
        }
        mx0 = fmaxf(mx0, __shfl_xor_sync(0xffffffffu, mx0, 1));
        mx0 = fmaxf(mx0, __shfl_xor_sync(0xffffffffu, mx0, 2));
        mx1 = fmaxf(mx1, __shfl_xor_sync(0xffffffffu, mx1, 1));
        mx1 = fmaxf(mx1, __shfl_xor_sync(0xffffffffu, mx1, 2));

        float mn0 = fmaxf(m0r, mx0), mn1 = fmaxf(m1r, mx1);
        float al0 = __expf(m0r - mn0), al1 = __expf(m1r - mn1);
        m0r = mn0; m1r = mn1;

        float ls0 = 0.f, ls1 = 0.f;
        #pragma unroll
        for (int j = 0; j < 8; j++) {
            float p0 = __expf(s[j][0] - mn0);
            float p1 = __expf(s[j][1] - mn0);
            float p2 = __expf(s[j][2] - mn1);
            float p3 = __expf(s[j][3] - mn1);
            ls0 += p0 + p1; ls1 += p2 + p3;
            *(float2*)&QP[(wm + gid) * AT_STR + j * 8 + 2 * tig]     = make_float2(p0, p1);
            *(float2*)&QP[(wm + gid + 8) * AT_STR + j * 8 + 2 * tig] = make_float2(p2, p3);
        }
        ls0 += __shfl_xor_sync(0xffffffffu, ls0, 1);
        ls0 += __shfl_xor_sync(0xffffffffu, ls0, 2);
        ls1 += __shfl_xor_sync(0xffffffffu, ls1, 1);
        ls1 += __shfl_xor_sync(0xffffffffu, ls1, 2);
        l0 = l0 * al0 + ls0;
        l1 = l1 * al1 + ls1;

        #pragma unroll
        for (int j = 0; j < 8; j++) {
            o[j][0] *= al0; o[j][1] *= al0; o[j][2] *= al1; o[j][3] *= al1;
        }
        __syncwarp();

        // O += P * V (per-warp 16x64)
        #pragma unroll
        for (int kb = 0; kb < 8; kb++) {
            int kc = kb * 8;
            uint32_t a[4] = { tf32cvt(QP[(wm + gid) * AT_STR + kc + tig]),
                              tf32cvt(QP[(wm + gid + 8) * AT_STR + kc + tig]),
                              tf32cvt(QP[(wm + gid) * AT_STR + kc + tig + 4]),
                              tf32cvt(QP[(wm + gid + 8) * AT_STR + kc + tig + 4]) };
            #pragma unroll
            for (int j = 0; j < 8; j++) {
                uint32_t bv[2] = { tf32cvt(vs[(kc + tig) * AT_STR + j * 8 + gid]),
                                   tf32cvt(vs[(kc + tig + 4) * AT_STR + j * 8 + gid]) };
                mma_tf32(o[j], a, bv);
            }
        }
        __syncthreads();
        cur ^= 1;
    }

    float inv0 = 1.0f / l0, inv1 = 1.0f / l1;
    float* ob0 = O + ((size_t)b * SEQ + q0 + wm + gid) * DMODEL + h * DHEAD;
    float* ob1 = O + ((size_t)b * SEQ + q0 + wm + gid + 8) * DMODEL + h * DHEAD;
    #pragma unroll
    for (int j = 0; j < 8; j++) {
        *(float2*)&ob0[j * 8 + 2 * tig] = make_float2(o[j][0] * inv0, o[j][1] * inv0);
        *(float2*)&ob1[j * 8 + 2 * tig] = make_float2(o[j][2] * inv1, o[j][3] * inv1);
    }
}

// ---------------- launch ----------------
extern "C" void kernel_launch(void* const* d_in, const int* in_sizes, int n_in,
                              void* d_out, int out_size) {
    const float* x      = (const float*)d_in[0];
    const float* Wq     = (const float*)d_in[1];
    const float* Wk     = (const float*)d_in[2];
    const float* Wv     = (const float*)d_in[3];
    const float* Wo     = (const float*)d_in[4];
    const float* W1     = (const float*)d_in[5];
    const float* W2     = (const float*)d_in[6];
    const float* gamma1 = (const float*)d_in[7];
    const float* beta1  = (const float*)d_in[8];
    const float* gamma2 = (const float*)d_in[9];
    const float* beta2  = (const float*)d_in[10];
    float* out = (float*)d_out;

    float *h, *q, *k, *v, *ctx, *res1, *h2, *mid;
    cudaGetSymbolAddress((void**)&h,    g_h);
    cudaGetSymbolAddress((void**)&q,    g_q);
    cudaGetSymbolAddress((void**)&k,    g_k);
    cudaGetSymbolAddress((void**)&v,    g_v);
    cudaGetSymbolAddress((void**)&ctx,  g_ctx);
    cudaGetSymbolAddress((void**)&res1, g_res1);
    cudaGetSymbolAddress((void**)&h2,   g_h2);
    cudaGetSymbolAddress((void**)&mid,  g_mid);

    cudaFuncSetAttribute(attn_tc, cudaFuncAttributeMaxDynamicSharedMemorySize, AT_SMEM_BYTES);
    cudaFuncSetAttribute(gemm_tc<false, false>, cudaFuncAttributeMaxDynamicSharedMemorySize, GEMM_SMEM_BYTES);
    cudaFuncSetAttribute(gemm_tc<false, true>,  cudaFuncAttributeMaxDynamicSharedMemorySize, GEMM_SMEM_BYTES);
    cudaFuncSetAttribute(gemm_tc<true, false>,  cudaFuncAttributeMaxDynamicSharedMemorySize, GEMM_SMEM_BYTES);
    cudaFuncSetAttribute(gemm_qkv, cudaFuncAttributeMaxDynamicSharedMemorySize, GEMM_SMEM_BYTES);

    // 1. LN1
    layernorm_kernel<<<NTOK, 256>>>(x, gamma1, beta1, h);

    // 2. fused QKV projection
    gemm_qkv<<<dim3(3 * DMODEL / 128, NTOK / 128), 256, GEMM_SMEM_BYTES>>>(h, Wq, Wk, Wv, q, k, v);

    // 3. attention (tensor-core flash)
    attn_tc<<<dim3(SEQ / 64, NHEADS, BATCH), 128, AT_SMEM_BYTES>>>(q, k, v, ctx);

    // 4. output projection + residual: res1 = x + ctx @ Wo
    dim3 gDD(DMODEL / 128, NTOK / 128);
    gemm_tc<false, true><<<gDD, 256, GEMM_SMEM_BYTES>>>(ctx, Wo, x, res1, NTOK, DMODEL, DMODEL);

    // 5. LN2
    layernorm_kernel<<<NTOK, 256>>>(res1, gamma2, beta2, h2);

    // 6. FFN
    gemm_tc<true, false><<<dim3(DHID / 128, NTOK / 128), 256, GEMM_SMEM_BYTES>>>(h2, W1, nullptr, mid, NTOK, DHID, DMODEL);
    gemm_tc<false, true><<<gDD, 256, GEMM_SMEM_BYTES>>>(mid, W2, res1, out, NTOK, DMODEL, DHID);
}

// round 4
// speedup vs baseline: 4.2892x; 1.1759x over previous
#include <cuda_runtime.h>
#include <math.h>
#include <stdint.h>

// Problem constants (EncoderLayer: B=2, S=2048, D=768, H=3072, 12 heads x 64)
#define BATCH 2
#define SEQ 2048
#define NTOK (BATCH * SEQ)          // 4096
#define DMODEL 768
#define DHID 3072
#define NHEADS 12
#define DHEAD 64
#define LN_EPS 1e-7f

// ---------------- scratch (no allocations allowed) ----------------
__device__ float g_h[NTOK * DMODEL];     // ln1 output (tf32-rounded)
__device__ float g_q[NTOK * DMODEL];
__device__ float g_k[NTOK * DMODEL];
__device__ float g_v[NTOK * DMODEL];
__device__ float g_ctx[NTOK * DMODEL];
__device__ float g_res1[NTOK * DMODEL];  // x + attn_out (full fp32)
__device__ float g_h2[NTOK * DMODEL];    // ln2 output (tf32-rounded)
__device__ float g_mid[NTOK * DHID];     // relu(h2 @ W1) (tf32-rounded)
// tf32-rounded weight copies
__device__ float g_wq[DMODEL * DMODEL];
__device__ float g_wk[DMODEL * DMODEL];
__device__ float g_wv[DMODEL * DMODEL];
__device__ float g_wo[DMODEL * DMODEL];
__device__ float g_w1[DMODEL * DHID];
__device__ float g_w2[DHID * DMODEL];

// ---------------- common PTX helpers ----------------
__device__ __forceinline__ uint32_t tf32cvt(float f) {
    uint32_t r;
    asm("cvt.rna.tf32.f32 %0, %1;" : "=r"(r) : "f"(f));
    return r;
}
__device__ __forceinline__ float rtf(float f) { return __uint_as_float(tf32cvt(f)); }

__device__ __forceinline__ void mma_tf32(float* c, const uint32_t* a, const uint32_t* b) {
    asm volatile(
        "mma.sync.aligned.m16n8k8.row.col.f32.tf32.tf32.f32 "
        "{%0,%1,%2,%3}, {%4,%5,%6,%7}, {%8,%9}, {%0,%1,%2,%3};"
        : "+f"(c[0]), "+f"(c[1]), "+f"(c[2]), "+f"(c[3])
        : "r"(a[0]), "r"(a[1]), "r"(a[2]), "r"(a[3]), "r"(b[0]), "r"(b[1]));
}
#define CP_ASYNC16(dst, src) \
    asm volatile("cp.async.cg.shared.global [%0], [%1], 16;\n" :: "r"(dst), "l"(src))
#define CP_COMMIT() asm volatile("cp.async.commit_group;\n" ::)
#define CP_WAIT(n)  asm volatile("cp.async.wait_group %0;\n" :: "n"(n))

// ---------------- weight rounding (tf32 pre-round) ----------------
__global__ void round_kernel(const float* __restrict__ src, float* __restrict__ dst, int n4) {
    int i = blockIdx.x * blockDim.x + threadIdx.x;
    if (i < n4) {
        float4 v = ((const float4*)src)[i];
        v.x = rtf(v.x); v.y = rtf(v.y); v.z = rtf(v.z); v.w = rtf(v.w);
        ((float4*)dst)[i] = v;
    }
}

// ---------------- LayerNorm (ddof=1), output tf32-rounded ----------------
__global__ void layernorm_kernel(const float* __restrict__ x,
                                 const float* __restrict__ gamma,
                                 const float* __restrict__ beta,
                                 float* __restrict__ y) {
    int row = blockIdx.x;
    int tid = threadIdx.x;
    const float* xr = x + (size_t)row * DMODEL;

    float v0 = xr[tid];
    float v1 = xr[tid + 256];
    float v2 = xr[tid + 512];

    float sum = v0 + v1 + v2;
    float ss  = v0 * v0 + v1 * v1 + v2 * v2;

    #pragma unroll
    for (int o = 16; o > 0; o >>= 1) {
        sum += __shfl_xor_sync(0xffffffffu, sum, o);
        ss  += __shfl_xor_sync(0xffffffffu, ss, o);
    }
    __shared__ float wsum[8], wss[8];
    int warp = tid >> 5, lane = tid & 31;
    if (lane == 0) { wsum[warp] = sum; wss[warp] = ss; }
    __syncthreads();
    float tot = 0.f, tots = 0.f;
    #pragma unroll
    for (int w = 0; w < 8; w++) { tot += wsum[w]; tots += wss[w]; }

    float mean = tot * (1.0f / DMODEL);
    float var  = (tots - tot * tot * (1.0f / DMODEL)) * (1.0f / (DMODEL - 1));
    var = fmaxf(var, 0.0f);
    float inv = 1.0f / (sqrtf(var) + LN_EPS);

    float* yr = y + (size_t)row * DMODEL;
    yr[tid]       = rtf(gamma[tid]       * (v0 - mean) * inv + beta[tid]);
    yr[tid + 256] = rtf(gamma[tid + 256] * (v1 - mean) * inv + beta[tid + 256]);
    yr[tid + 512] = rtf(gamma[tid + 512] * (v2 - mean) * inv + beta[tid + 512]);
}

// ---------------- tf32 tensor-core GEMM core ----------------
// C[M,N] = op(A[M,K] @ B[K,N] [+ Cadd]) tile at (m0, n0). BM=BN=128, BK=32.
// 128 threads = 4 warps (2 x 2), warp tile 64x64. Inputs pre-rounded to tf32:
// fragments are raw bit loads (no cvt in the hot loop). cp.async double-buffered.
#define GEMM_SA 36
#define GEMM_SB 136
#define GEMM_SMEM_WORDS (128 * GEMM_SA + 32 * GEMM_SB)
#define GEMM_SMEM_BYTES (2 * GEMM_SMEM_WORDS * 4)   // 71680

template <bool RELU, bool ADD, bool ROUND>
__device__ __forceinline__
void gemm_core(const float* __restrict__ A, const float* __restrict__ B,
               const float* __restrict__ Cadd, float* __restrict__ C,
               int M, int N, int K, int m0, int n0) {
    extern __shared__ float sm[];
    float* As[2] = { sm, sm + GEMM_SMEM_WORDS };
    float* Bs[2] = { sm + 128 * GEMM_SA, sm + GEMM_SMEM_WORDS + 128 * GEMM_SA };

    int tid = threadIdx.x;                  // 128
    int warp = tid >> 5, lane = tid & 31;
    int gid = lane >> 2, tig = lane & 3;
    int wm = (warp & 1) * 64, wn = (warp >> 1) * 64;

    float acc[4][8][4] = {};

    auto load_tiles = [&](float* as, float* bs, int k0) {
        #pragma unroll
        for (int i = 0; i < 8; i++) {
            int c = tid + 128 * i;              // A: 128 rows x 8 chunks
            int row = c >> 3, col = (c & 7) * 4;
            uint32_t dst = (uint32_t)__cvta_generic_to_shared(&as[row * GEMM_SA + col]);
            CP_ASYNC16(dst, A + (size_t)(m0 + row) * K + k0 + col);
        }
        #pragma unroll
        for (int i = 0; i < 8; i++) {
            int c = tid + 128 * i;              // B: 32 rows x 32 chunks
            int row = c >> 5, col = (c & 31) * 4;
            uint32_t dst = (uint32_t)__cvta_generic_to_shared(&bs[row * GEMM_SB + col]);
            CP_ASYNC16(dst, B + (size_t)(k0 + row) * N + n0 + col);
        }
    };

    load_tiles(As[0], Bs[0], 0);
    CP_COMMIT();

    int nIter = K >> 5;
    int cur = 0;
    for (int it = 0; it < nIter; it++) {
        if (it + 1 < nIter) {
            load_tiles(As[cur ^ 1], Bs[cur ^ 1], (it + 1) * 32);
            CP_COMMIT();
            CP_WAIT(1);
        } else {
            CP_WAIT(0);
        }
        __syncthreads();

        const uint32_t* as = (const uint32_t*)As[cur];
        const uint32_t* bs = (const uint32_t*)Bs[cur];
        #pragma unroll
        for (int kk = 0; kk < 4; kk++) {
            int kb = kk * 8;
            uint32_t a[4][4], b[8][2];
            #pragma unroll
            for (int i = 0; i < 4; i++) {
                int r = wm + i * 16 + gid;
                a[i][0] = as[r * GEMM_SA + kb + tig];
                a[i][1] = as[(r + 8) * GEMM_SA + kb + tig];
                a[i][2] = as[r * GEMM_SA + kb + tig + 4];
                a[i][3] = as[(r + 8) * GEMM_SA + kb + tig + 4];
            }
            #pragma unroll
            for (int j = 0; j < 8; j++) {
                int nn = wn + j * 8 + gid;
                b[j][0] = bs[(kb + tig) * GEMM_SB + nn];
                b[j][1] = bs[(kb + tig + 4) * GEMM_SB + nn];
            }
            #pragma unroll
            for (int i = 0; i < 4; i++)
                #pragma unroll
                for (int j = 0; j < 8; j++)
                    mma_tf32(acc[i][j], a[i], b[j]);
        }
        __syncthreads();
        cur ^= 1;
    }

    #pragma unroll
    for (int i = 0; i < 4; i++) {
        int r = m0 + wm + i * 16 + gid;
        #pragma unroll
        for (int j = 0; j < 8; j++) {
            int cc = n0 + wn + j * 8 + 2 * tig;
            size_t o0 = (size_t)r * N + cc;
            size_t o1 = (size_t)(r + 8) * N + cc;
            float2 v0 = make_float2(acc[i][j][0], acc[i][j][1]);
            float2 v1 = make_float2(acc[i][j][2], acc[i][j][3]);
            if (ADD) {
                float2 t0 = *(const float2*)&Cadd[o0];
                float2 t1 = *(const float2*)&Cadd[o1];
                v0.x += t0.x; v0.y += t0.y;
                v1.x += t1.x; v1.y += t1.y;
            }
            if (RELU) {
                v0.x = fmaxf(v0.x, 0.f); v0.y = fmaxf(v0.y, 0.f);
                v1.x = fmaxf(v1.x, 0.f); v1.y = fmaxf(v1.y, 0.f);
            }
            if (ROUND) {
                v0.x = rtf(v0.x); v0.y = rtf(v0.y);
                v1.x = rtf(v1.x); v1.y = rtf(v1.y);
            }
            *(float2*)&C[o0] = v0;
            *(float2*)&C[o1] = v1;
        }
    }
}

template <bool RELU, bool ADD, bool ROUND>
__global__ __launch_bounds__(128, 2)
void gemm_tc(const float* __restrict__ A, const float* __restrict__ B,
             const float* __restrict__ Cadd, float* __restrict__ C,
             int M, int N, int K) {
    gemm_core<RELU, ADD, ROUND>(A, B, Cadd, C, M, N, K, blockIdx.y * 128, blockIdx.x * 128);
}

// Fused QKV: grid.x = 3 * (DMODEL/128); block picks its weight/output.
__global__ __launch_bounds__(128, 2)
void gemm_qkv(const float* __restrict__ A,
              const float* __restrict__ Wq, const float* __restrict__ Wk,
              const float* __restrict__ Wv,
              float* __restrict__ Cq, float* __restrict__ Ck, float* __restrict__ Cv) {
    int nblk = DMODEL / 128;                 // 6
    int which = blockIdx.x / nblk;
    int n0 = (blockIdx.x % nblk) * 128;
    const float* B = (which == 0) ? Wq : (which == 1) ? Wk : Wv;
    float* C = (which == 0) ? Cq : (which == 1) ? Ck : Cv;
    gemm_core<false, false, true>(A, B, nullptr, C, NTOK, DMODEL, DMODEL, blockIdx.y * 128, n0);
}

// ---------------- tf32 tensor-core flash attention ----------------
// grid (SEQ/64, NHEADS, BATCH), 128 threads = 4 warps; warp owns 16 q-rows.
// Q/K/V are pre-rounded to tf32 -> raw-bit fragment loads. P rounded at store.
#define AT_STR 68
#define AT_TILE (64 * AT_STR)
#define AT_SMEM_BYTES (5 * AT_TILE * 4)     // 2xK, 2xV, 1x(Q then P) = 87040

__global__ __launch_bounds__(128)
void attn_tc(const float* __restrict__ Q, const float* __restrict__ K,
             const float* __restrict__ V, float* __restrict__ O) {
    extern __shared__ float sma[];
    float* Ks[2] = { sma, sma + AT_TILE };
    float* Vs[2] = { sma + 2 * AT_TILE, sma + 3 * AT_TILE };
    float* QP = sma + 4 * AT_TILE;           // Q tile, then reused as P

    int tid = threadIdx.x;
    int b = blockIdx.z, h = blockIdx.y;
    int q0 = blockIdx.x * 64;
    int warp = tid >> 5, lane = tid & 31;
    int gid = lane >> 2, tig = lane & 3;
    int wm = warp * 16;

    const float* qbase = Q + (size_t)b * SEQ * DMODEL + h * DHEAD;
    const float* kbase = K + (size_t)b * SEQ * DMODEL + h * DHEAD;
    const float* vbase = V + (size_t)b * SEQ * DMODEL + h * DHEAD;

    for (int i = tid; i < 1024; i += 128) {
        int r = i >> 4, c4 = (i & 15) * 4;
        *(float4*)&QP[r * AT_STR + c4] = *(const float4*)&qbase[(size_t)(q0 + r) * DMODEL + c4];
    }
    auto loadKV = [&](int t, int buf) {
        int j0 = t * 64;
        #pragma unroll
        for (int i = 0; i < 8; i++) {
            int c = tid + 128 * i;
            int r = c >> 4, c4 = (c & 15) * 4;
            uint32_t dk = (uint32_t)__cvta_generic_to_shared(&Ks[buf][r * AT_STR + c4]);
            uint32_t dv = (uint32_t)__cvta_generic_to_shared(&Vs[buf][r * AT_STR + c4]);
            CP_ASYNC16(dk, kbase + (size_t)(j0 + r) * DMODEL + c4);
            CP_ASYNC16(dv, vbase + (size_t)(j0 + r) * DMODEL + c4);
        }
    };
    loadKV(0, 0);
    CP_COMMIT();
    __syncthreads();

    uint32_t qf[8][4];
    const uint32_t* qpu = (const uint32_t*)QP;
    #pragma unroll
    for (int kb = 0; kb < 8; kb++) {
        int kc = kb * 8;
        qf[kb][0] = qpu[(wm + gid) * AT_STR + kc + tig];
        qf[kb][1] = qpu[(wm + gid + 8) * AT_STR + kc + tig];
        qf[kb][2] = qpu[(wm + gid) * AT_STR + kc + tig + 4];
        qf[kb][3] = qpu[(wm + gid + 8) * AT_STR + kc + tig + 4];
    }

    float m0r = -1e30f, m1r = -1e30f, l0 = 0.f, l1 = 0.f;
    float o[8][4] = {};

    const int NT = SEQ / 64;
    int cur = 0;
    for (int t = 0; t < NT; t++) {
        if (t + 1 < NT) {
            loadKV(t + 1, cur ^ 1);
            CP_COMMIT();
            CP_WAIT(1);
        } else {
            CP_WAIT(0);
        }
        __syncthreads();

        const uint32_t* ks = (const uint32_t*)Ks[cur];
        const uint32_t* vs = (const uint32_t*)Vs[cur];

        // S = Q * K^T (per-warp 16x64)
        float s[8][4] = {};
        #pragma unroll
        for (int kb = 0; kb < 8; kb++) {
            int kc = kb * 8;
            #pragma unroll
            for (int j = 0; j < 8; j++) {
                int nr = j * 8 + gid;
                uint32_t bv[2] = { ks[nr * AT_STR + kc + tig],
                                   ks[nr * AT_STR + kc + tig + 4] };
                mma_tf32(s[j], qf[kb], bv);
            }
        }

        float mx0 = -1e30f, mx1 = -1e30f;
        #pragma unroll
        for (int j = 0; j < 8; j++) {
            s[j][0] *= 0.125f; s[j][1] *= 0.125f; s[j][2] *= 0.125f; s[j][3] *= 0.125f;
            mx0 = fmaxf(mx0, fmaxf(s[j][0], s[j][1]));
            mx1 = fmaxf(mx1, fmaxf(s[j][2], s[j][3]));
        }
        mx0 = fmaxf(mx0, __shfl_xor_sync(0xffffffffu, mx0, 1));
        mx0 = fmaxf(mx0, __shfl_xor_sync(0xffffffffu, mx0, 2));
        mx1 = fmaxf(mx1, __shfl_xor_sync(0xffffffffu, mx1, 1));
        mx1 = fmaxf(mx1, __shfl_xor_sync(0xffffffffu, mx1, 2));

        float mn0 = fmaxf(m0r, mx0), mn1 = fmaxf(m1r, mx1);
        float al0 = __expf(m0r - mn0), al1 = __expf(m1r - mn1);
        m0r = mn0; m1r = mn1;

        float ls0 = 0.f, ls1 = 0.f;
        #pragma unroll
        for (int j = 0; j < 8; j++) {
            float p0 = __expf(s[j][0] - mn0);
            float p1 = __expf(s[j][1] - mn0);
            float p2 = __expf(s[j][2] - mn1);
            float p3 = __expf(s[j][3] - mn1);
            ls0 += p0 + p1; ls1 += p2 + p3;
            *(float2*)&QP[(wm + gid) * AT_STR + j * 8 + 2 * tig]     = make_float2(rtf(p0), rtf(p1));
            *(float2*)&QP[(wm + gid + 8) * AT_STR + j * 8 + 2 * tig] = make_float2(rtf(p2), rtf(p3));
        }
        ls0 += __shfl_xor_sync(0xffffffffu, ls0, 1);
        ls0 += __shfl_xor_sync(0xffffffffu, ls0, 2);
        ls1 += __shfl_xor_sync(0xffffffffu, ls1, 1);
        ls1 += __shfl_xor_sync(0xffffffffu, ls1, 2);
        l0 = l0 * al0 + ls0;
        l1 = l1 * al1 + ls1;

        #pragma unroll
        for (int j = 0; j < 8; j++) {
            o[j][0] *= al0; o[j][1] *= al0; o[j][2] *= al1; o[j][3] *= al1;
        }
        __syncwarp();

        // O += P * V (per-warp 16x64)
        #pragma unroll
        for (int kb = 0; kb < 8; kb++) {
            int kc = kb * 8;
            uint32_t a[4] = { qpu[(wm + gid) * AT_STR + kc + tig],
                              qpu[(wm + gid + 8) * AT_STR + kc + tig],
                              qpu[(wm + gid) * AT_STR + kc + tig + 4],
                              qpu[(wm + gid + 8) * AT_STR + kc + tig + 4] };
            #pragma unroll
            for (int j = 0; j < 8; j++) {
                uint32_t bv[2] = { vs[(kc + tig) * AT_STR + j * 8 + gid],
                                   vs[(kc + tig + 4) * AT_STR + j * 8 + gid] };
                mma_tf32(o[j], a, bv);
            }
        }
        __syncthreads();
        cur ^= 1;
    }

    float inv0 = 1.0f / l0, inv1 = 1.0f / l1;
    float* ob0 = O + ((size_t)b * SEQ + q0 + wm + gid) * DMODEL + h * DHEAD;
    float* ob1 = O + ((size_t)b * SEQ + q0 + wm + gid + 8) * DMODEL + h * DHEAD;
    #pragma unroll
    for (int j = 0; j < 8; j++) {
        *(float2*)&ob0[j * 8 + 2 * tig] = make_float2(rtf(o[j][0] * inv0), rtf(o[j][1] * inv0));
        *(float2*)&ob1[j * 8 + 2 * tig] = make_float2(rtf(o[j][2] * inv1), rtf(o[j][3] * inv1));
    }
}

// ---------------- launch ----------------
extern "C" void kernel_launch(void* const* d_in, const int* in_sizes, int n_in,
                              void* d_out, int out_size) {
    const float* x      = (const float*)d_in[0];
    const float* Wq     = (const float*)d_in[1];
    const float* Wk     = (const float*)d_in[2];
    const float* Wv     = (const float*)d_in[3];
    const float* Wo     = (const float*)d_in[4];
    const float* W1     = (const float*)d_in[5];
    const float* W2     = (const float*)d_in[6];
    const float* gamma1 = (const float*)d_in[7];
    const float* beta1  = (const float*)d_in[8];
    const float* gamma2 = (const float*)d_in[9];
    const float* beta2  = (const float*)d_in[10];
    float* out = (float*)d_out;

    float *h, *q, *k, *v, *ctx, *res1, *h2, *mid;
    float *wq, *wk, *wv, *wo, *w1, *w2;
    cudaGetSymbolAddress((void**)&h,    g_h);
    cudaGetSymbolAddress((void**)&q,    g_q);
    cudaGetSymbolAddress((void**)&k,    g_k);
    cudaGetSymbolAddress((void**)&v,    g_v);
    cudaGetSymbolAddress((void**)&ctx,  g_ctx);
    cudaGetSymbolAddress((void**)&res1, g_res1);
    cudaGetSymbolAddress((void**)&h2,   g_h2);
    cudaGetSymbolAddress((void**)&mid,  g_mid);
    cudaGetSymbolAddress((void**)&wq,   g_wq);
    cudaGetSymbolAddress((void**)&wk,   g_wk);
    cudaGetSymbolAddress((void**)&wv,   g_wv);
    cudaGetSymbolAddress((void**)&wo,   g_wo);
    cudaGetSymbolAddress((void**)&w1,   g_w1);
    cudaGetSymbolAddress((void**)&w2,   g_w2);

    cudaFuncSetAttribute(attn_tc, cudaFuncAttributeMaxDynamicSharedMemorySize, AT_SMEM_BYTES);
    cudaFuncSetAttribute(gemm_tc<false, true, false>, cudaFuncAttributeMaxDynamicSharedMemorySize, GEMM_SMEM_BYTES);
    cudaFuncSetAttribute(gemm_tc<true, false, true>,  cudaFuncAttributeMaxDynamicSharedMemorySize, GEMM_SMEM_BYTES);
    cudaFuncSetAttribute(gemm_qkv, cudaFuncAttributeMaxDynamicSharedMemorySize, GEMM_SMEM_BYTES);

    // 0. pre-round weights to tf32
    const int DD4 = DMODEL * DMODEL / 4, DH4 = DMODEL * DHID / 4;
    round_kernel<<<(DD4 + 255) / 256, 256>>>(Wq, wq, DD4);
    round_kernel<<<(DD4 + 255) / 256, 256>>>(Wk, wk, DD4);
    round_kernel<<<(DD4 + 255) / 256, 256>>>(Wv, wv, DD4);
    round_kernel<<<(DD4 + 255) / 256, 256>>>(Wo, wo, DD4);
    round_kernel<<<(DH4 + 255) / 256, 256>>>(W1, w1, DH4);
    round_kernel<<<(DH4 + 255) / 256, 256>>>(W2, w2, DH4);

    // 1. LN1 (rounded output)
    layernorm_kernel<<<NTOK, 256>>>(x, gamma1, beta1, h);

    // 2. fused QKV projection (rounded outputs)
    gemm_qkv<<<dim3(3 * DMODEL / 128, NTOK / 128), 128, GEMM_SMEM_BYTES>>>(h, wq, wk, wv, q, k, v);

    // 3. attention (rounded ctx)
    attn_tc<<<dim3(SEQ / 64, NHEADS, BATCH), 128, AT_SMEM_BYTES>>>(q, k, v, ctx);

    // 4. output projection + residual: res1 = x + ctx @ Wo (full fp32 out)
    dim3 gDD(DMODEL / 128, NTOK / 128);
    gemm_tc<false, true, false><<<gDD, 128, GEMM_SMEM_BYTES>>>(ctx, wo, x, res1, NTOK, DMODEL, DMODEL);

    // 5. LN2 (rounded output)
    layernorm_kernel<<<NTOK, 256>>>(res1, gamma2, beta2, h2);

    // 6. FFN
    gemm_tc<true, false, true><<<dim3(DHID / 128, NTOK / 128), 128, GEMM_SMEM_BYTES>>>(h2, w1, nullptr, mid, NTOK, DHID, DMODEL);
    gemm_tc<false, true, false><<<gDD, 128, GEMM_SMEM_BYTES>>>(mid, w2, res1, out, NTOK, DMODEL, DHID);
}

// round 7
// speedup vs baseline: 5.8869x; 1.3725x over previous
#include <cuda_runtime.h>
#include <cuda_fp16.h>
#include <math.h>
#include <stdint.h>

// Problem constants (EncoderLayer: B=2, S=2048, D=768, H=3072, 12 heads x 64)
#define BATCH 2
#define SEQ 2048
#define NTOK (BATCH * SEQ)          // 4096
#define DMODEL 768
#define DHID 3072
#define NHEADS 12
#define DHEAD 64
#define LN_EPS 1e-7f

// ---------------- scratch (no allocations allowed) ----------------
__device__ __half g_h[NTOK * DMODEL];    // ln1 output (fp16)
__device__ float  g_q[NTOK * DMODEL];    // tf32-rounded fp32 (for attn)
__device__ float  g_k[NTOK * DMODEL];
__device__ float  g_v[NTOK * DMODEL];
__device__ __half g_ctx[NTOK * DMODEL];  // attention output (fp16)
__device__ float  g_res1[NTOK * DMODEL]; // x + attn_out (full fp32)
__device__ __half g_h2[NTOK * DMODEL];   // ln2 output (fp16)
__device__ __half g_mid[NTOK * DHID];    // relu(h2 @ W1) (fp16)
// fp16 weight copies (row-major [K][N], as given)
__device__ __half g_wqh[DMODEL * DMODEL];
__device__ __half g_wkh[DMODEL * DMODEL];
__device__ __half g_wvh[DMODEL * DMODEL];
__device__ __half g_woh[DMODEL * DMODEL];
__device__ __half g_w1h[DMODEL * DHID];
__device__ __half g_w2h[DHID * DMODEL];

// ---------------- common PTX helpers ----------------
__device__ __forceinline__ uint32_t tf32cvt(float f) {
    uint32_t r;
    asm("cvt.rna.tf32.f32 %0, %1;" : "=r"(r) : "f"(f));
    return r;
}
__device__ __forceinline__ float rtf(float f) { return __uint_as_float(tf32cvt(f)); }

__device__ __forceinline__ void mma_tf32(float* c, const uint32_t* a, const uint32_t* b) {
    asm volatile(
        "mma.sync.aligned.m16n8k8.row.col.f32.tf32.tf32.f32 "
        "{%0,%1,%2,%3}, {%4,%5,%6,%7}, {%8,%9}, {%0,%1,%2,%3};"
        : "+f"(c[0]), "+f"(c[1]), "+f"(c[2]), "+f"(c[3])
        : "r"(a[0]), "r"(a[1]), "r"(a[2]), "r"(a[3]), "r"(b[0]), "r"(b[1]));
}
__device__ __forceinline__ void mma_f16(float* c, const uint32_t* a, const uint32_t* b) {
    asm volatile(
        "mma.sync.aligned.m16n8k16.row.col.f32.f16.f16.f32 "
        "{%0,%1,%2,%3}, {%4,%5,%6,%7}, {%8,%9}, {%0,%1,%2,%3};"
        : "+f"(c[0]), "+f"(c[1]), "+f"(c[2]), "+f"(c[3])
        : "r"(a[0]), "r"(a[1]), "r"(a[2]), "r"(a[3]), "r"(b[0]), "r"(b[1]));
}
#define LDSM_X4(r, addr) \
    asm volatile("ldmatrix.sync.aligned.m8n8.x4.shared.b16 {%0,%1,%2,%3}, [%4];" \
                 : "=r"((r)[0]), "=r"((r)[1]), "=r"((r)[2]), "=r"((r)[3]) : "r"(addr))
#define LDSM_X4_T(r, addr) \
    asm volatile("ldmatrix.sync.aligned.m8n8.x4.trans.shared.b16 {%0,%1,%2,%3}, [%4];" \
                 : "=r"((r)[0]), "=r"((r)[1]), "=r"((r)[2]), "=r"((r)[3]) : "r"(addr))
#define CP_ASYNC16(dst, src) \
    asm volatile("cp.async.cg.shared.global [%0], [%1], 16;\n" :: "r"(dst), "l"(src))
#define CP_COMMIT() asm volatile("cp.async.commit_group;\n" ::)
#define CP_WAIT(n)  asm volatile("cp.async.wait_group %0;\n" :: "n"(n))

__device__ __forceinline__ uint32_t smem_u32(const void* p) {
    uint32_t a;
    asm("{ .reg .u64 t; cvta.to.shared.u64 t, %1; cvt.u32.u64 %0, t; }" : "=r"(a) : "l"(p));
    return a;
}

// ---------------- weight fp32 -> fp16 convert ----------------
__global__ void cvt_half(const float* __restrict__ src, __half* __restrict__ dst, int n4) {
    int i = blockIdx.x * blockDim.x + threadIdx.x;
    if (i < n4) {
        float4 v = ((const float4*)src)[i];
        __half2 h0 = __floats2half2_rn(v.x, v.y);
        __half2 h1 = __floats2half2_rn(v.z, v.w);
        ((__half2*)dst)[2 * i]     = h0;
        ((__half2*)dst)[2 * i + 1] = h1;
    }
}

// ---------------- LayerNorm (ddof=1), output fp16 ----------------
__global__ void layernorm_kernel(const float* __restrict__ x,
                                 const float* __restrict__ gamma,
                                 const float* __restrict__ beta,
                                 __half* __restrict__ y) {
    int row = blockIdx.x;
    int tid = threadIdx.x;
    const float* xr = x + (size_t)row * DMODEL;

    float v0 = xr[tid];
    float v1 = xr[tid + 256];
    float v2 = xr[tid + 512];

    float sum = v0 + v1 + v2;
    float ss  = v0 * v0 + v1 * v1 + v2 * v2;

    #pragma unroll
    for (int o = 16; o > 0; o >>= 1) {
        sum += __shfl_xor_sync(0xffffffffu, sum, o);
        ss  += __shfl_xor_sync(0xffffffffu, ss, o);
    }
    __shared__ float wsum[8], wss[8];
    int warp = tid >> 5, lane = tid & 31;
    if (lane == 0) { wsum[warp] = sum; wss[warp] = ss; }
    __syncthreads();
    float tot = 0.f, tots = 0.f;
    #pragma unroll
    for (int w = 0; w < 8; w++) { tot += wsum[w]; tots += wss[w]; }

    float mean = tot * (1.0f / DMODEL);
    float var  = (tots - tot * tot * (1.0f / DMODEL)) * (1.0f / (DMODEL - 1));
    var = fmaxf(var, 0.0f);
    float inv = 1.0f / (sqrtf(var) + LN_EPS);

    __half* yr = y + (size_t)row * DMODEL;
    yr[tid]       = __float2half(gamma[tid]       * (v0 - mean) * inv + beta[tid]);
    yr[tid + 256] = __float2half(gamma[tid + 256] * (v1 - mean) * inv + beta[tid + 256]);
    yr[tid + 512] = __float2half(gamma[tid + 512] * (v2 - mean) * inv + beta[tid + 512]);
}

// ---------------- fp16 tensor-core GEMM (m16n8k16, fp32 accum) ----------------
// C[M,N] = op(A[M,K] @ B[K,N] [+ Cadd]) tile at (m0, n0). A,B fp16 row-major.
// Block 128x128, BK=64, 256 threads = 8 warps (4m x 2n), warp tile 32x64.
// ldmatrix fragments, cp.async double-buffered smem with row padding.
#define HG_SA 72                     // A row stride in halves (64 + 8)
#define HG_SB 136                    // B row stride in halves (128 + 8)
#define HG_A_HALVES (128 * HG_SA)    // 9216
#define HG_B_HALVES (64 * HG_SB)     // 8704
#define HG_STAGE_HALVES (HG_A_HALVES + HG_B_HALVES)
#define HG_SMEM_BYTES (2 * HG_STAGE_HALVES * 2)    // 71680

// OUTK: 0 = float raw, 1 = float tf32-rounded, 2 = half
template <bool RELU, bool ADD, int OUTK>
__device__ __forceinline__
void gemmh_core(const __half* __restrict__ A, const __half* __restrict__ B,
                const float* __restrict__ Cadd, void* __restrict__ C,
                int N, int K, int m0, int n0) {
    extern __shared__ __half smh[];
    __half* As[2] = { smh, smh + HG_STAGE_HALVES };
    __half* Bs[2] = { smh + HG_A_HALVES, smh + HG_STAGE_HALVES + HG_A_HALVES };

    int tid = threadIdx.x;              // 256
    int warp = tid >> 5, lane = tid & 31;
    int gid = lane >> 2, tig = lane & 3;
    int wm = (warp & 3) * 32, wn = (warp >> 2) * 64;
    int lr = lane & 15, lc = lane >> 4;  // ldmatrix addressing

    float acc[2][8][4] = {};

    auto fill = [&](__half* as, __half* bs, int k0) {
        #pragma unroll
        for (int i = 0; i < 4; i++) {
            int c = tid + 256 * i;          // A: 1024 chunks = 128 rows x 8
            int r = c >> 3, cc = c & 7;
            uint32_t dst = smem_u32(as + r * HG_SA + cc * 8);
            CP_ASYNC16(dst, A + (size_t)(m0 + r) * K + k0 + cc * 8);
        }
        #pragma unroll
        for (int i = 0; i < 4; i++) {
            int c = tid + 256 * i;          // B: 1024 chunks = 64 rows x 16
            int r = c >> 4, cc = c & 15;
            uint32_t dst = smem_u32(bs + r * HG_SB + cc * 8);
            CP_ASYNC16(dst, B + (size_t)(k0 + r) * N + n0 + cc * 8);
        }
    };

    fill(As[0], Bs[0], 0);
    CP_COMMIT();

    int nIter = K >> 6;                 // BK = 64
    int cur = 0;
    for (int it = 0; it < nIter; it++) {
        if (it + 1 < nIter) {
            fill(As[cur ^ 1], Bs[cur ^ 1], (it + 1) * 64);
            CP_COMMIT();
            CP_WAIT(1);
        } else {
            CP_WAIT(0);
        }
        __syncthreads();

        uint32_t abase = smem_u32(As[cur]);
        uint32_t bbase = smem_u32(Bs[cur]);
        #pragma unroll
        for (int kc16 = 0; kc16 < 4; kc16++) {
            int kc = kc16 * 16;
            uint32_t af[2][4], bf[4][4];
            #pragma unroll
            for (int i = 0; i < 2; i++)
                LDSM_X4(af[i], abase + ((wm + i * 16 + lr) * HG_SA + kc + 8 * lc) * 2);
            #pragma unroll
            for (int jj = 0; jj < 4; jj++)
                LDSM_X4_T(bf[jj], bbase + ((kc + lr) * HG_SB + wn + jj * 16 + 8 * lc) * 2);
            #pragma unroll
            for (int i = 0; i < 2; i++)
                #pragma unroll
                for (int j = 0; j < 8; j++)
                    mma_f16(acc[i][j], af[i], &bf[j >> 1][(j & 1) * 2]);
        }
        __syncthreads();
        cur ^= 1;
    }

    // epilogue: acc[i][j] covers rows (wm+i*16+gid, +8), cols wn+j*8+2*tig
    #pragma unroll
    for (int i = 0; i < 2; i++) {
        int r = m0 + wm + i * 16 + gid;
        #pragma unroll
        for (int j = 0; j < 8; j++) {
            int cc = n0 + wn + j * 8 + 2 * tig;
            size_t o0 = (size_t)r * N + cc;
            size_t o1 = (size_t)(r + 8) * N + cc;
            float2 v0 = make_float2(acc[i][j][0], acc[i][j][1]);
            float2 v1 = make_float2(acc[i][j][2], acc[i][j][3]);
            if (ADD) {
                float2 t0 = *(const float2*)&Cadd[o0];
                float2 t1 = *(const float2*)&Cadd[o1];
                v0.x += t0.x; v0.y += t0.y;
                v1.x += t1.x; v1.y += t1.y;
            }
            if (RELU) {
                v0.x = fmaxf(v0.x, 0.f); v0.y = fmaxf(v0.y, 0.f);
                v1.x = fmaxf(v1.x, 0.f); v1.y = fmaxf(v1.y, 0.f);
            }
            if (OUTK == 2) {
                ((__half2*)C)[o0 >> 1] = __floats2half2_rn(v0.x, v0.y);
                ((__half2*)C)[o1 >> 1] = __floats2half2_rn(v1.x, v1.y);
            } else {
                if (OUTK == 1) {
                    v0.x = rtf(v0.x); v0.y = rtf(v0.y);
                    v1.x = rtf(v1.x); v1.y = rtf(v1.y);
                }
                *(float2*)&((float*)C)[o0] = v0;
                *(float2*)&((float*)C)[o1] = v1;
            }
        }
    }
}

template <bool RELU, bool ADD, int OUTK>
__global__ __launch_bounds__(256, 2)
void gemmh(const __half* __restrict__ A, const __half* __restrict__ B,
           const float* __restrict__ Cadd, void* __restrict__ C,
           int N, int K) {
    gemmh_core<RELU, ADD, OUTK>(A, B, Cadd, C, N, K, blockIdx.y * 128, blockIdx.x * 128);
}

// Fused QKV: grid.x = 3 * (DMODEL/128); block picks its weight/output.
__global__ __launch_bounds__(256, 2)
void gemmh_qkv(const __half* __restrict__ A,
               const __half* __restrict__ Wq, const __half* __restrict__ Wk,
               const __half* __restrict__ Wv,
               float* __restrict__ Cq, float* __restrict__ Ck, float* __restrict__ Cv) {
    int nblk = DMODEL / 128;                 // 6
    int which = blockIdx.x / nblk;
    int n0 = (blockIdx.x % nblk) * 128;
    const __half* B = (which == 0) ? Wq : (which == 1) ? Wk : Wv;
    float* C = (which == 0) ? Cq : (which == 1) ? Ck : Cv;
    gemmh_core<false, false, 1>(A, B, nullptr, C, DMODEL, DMODEL, blockIdx.y * 128, n0);
}

// ---------------- tf32 tensor-core flash attention ----------------
// Unchanged math; output now fp16 (consumed by the Wo fp16 GEMM).
#define AT_STR 68
#define AT_TILE (64 * AT_STR)
#define AT_SMEM_BYTES (5 * AT_TILE * 4)     // 87040

__global__ __launch_bounds__(128)
void attn_tc(const float* __restrict__ Q, const float* __restrict__ K,
             const float* __restrict__ V, __half* __restrict__ O) {
    extern __shared__ float sma[];
    float* Ks[2] = { sma, sma + AT_TILE };
    float* Vs[2] = { sma + 2 * AT_TILE, sma + 3 * AT_TILE };
    float* QP = sma + 4 * AT_TILE;

    int tid = threadIdx.x;
    int b = blockIdx.z, h = blockIdx.y;
    int q0 = blockIdx.x * 64;
    int warp = tid >> 5, lane = tid & 31;
    int gid = lane >> 2, tig = lane & 3;
    int wm = warp * 16;

    const float* qbase = Q + (size_t)b * SEQ * DMODEL + h * DHEAD;
    const float* kbase = K + (size_t)b * SEQ * DMODEL + h * DHEAD;
    const float* vbase = V + (size_t)b * SEQ * DMODEL + h * DHEAD;

    for (int i = tid; i < 1024; i += 128) {
        int r = i >> 4, c4 = (i & 15) * 4;
        *(float4*)&QP[r * AT_STR + c4] = *(const float4*)&qbase[(size_t)(q0 + r) * DMODEL + c4];
    }
    auto loadKV = [&](int t, int buf) {
        int j0 = t * 64;
        #pragma unroll
        for (int i = 0; i < 8; i++) {
            int c = tid + 128 * i;
            int r = c >> 4, c4 = (c & 15) * 4;
            uint32_t dk = smem_u32(&Ks[buf][r * AT_STR + c4]);
            uint32_t dv = smem_u32(&Vs[buf][r * AT_STR + c4]);
            CP_ASYNC16(dk, kbase + (size_t)(j0 + r) * DMODEL + c4);
            CP_ASYNC16(dv, vbase + (size_t)(j0 + r) * DMODEL + c4);
        }
    };
    loadKV(0, 0);
    CP_COMMIT();
    __syncthreads();

    uint32_t qf[8][4];
    const uint32_t* qpu = (const uint32_t*)QP;
    #pragma unroll
    for (int kb = 0; kb < 8; kb++) {
        int kc = kb * 8;
        qf[kb][0] = qpu[(wm + gid) * AT_STR + kc + tig];
        qf[kb][1] = qpu[(wm + gid + 8) * AT_STR + kc + tig];
        qf[kb][2] = qpu[(wm + gid) * AT_STR + kc + tig + 4];
        qf[kb][3] = qpu[(wm + gid + 8) * AT_STR + kc + tig + 4];
    }

    float m0r = -1e30f, m1r = -1e30f, l0 = 0.f, l1 = 0.f;
    float o[8][4] = {};

    const int NT = SEQ / 64;
    int cur = 0;
    for (int t = 0; t < NT; t++) {
        if (t + 1 < NT) {
            loadKV(t + 1, cur ^ 1);
            CP_COMMIT();
            CP_WAIT(1);
        } else {
            CP_WAIT(0);
        }
        __syncthreads();

        const uint32_t* ks = (const uint32_t*)Ks[cur];
        const uint32_t* vs = (const uint32_t*)Vs[cur];

        float s[8][4] = {};
        #pragma unroll
        for (int kb = 0; kb < 8; kb++) {
            int kc = kb * 8;
            #pragma unroll
            for (int j = 0; j < 8; j++) {
                int nr = j * 8 + gid;
                uint32_t bv[2] = { ks[nr * AT_STR + kc + tig],
                                   ks[nr * AT_STR + kc + tig + 4] };
                mma_tf32(s[j], qf[kb], bv);
            }
        }

        float mx0 = -1e30f, mx1 = -1e30f;
        #pragma unroll
        for (int j = 0; j < 8; j++) {
            s[j][0] *= 0.125f; s[j][1] *= 0.125f; s[j][2] *= 0.125f; s[j][3] *= 0.125f;
            mx0 = fmaxf(mx0, fmaxf(s[j][0], s[j][1]));
            mx1 = fmaxf(mx1, fmaxf(s[j][2], s[j][3]));
        }
        mx0 = fmaxf(mx0, __shfl_xor_sync(0xffffffffu, mx0, 1));
        mx0 = fmaxf(mx0, __shfl_xor_sync(0xffffffffu, mx0, 2));
        mx1 = fmaxf(mx1, __shfl_xor_sync(0xffffffffu, mx1, 1));
        mx1 = fmaxf(mx1, __shfl_xor_sync(0xffffffffu, mx1, 2));

        float mn0 = fmaxf(m0r, mx0), mn1 = fmaxf(m1r, mx1);
        float al0 = __expf(m0r - mn0), al1 = __expf(m1r - mn1);
        m0r = mn0; m1r = mn1;

        float ls0 = 0.f, ls1 = 0.f;
        #pragma unroll
        for (int j = 0; j < 8; j++) {
            float p0 = __expf(s[j][0] - mn0);
            float p1 = __expf(s[j][1] - mn0);
            float p2 = __expf(s[j][2] - mn1);
            float p3 = __expf(s[j][3] - mn1);
            ls0 += p0 + p1; ls1 += p2 + p3;
            *(float2*)&QP[(wm + gid) * AT_STR + j * 8 + 2 * tig]     = make_float2(rtf(p0), rtf(p1));
            *(float2*)&QP[(wm + gid + 8) * AT_STR + j * 8 + 2 * tig] = make_float2(rtf(p2), rtf(p3));
        }
        ls0 += __shfl_xor_sync(0xffffffffu, ls0, 1);
        ls0 += __shfl_xor_sync(0xffffffffu, ls0, 2);
        ls1 += __shfl_xor_sync(0xffffffffu, ls1, 1);
        ls1 += __shfl_xor_sync(0xffffffffu, ls1, 2);
        l0 = l0 * al0 + ls0;
        l1 = l1 * al1 + ls1;

        #pragma unroll
        for (int j = 0; j < 8; j++) {
            o[j][0] *= al0; o[j][1] *= al0; o[j][2] *= al1; o[j][3] *= al1;
        }
        __syncwarp();

        #pragma unroll
        for (int kb = 0; kb < 8; kb++) {
            int kc = kb * 8;
            uint32_t a[4] = { qpu[(wm + gid) * AT_STR + kc + tig],
                              qpu[(wm + gid + 8) * AT_STR + kc + tig],
                              qpu[(wm + gid) * AT_STR + kc + tig + 4],
                              qpu[(wm + gid + 8) * AT_STR + kc + tig + 4] };
            #pragma unroll
            for (int j = 0; j < 8; j++) {
                uint32_t bv[2] = { vs[(kc + tig) * AT_STR + j * 8 + gid],
                                   vs[(kc + tig + 4) * AT_STR + j * 8 + gid] };
                mma_tf32(o[j], a, bv);
            }
        }
        __syncthreads();
        cur ^= 1;
    }

    float inv0 = 1.0f / l0, inv1 = 1.0f / l1;
    __half* ob0 = O + ((size_t)b * SEQ + q0 + wm + gid) * DMODEL + h * DHEAD;
    __half* ob1 = O + ((size_t)b * SEQ + q0 + wm + gid + 8) * DMODEL + h * DHEAD;
    #pragma unroll
    for (int j = 0; j < 8; j++) {
        *(__half2*)&ob0[j * 8 + 2 * tig] = __floats2half2_rn(o[j][0] * inv0, o[j][1] * inv0);
        *(__half2*)&ob1[j * 8 + 2 * tig] = __floats2half2_rn(o[j][2] * inv1, o[j][3] * inv1);
    }
}

// ---------------- launch ----------------
extern "C" void kernel_launch(void* const* d_in, const int* in_sizes, int n_in,
                              void* d_out, int out_size) {
    const float* x      = (const float*)d_in[0];
    const float* Wq     = (const float*)d_in[1];
    const float* Wk     = (const float*)d_in[2];
    const float* Wv     = (const float*)d_in[3];
    const float* Wo     = (const float*)d_in[4];
    const float* W1     = (const float*)d_in[5];
    const float* W2     = (const float*)d_in[6];
    const float* gamma1 = (const float*)d_in[7];
    const float* beta1  = (const float*)d_in[8];
    const float* gamma2 = (const float*)d_in[9];
    const float* beta2  = (const float*)d_in[10];
    float* out = (float*)d_out;

    __half *h, *ctx, *h2, *mid, *wqh, *wkh, *wvh, *woh, *w1h, *w2h;
    float *q, *k, *v, *res1;
    cudaGetSymbolAddress((void**)&h,    g_h);
    cudaGetSymbolAddress((void**)&q,    g_q);
    cudaGetSymbolAddress((void**)&k,    g_k);
    cudaGetSymbolAddress((void**)&v,    g_v);
    cudaGetSymbolAddress((void**)&ctx,  g_ctx);
    cudaGetSymbolAddress((void**)&res1, g_res1);
    cudaGetSymbolAddress((void**)&h2,   g_h2);
    cudaGetSymbolAddress((void**)&mid,  g_mid);
    cudaGetSymbolAddress((void**)&wqh,  g_wqh);
    cudaGetSymbolAddress((void**)&wkh,  g_wkh);
    cudaGetSymbolAddress((void**)&wvh,  g_wvh);
    cudaGetSymbolAddress((void**)&woh,  g_woh);
    cudaGetSymbolAddress((void**)&w1h,  g_w1h);
    cudaGetSymbolAddress((void**)&w2h,  g_w2h);

    cudaFuncSetAttribute(attn_tc, cudaFuncAttributeMaxDynamicSharedMemorySize, AT_SMEM_BYTES);
    cudaFuncSetAttribute(gemmh<false, true, 0>, cudaFuncAttributeMaxDynamicSharedMemorySize, HG_SMEM_BYTES);
    cudaFuncSetAttribute(gemmh<true, false, 2>, cudaFuncAttributeMaxDynamicSharedMemorySize, HG_SMEM_BYTES);
    cudaFuncSetAttribute(gemmh_qkv, cudaFuncAttributeMaxDynamicSharedMemorySize, HG_SMEM_BYTES);

    // 0. convert weights fp32 -> fp16
    const int DD4 = DMODEL * DMODEL / 4, DH4 = DMODEL * DHID / 4;
    cvt_half<<<(DD4 + 255) / 256, 256>>>(Wq, wqh, DD4);
    cvt_half<<<(DD4 + 255) / 256, 256>>>(Wk, wkh, DD4);
    cvt_half<<<(DD4 + 255) / 256, 256>>>(Wv, wvh, DD4);
    cvt_half<<<(DD4 + 255) / 256, 256>>>(Wo, woh, DD4);
    cvt_half<<<(DH4 + 255) / 256, 256>>>(W1, w1h, DH4);
    cvt_half<<<(DH4 + 255) / 256, 256>>>(W2, w2h, DH4);

    // 1. LN1 -> h (fp16)
    layernorm_kernel<<<NTOK, 256>>>(x, gamma1, beta1, h);

    // 2. fused QKV projection -> q,k,v (tf32-rounded fp32 for attention)
    gemmh_qkv<<<dim3(3 * DMODEL / 128, NTOK / 128), 256, HG_SMEM_BYTES>>>(h, wqh, wkh, wvh, q, k, v);

    // 3. attention -> ctx (fp16)
    attn_tc<<<dim3(SEQ / 64, NHEADS, BATCH), 128, AT_SMEM_BYTES>>>(q, k, v, ctx);

    // 4. output projection + residual: res1 = x + ctx @ Wo (fp32)
    gemmh<false, true, 0><<<dim3(DMODEL / 128, NTOK / 128), 256, HG_SMEM_BYTES>>>(ctx, woh, x, res1, DMODEL, DMODEL);

    // 5. LN2 -> h2 (fp16)
    layernorm_kernel<<<NTOK, 256>>>(res1, gamma2, beta2, h2);

    // 6. FFN
    gemmh<true, false, 2><<<dim3(DHID / 128, NTOK / 128), 256, HG_SMEM_BYTES>>>(h2, w1h, nullptr, mid, DHID, DMODEL);
    gemmh<false, true, 0><<<dim3(DMODEL / 128, NTOK / 128), 256, HG_SMEM_BYTES>>>(mid, w2h, res1, out, DMODEL, DHID);
}

// round 8
// speedup vs baseline: 8.7429x; 1.4851x over previous
#include <cuda_runtime.h>
#include <cuda_fp16.h>
#include <math.h>
#include <stdint.h>

// Problem constants (EncoderLayer: B=2, S=2048, D=768, H=3072, 12 heads x 64)
#define BATCH 2
#define SEQ 2048
#define NTOK (BATCH * SEQ)          // 4096
#define DMODEL 768
#define DHID 3072
#define NHEADS 12
#define DHEAD 64
#define LN_EPS 1e-7f

// ---------------- scratch (no allocations allowed) ----------------
__device__ __half g_h[NTOK * DMODEL];    // ln1 output (fp16)
__device__ __half g_q[NTOK * DMODEL];    // fp16 (for attn)
__device__ __half g_k[NTOK * DMODEL];
__device__ __half g_v[NTOK * DMODEL];
__device__ __half g_ctx[NTOK * DMODEL];  // attention output (fp16)
__device__ float  g_res1[NTOK * DMODEL]; // x + attn_out (full fp32)
__device__ __half g_h2[NTOK * DMODEL];   // ln2 output (fp16)
__device__ __half g_mid[NTOK * DHID];    // relu(h2 @ W1) (fp16)
// fp16 weight copies (row-major [K][N], as given)
__device__ __half g_wqh[DMODEL * DMODEL];
__device__ __half g_wkh[DMODEL * DMODEL];
__device__ __half g_wvh[DMODEL * DMODEL];
__device__ __half g_woh[DMODEL * DMODEL];
__device__ __half g_w1h[DMODEL * DHID];
__device__ __half g_w2h[DHID * DMODEL];

// ---------------- common PTX helpers ----------------
__device__ __forceinline__ uint32_t tf32cvt(float f) {
    uint32_t r;
    asm("cvt.rna.tf32.f32 %0, %1;" : "=r"(r) : "f"(f));
    return r;
}
__device__ __forceinline__ float rtf(float f) { return __uint_as_float(tf32cvt(f)); }

__device__ __forceinline__ void mma_f16(float* c, const uint32_t* a, const uint32_t* b) {
    asm volatile(
        "mma.sync.aligned.m16n8k16.row.col.f32.f16.f16.f32 "
        "{%0,%1,%2,%3}, {%4,%5,%6,%7}, {%8,%9}, {%0,%1,%2,%3};"
        : "+f"(c[0]), "+f"(c[1]), "+f"(c[2]), "+f"(c[3])
        : "r"(a[0]), "r"(a[1]), "r"(a[2]), "r"(a[3]), "r"(b[0]), "r"(b[1]));
}
#define LDSM_X4(r, addr) \
    asm volatile("ldmatrix.sync.aligned.m8n8.x4.shared.b16 {%0,%1,%2,%3}, [%4];" \
                 : "=r"((r)[0]), "=r"((r)[1]), "=r"((r)[2]), "=r"((r)[3]) : "r"(addr))
#define LDSM_X4_T(r, addr) \
    asm volatile("ldmatrix.sync.aligned.m8n8.x4.trans.shared.b16 {%0,%1,%2,%3}, [%4];" \
                 : "=r"((r)[0]), "=r"((r)[1]), "=r"((r)[2]), "=r"((r)[3]) : "r"(addr))
#define CP_ASYNC16(dst, src) \
    asm volatile("cp.async.cg.shared.global [%0], [%1], 16;\n" :: "r"(dst), "l"(src))
#define CP_COMMIT() asm volatile("cp.async.commit_group;\n" ::)
#define CP_WAIT(n)  asm volatile("cp.async.wait_group %0;\n" :: "n"(n))

__device__ __forceinline__ uint32_t smem_u32(const void* p) {
    uint32_t a;
    asm("{ .reg .u64 t; cvta.to.shared.u64 t, %1; cvt.u32.u64 %0, t; }" : "=r"(a) : "l"(p));
    return a;
}

// ---------------- fused weight fp32 -> fp16 convert (all 6 weights) ----------------
#define CVT_DD (DMODEL * DMODEL / 4)     // 147456 float4s
#define CVT_DH (DMODEL * DHID / 4)       // 589824 float4s
__global__ void cvt_all(const float* __restrict__ s0, const float* __restrict__ s1,
                        const float* __restrict__ s2, const float* __restrict__ s3,
                        const float* __restrict__ s4, const float* __restrict__ s5,
                        __half* __restrict__ d0, __half* __restrict__ d1,
                        __half* __restrict__ d2, __half* __restrict__ d3,
                        __half* __restrict__ d4, __half* __restrict__ d5) {
    int w = blockIdx.y;
    const float* src = (w == 0) ? s0 : (w == 1) ? s1 : (w == 2) ? s2
                     : (w == 3) ? s3 : (w == 4) ? s4 : s5;
    __half* dst = (w == 0) ? d0 : (w == 1) ? d1 : (w == 2) ? d2
                : (w == 3) ? d3 : (w == 4) ? d4 : d5;
    int n4 = (w < 4) ? CVT_DD : CVT_DH;
    int i = blockIdx.x * blockDim.x + threadIdx.x;
    if (i < n4) {
        float4 v = ((const float4*)src)[i];
        ((__half2*)dst)[2 * i]     = __floats2half2_rn(v.x, v.y);
        ((__half2*)dst)[2 * i + 1] = __floats2half2_rn(v.z, v.w);
    }
}

// ---------------- LayerNorm (ddof=1), output fp16 ----------------
__global__ void layernorm_kernel(const float* __restrict__ x,
                                 const float* __restrict__ gamma,
                                 const float* __restrict__ beta,
                                 __half* __restrict__ y) {
    int row = blockIdx.x;
    int tid = threadIdx.x;
    const float* xr = x + (size_t)row * DMODEL;

    float v0 = xr[tid];
    float v1 = xr[tid + 256];
    float v2 = xr[tid + 512];

    float sum = v0 + v1 + v2;
    float ss  = v0 * v0 + v1 * v1 + v2 * v2;

    #pragma unroll
    for (int o = 16; o > 0; o >>= 1) {
        sum += __shfl_xor_sync(0xffffffffu, sum, o);
        ss  += __shfl_xor_sync(0xffffffffu, ss, o);
    }
    __shared__ float wsum[8], wss[8];
    int warp = tid >> 5, lane = tid & 31;
    if (lane == 0) { wsum[warp] = sum; wss[warp] = ss; }
    __syncthreads();
    float tot = 0.f, tots = 0.f;
    #pragma unroll
    for (int w = 0; w < 8; w++) { tot += wsum[w]; tots += wss[w]; }

    float mean = tot * (1.0f / DMODEL);
    float var  = (tots - tot * tot * (1.0f / DMODEL)) * (1.0f / (DMODEL - 1));
    var = fmaxf(var, 0.0f);
    float inv = 1.0f / (sqrtf(var) + LN_EPS);

    __half* yr = y + (size_t)row * DMODEL;
    yr[tid]       = __float2half(gamma[tid]       * (v0 - mean) * inv + beta[tid]);
    yr[tid + 256] = __float2half(gamma[tid + 256] * (v1 - mean) * inv + beta[tid + 256]);
    yr[tid + 512] = __float2half(gamma[tid + 512] * (v2 - mean) * inv + beta[tid + 512]);
}

// ---------------- fp16 tensor-core GEMM (m16n8k16, fp32 accum) ----------------
#define HG_SA 72                     // A row stride in halves (64 + 8)
#define HG_SB 136                    // B row stride in halves (128 + 8)
#define HG_A_HALVES (128 * HG_SA)    // 9216
#define HG_B_HALVES (64 * HG_SB)     // 8704
#define HG_STAGE_HALVES (HG_A_HALVES + HG_B_HALVES)
#define HG_SMEM_BYTES (2 * HG_STAGE_HALVES * 2)    // 71680

// OUTK: 0 = float raw, 1 = float tf32-rounded, 2 = half
template <bool RELU, bool ADD, int OUTK>
__device__ __forceinline__
void gemmh_core(const __half* __restrict__ A, const __half* __restrict__ B,
                const float* __restrict__ Cadd, void* __restrict__ C,
                int N, int K, int m0, int n0) {
    extern __shared__ __half smh[];
    __half* As[2] = { smh, smh + HG_STAGE_HALVES };
    __half* Bs[2] = { smh + HG_A_HALVES, smh + HG_STAGE_HALVES + HG_A_HALVES };

    int tid = threadIdx.x;              // 256
    int warp = tid >> 5, lane = tid & 31;
    int gid = lane >> 2, tig = lane & 3;
    int wm = (warp & 3) * 32, wn = (warp >> 2) * 64;
    int lr = lane & 15, lc = lane >> 4;  // ldmatrix addressing

    float acc[2][8][4] = {};

    auto fill = [&](__half* as, __half* bs, int k0) {
        #pragma unroll
        for (int i = 0; i < 4; i++) {
            int c = tid + 256 * i;          // A: 1024 chunks = 128 rows x 8
            int r = c >> 3, cc = c & 7;
            uint32_t dst = smem_u32(as + r * HG_SA + cc * 8);
            CP_ASYNC16(dst, A + (size_t)(m0 + r) * K + k0 + cc * 8);
        }
        #pragma unroll
        for (int i = 0; i < 4; i++) {
            int c = tid + 256 * i;          // B: 1024 chunks = 64 rows x 16
            int r = c >> 4, cc = c & 15;
            uint32_t dst = smem_u32(bs + r * HG_SB + cc * 8);
            CP_ASYNC16(dst, B + (size_t)(k0 + r) * N + n0 + cc * 8);
        }
    };

    fill(As[0], Bs[0], 0);
    CP_COMMIT();

    int nIter = K >> 6;                 // BK = 64
    int cur = 0;
    for (int it = 0; it < nIter; it++) {
        if (it + 1 < nIter) {
            fill(As[cur ^ 1], Bs[cur ^ 1], (it + 1) * 64);
            CP_COMMIT();
            CP_WAIT(1);
        } else {
            CP_WAIT(0);
        }
        __syncthreads();

        uint32_t abase = smem_u32(As[cur]);
        uint32_t bbase = smem_u32(Bs[cur]);
        #pragma unroll
        for (int kc16 = 0; kc16 < 4; kc16++) {
            int kc = kc16 * 16;
            uint32_t af[2][4], bf[4][4];
            #pragma unroll
            for (int i = 0; i < 2; i++)
                LDSM_X4(af[i], abase + ((wm + i * 16 + lr) * HG_SA + kc + 8 * lc) * 2);
            #pragma unroll
            for (int jj = 0; jj < 4; jj++)
                LDSM_X4_T(bf[jj], bbase + ((kc + lr) * HG_SB + wn + jj * 16 + 8 * lc) * 2);
            #pragma unroll
            for (int i = 0; i < 2; i++)
                #pragma unroll
                for (int j = 0; j < 8; j++)
                    mma_f16(acc[i][j], af[i], &bf[j >> 1][(j & 1) * 2]);
        }
        __syncthreads();
        cur ^= 1;
    }

    #pragma unroll
    for (int i = 0; i < 2; i++) {
        int r = m0 + wm + i * 16 + gid;
        #pragma unroll
        for (int j = 0; j < 8; j++) {
            int cc = n0 + wn + j * 8 + 2 * tig;
            size_t o0 = (size_t)r * N + cc;
            size_t o1 = (size_t)(r + 8) * N + cc;
            float2 v0 = make_float2(acc[i][j][0], acc[i][j][1]);
            float2 v1 = make_float2(acc[i][j][2], acc[i][j][3]);
            if (ADD) {
                float2 t0 = *(const float2*)&Cadd[o0];
                float2 t1 = *(const float2*)&Cadd[o1];
                v0.x += t0.x; v0.y += t0.y;
                v1.x += t1.x; v1.y += t1.y;
            }
            if (RELU) {
                v0.x = fmaxf(v0.x, 0.f); v0.y = fmaxf(v0.y, 0.f);
                v1.x = fmaxf(v1.x, 0.f); v1.y = fmaxf(v1.y, 0.f);
            }
            if (OUTK == 2) {
                ((__half2*)C)[o0 >> 1] = __floats2half2_rn(v0.x, v0.y);
                ((__half2*)C)[o1 >> 1] = __floats2half2_rn(v1.x, v1.y);
            } else {
                if (OUTK == 1) {
                    v0.x = rtf(v0.x); v0.y = rtf(v0.y);
                    v1.x = rtf(v1.x); v1.y = rtf(v1.y);
                }
                *(float2*)&((float*)C)[o0] = v0;
                *(float2*)&((float*)C)[o1] = v1;
            }
        }
    }
}

template <bool RELU, bool ADD, int OUTK>
__global__ __launch_bounds__(256, 2)
void gemmh(const __half* __restrict__ A, const __half* __restrict__ B,
           const float* __restrict__ Cadd, void* __restrict__ C,
           int N, int K) {
    gemmh_core<RELU, ADD, OUTK>(A, B, Cadd, C, N, K, blockIdx.y * 128, blockIdx.x * 128);
}

// Fused QKV: grid.x = 3 * (DMODEL/128); block picks its weight/output. fp16 outs.
__global__ __launch_bounds__(256, 2)
void gemmh_qkv(const __half* __restrict__ A,
               const __half* __restrict__ Wq, const __half* __restrict__ Wk,
               const __half* __restrict__ Wv,
               __half* __restrict__ Cq, __half* __restrict__ Ck, __half* __restrict__ Cv) {
    int nblk = DMODEL / 128;                 // 6
    int which = blockIdx.x / nblk;
    int n0 = (blockIdx.x % nblk) * 128;
    const __half* B = (which == 0) ? Wq : (which == 1) ? Wk : Wv;
    __half* C = (which == 0) ? Cq : (which == 1) ? Ck : Cv;
    gemmh_core<false, false, 2>(A, B, nullptr, C, DMODEL, DMODEL, blockIdx.y * 128, n0);
}

// ---------------- fp16 tensor-core flash attention ----------------
// grid (SEQ/64, NHEADS, BATCH), 128 threads = 4 warps; warp owns 16 q-rows.
// QK^T: Q A-frags (preloaded), K B-frags via ldmatrix non-trans ({f0,f2},{f1,f3}).
// PV:   P A-frags via ldmatrix,   V B-frags via ldmatrix.trans ({f0,f1},{f2,f3}).
#define AH_STR 72
#define AH_TILE (64 * AH_STR)               // halves
#define AH_SMEM_BYTES (5 * AH_TILE * 2)     // 2xK, 2xV, 1x(Q then P) = 46080

__global__ __launch_bounds__(128)
void attn_h(const __half* __restrict__ Q, const __half* __restrict__ K,
            const __half* __restrict__ V, __half* __restrict__ O) {
    extern __shared__ __half smah[];
    __half* Ks[2] = { smah, smah + AH_TILE };
    __half* Vs[2] = { smah + 2 * AH_TILE, smah + 3 * AH_TILE };
    __half* QP = smah + 4 * AH_TILE;         // Q tile, then reused as P

    int tid = threadIdx.x;
    int b = blockIdx.z, h = blockIdx.y;
    int q0 = blockIdx.x * 64;
    int warp = tid >> 5, lane = tid & 31;
    int gid = lane >> 2, tig = lane & 3;
    int lr = lane & 15, lc = lane >> 4;
    int wm = warp * 16;

    const __half* qbase = Q + (size_t)b * SEQ * DMODEL + h * DHEAD;
    const __half* kbase = K + (size_t)b * SEQ * DMODEL + h * DHEAD;
    const __half* vbase = V + (size_t)b * SEQ * DMODEL + h * DHEAD;

    // stage Q tile: 64 rows x 64 halves, 16B chunks
    for (int i = tid; i < 512; i += 128) {
        int r = i >> 3, c8 = (i & 7) * 8;
        *(uint4*)&QP[r * AH_STR + c8] = *(const uint4*)&qbase[(size_t)(q0 + r) * DMODEL + c8];
    }
    auto loadKV = [&](int t, int buf) {
        int j0 = t * 64;
        #pragma unroll
        for (int i = 0; i < 4; i++) {
            int c = tid + 128 * i;
            int r = c >> 3, c8 = (c & 7) * 8;
            CP_ASYNC16(smem_u32(&Ks[buf][r * AH_STR + c8]), kbase + (size_t)(j0 + r) * DMODEL + c8);
            CP_ASYNC16(smem_u32(&Vs[buf][r * AH_STR + c8]), vbase + (size_t)(j0 + r) * DMODEL + c8);
        }
    };
    loadKV(0, 0);
    CP_COMMIT();
    __syncthreads();

    // preload Q fragments (4 k16 chunks)
    uint32_t qb = smem_u32(QP);
    uint32_t qf[4][4];
    #pragma unroll
    for (int kc = 0; kc < 4; kc++)
        LDSM_X4(qf[kc], qb + ((wm + lr) * AH_STR + kc * 16 + 8 * lc) * 2);
    // QP rows [wm, wm+16) now warp-private: reuse as P

    float m0r = -1e30f, m1r = -1e30f, l0 = 0.f, l1 = 0.f;
    float o[8][4] = {};

    const int NT = SEQ / 64;
    int cur = 0;
    for (int t = 0; t < NT; t++) {
        if (t + 1 < NT) {
            loadKV(t + 1, cur ^ 1);
            CP_COMMIT();
            CP_WAIT(1);
        } else {
            CP_WAIT(0);
        }
        __syncthreads();

        uint32_t kb = smem_u32(Ks[cur]);
        uint32_t vb = smem_u32(Vs[cur]);

        // S = Q * K^T (warp: 16 x 64)
        float s[8][4] = {};
        #pragma unroll
        for (int kc = 0; kc < 4; kc++) {
            #pragma unroll
            for (int nt = 0; nt < 4; nt++) {
                uint32_t kf[4];
                LDSM_X4(kf, kb + ((nt * 16 + lr) * AH_STR + kc * 16 + 8 * lc) * 2);
                uint32_t b0[2] = { kf[0], kf[2] }, b1[2] = { kf[1], kf[3] };
                mma_f16(s[2 * nt],     qf[kc], b0);
                mma_f16(s[2 * nt + 1], qf[kc], b1);
            }
        }

        float mx0 = -1e30f, mx1 = -1e30f;
        #pragma unroll
        for (int j = 0; j < 8; j++) {
            s[j][0] *= 0.125f; s[j][1] *= 0.125f; s[j][2] *= 0.125f; s[j][3] *= 0.125f;
            mx0 = fmaxf(mx0, fmaxf(s[j][0], s[j][1]));
            mx1 = fmaxf(mx1, fmaxf(s[j][2], s[j][3]));
        }
        mx0 = fmaxf(mx0, __shfl_xor_sync(0xffffffffu, mx0, 1));
        mx0 = fmaxf(mx0, __shfl_xor_sync(0xffffffffu, mx0, 2));
        mx1 = fmaxf(mx1, __shfl_xor_sync(0xffffffffu, mx1, 1));
        mx1 = fmaxf(mx1, __shfl_xor_sync(0xffffffffu, mx1, 2));

        float mn0 = fmaxf(m0r, mx0), mn1 = fmaxf(m1r, mx1);
        float al0 = __expf(m0r - mn0), al1 = __expf(m1r - mn1);
        m0r = mn0; m1r = mn1;

        float ls0 = 0.f, ls1 = 0.f;
        #pragma unroll
        for (int j = 0; j < 8; j++) {
            float p0 = __expf(s[j][0] - mn0);
            float p1 = __expf(s[j][1] - mn0);
            float p2 = __expf(s[j][2] - mn1);
            float p3 = __expf(s[j][3] - mn1);
            ls0 += p0 + p1; ls1 += p2 + p3;
            *(__half2*)&QP[(wm + gid) * AH_STR + j * 8 + 2 * tig]     = __floats2half2_rn(p0, p1);
            *(__half2*)&QP[(wm + gid + 8) * AH_STR + j * 8 + 2 * tig] = __floats2half2_rn(p2, p3);
        }
        ls0 += __shfl_xor_sync(0xffffffffu, ls0, 1);
        ls0 += __shfl_xor_sync(0xffffffffu, ls0, 2);
        ls1 += __shfl_xor_sync(0xffffffffu, ls1, 1);
        ls1 += __shfl_xor_sync(0xffffffffu, ls1, 2);
        l0 = l0 * al0 + ls0;
        l1 = l1 * al1 + ls1;

        #pragma unroll
        for (int j = 0; j < 8; j++) {
            o[j][0] *= al0; o[j][1] *= al0; o[j][2] *= al1; o[j][3] *= al1;
        }
        __syncwarp();

        // O += P * V (warp: 16 x 64; k = keys)
        #pragma unroll
        for (int kc = 0; kc < 4; kc++) {
            uint32_t pf[4];
            LDSM_X4(pf, qb + ((wm + lr) * AH_STR + kc * 16 + 8 * lc) * 2);
            #pragma unroll
            for (int nt = 0; nt < 4; nt++) {
                uint32_t vf[4];
                LDSM_X4_T(vf, vb + ((kc * 16 + lr) * AH_STR + nt * 16 + 8 * lc) * 2);
                mma_f16(o[2 * nt],     pf, vf);
                mma_f16(o[2 * nt + 1], pf, vf + 2);
            }
        }
        __syncthreads();
        cur ^= 1;
    }

    float inv0 = 1.0f / l0, inv1 = 1.0f / l1;
    __half* ob0 = O + ((size_t)b * SEQ + q0 + wm + gid) * DMODEL + h * DHEAD;
    __half* ob1 = O + ((size_t)b * SEQ + q0 + wm + gid + 8) * DMODEL + h * DHEAD;
    #pragma unroll
    for (int j = 0; j < 8; j++) {
        *(__half2*)&ob0[j * 8 + 2 * tig] = __floats2half2_rn(o[j][0] * inv0, o[j][1] * inv0);
        *(__half2*)&ob1[j * 8 + 2 * tig] = __floats2half2_rn(o[j][2] * inv1, o[j][3] * inv1);
    }
}

// ---------------- launch ----------------
extern "C" void kernel_launch(void* const* d_in, const int* in_sizes, int n_in,
                              void* d_out, int out_size) {
    const float* x      = (const float*)d_in[0];
    const float* Wq     = (const float*)d_in[1];
    const float* Wk     = (const float*)d_in[2];
    const float* Wv     = (const float*)d_in[3];
    const float* Wo     = (const float*)d_in[4];
    const float* W1     = (const float*)d_in[5];
    const float* W2     = (const float*)d_in[6];
    const float* gamma1 = (const float*)d_in[7];
    const float* beta1  = (const float*)d_in[8];
    const float* gamma2 = (const float*)d_in[9];
    const float* beta2  = (const float*)d_in[10];
    float* out = (float*)d_out;

    __half *h, *q, *k, *v, *ctx, *h2, *mid, *wqh, *wkh, *wvh, *woh, *w1h, *w2h;
    float *res1;
    cudaGetSymbolAddress((void**)&h,    g_h);
    cudaGetSymbolAddress((void**)&q,    g_q);
    cudaGetSymbolAddress((void**)&k,    g_k);
    cudaGetSymbolAddress((void**)&v,    g_v);
    cudaGetSymbolAddress((void**)&ctx,  g_ctx);
    cudaGetSymbolAddress((void**)&res1, g_res1);
    cudaGetSymbolAddress((void**)&h2,   g_h2);
    cudaGetSymbolAddress((void**)&mid,  g_mid);
    cudaGetSymbolAddress((void**)&wqh,  g_wqh);
    cudaGetSymbolAddress((void**)&wkh,  g_wkh);
    cudaGetSymbolAddress((void**)&wvh,  g_wvh);
    cudaGetSymbolAddress((void**)&woh,  g_woh);
    cudaGetSymbolAddress((void**)&w1h,  g_w1h);
    cudaGetSymbolAddress((void**)&w2h,  g_w2h);

    cudaFuncSetAttribute(attn_h, cudaFuncAttributeMaxDynamicSharedMemorySize, AH_SMEM_BYTES);
    cudaFuncSetAttribute(gemmh<false, true, 0>, cudaFuncAttributeMaxDynamicSharedMemorySize, HG_SMEM_BYTES);
    cudaFuncSetAttribute(gemmh<true, false, 2>, cudaFuncAttributeMaxDynamicSharedMemorySize, HG_SMEM_BYTES);
    cudaFuncSetAttribute(gemmh_qkv, cudaFuncAttributeMaxDynamicSharedMemorySize, HG_SMEM_BYTES);

    // 0. convert all weights fp32 -> fp16 (single launch)
    cvt_all<<<dim3((CVT_DH + 255) / 256, 6), 256>>>(Wq, Wk, Wv, Wo, W1, W2,
                                                    wqh, wkh, wvh, woh, w1h, w2h);

    // 1. LN1 -> h (fp16)
    layernorm_kernel<<<NTOK, 256>>>(x, gamma1, beta1, h);

    // 2. fused QKV projection -> q,k,v (fp16)
    gemmh_qkv<<<dim3(3 * DMODEL / 128, NTOK / 128), 256, HG_SMEM_BYTES>>>(h, wqh, wkh, wvh, q, k, v);

    // 3. attention -> ctx (fp16)
    attn_h<<<dim3(SEQ / 64, NHEADS, BATCH), 128, AH_SMEM_BYTES>>>(q, k, v, ctx);

    // 4. output projection + residual: res1 = x + ctx @ Wo (fp32)
    gemmh<false, true, 0><<<dim3(DMODEL / 128, NTOK / 128), 256, HG_SMEM_BYTES>>>(ctx, woh, x, res1, DMODEL, DMODEL);

    // 5. LN2 -> h2 (fp16)
    layernorm_kernel<<<NTOK, 256>>>(res1, gamma2, beta2, h2);

    // 6. FFN
    gemmh<true, false, 2><<<dim3(DHID / 128, NTOK / 128), 256, HG_SMEM_BYTES>>>(h2, w1h, nullptr, mid, DHID, DMODEL);
    gemmh<false, true, 0><<<dim3(DMODEL / 128, NTOK / 128), 256, HG_SMEM_BYTES>>>(mid, w2h, res1, out, DMODEL, DHID);
}

// round 9
// speedup vs baseline: 8.7737x; 1.0035x over previous
#include <cuda_runtime.h>
#include <cuda_fp16.h>
#include <math.h>
#include <stdint.h>

// Problem constants (EncoderLayer: B=2, S=2048, D=768, H=3072, 12 heads x 64)
#define BATCH 2
#define SEQ 2048
#define NTOK (BATCH * SEQ)          // 4096
#define DMODEL 768
#define DHID 3072
#define NHEADS 12
#define DHEAD 64
#define LN_EPS 1e-7f

// ---------------- scratch (no allocations allowed) ----------------
__device__ __half g_h[NTOK * DMODEL];    // ln1 output (fp16)
__device__ __half g_q[NTOK * DMODEL];    // fp16 (for attn)
__device__ __half g_k[NTOK * DMODEL];
__device__ __half g_v[NTOK * DMODEL];
__device__ __half g_ctx[NTOK * DMODEL];  // attention output (fp16)
__device__ float  g_res1[NTOK * DMODEL]; // x + attn_out (full fp32)
__device__ __half g_h2[NTOK * DMODEL];   // ln2 output (fp16)
__device__ __half g_mid[NTOK * DHID];    // relu(h2 @ W1) (fp16)
// fp16 weight copies (row-major [K][N], as given)
__device__ __half g_wqh[DMODEL * DMODEL];
__device__ __half g_wkh[DMODEL * DMODEL];
__device__ __half g_wvh[DMODEL * DMODEL];
__device__ __half g_woh[DMODEL * DMODEL];
__device__ __half g_w1h[DMODEL * DHID];
__device__ __half g_w2h[DHID * DMODEL];

// ---------------- common PTX helpers ----------------
__device__ __forceinline__ void mma_f16(float* c, const uint32_t* a, const uint32_t* b) {
    asm volatile(
        "mma.sync.aligned.m16n8k16.row.col.f32.f16.f16.f32 "
        "{%0,%1,%2,%3}, {%4,%5,%6,%7}, {%8,%9}, {%0,%1,%2,%3};"
        : "+f"(c[0]), "+f"(c[1]), "+f"(c[2]), "+f"(c[3])
        : "r"(a[0]), "r"(a[1]), "r"(a[2]), "r"(a[3]), "r"(b[0]), "r"(b[1]));
}
#define LDSM_X4(r, addr) \
    asm volatile("ldmatrix.sync.aligned.m8n8.x4.shared.b16 {%0,%1,%2,%3}, [%4];" \
                 : "=r"((r)[0]), "=r"((r)[1]), "=r"((r)[2]), "=r"((r)[3]) : "r"(addr))
#define LDSM_X4_T(r, addr) \
    asm volatile("ldmatrix.sync.aligned.m8n8.x4.trans.shared.b16 {%0,%1,%2,%3}, [%4];" \
                 : "=r"((r)[0]), "=r"((r)[1]), "=r"((r)[2]), "=r"((r)[3]) : "r"(addr))
#define CP_ASYNC16(dst, src) \
    asm volatile("cp.async.cg.shared.global [%0], [%1], 16;\n" :: "r"(dst), "l"(src))
#define CP_COMMIT() asm volatile("cp.async.commit_group;\n" ::)
#define CP_WAIT(n)  asm volatile("cp.async.wait_group %0;\n" :: "n"(n))

__device__ __forceinline__ uint32_t smem_u32(const void* p) {
    uint32_t a;
    asm("{ .reg .u64 t; cvta.to.shared.u64 t, %1; cvt.u32.u64 %0, t; }" : "=r"(a) : "l"(p));
    return a;
}

// ---------------- fused weight fp32 -> fp16 convert (all 6 weights) ----------------
#define CVT_DD (DMODEL * DMODEL / 4)     // 147456 float4s
#define CVT_DH (DMODEL * DHID / 4)       // 589824 float4s
__global__ void cvt_all(const float* __restrict__ s0, const float* __restrict__ s1,
                        const float* __restrict__ s2, const float* __restrict__ s3,
                        const float* __restrict__ s4, const float* __restrict__ s5,
                        __half* __restrict__ d0, __half* __restrict__ d1,
                        __half* __restrict__ d2, __half* __restrict__ d3,
                        __half* __restrict__ d4, __half* __restrict__ d5) {
    int w = blockIdx.y;
    const float* src = (w == 0) ? s0 : (w == 1) ? s1 : (w == 2) ? s2
                     : (w == 3) ? s3 : (w == 4) ? s4 : s5;
    __half* dst = (w == 0) ? d0 : (w == 1) ? d1 : (w == 2) ? d2
                : (w == 3) ? d3 : (w == 4) ? d4 : d5;
    int n4 = (w < 4) ? CVT_DD : CVT_DH;
    int i = blockIdx.x * blockDim.x + threadIdx.x;
    if (i < n4) {
        float4 v = ((const float4*)src)[i];
        ((__half2*)dst)[2 * i]     = __floats2half2_rn(v.x, v.y);
        ((__half2*)dst)[2 * i + 1] = __floats2half2_rn(v.z, v.w);
    }
}

// ---------------- LayerNorm (ddof=1), output fp16 ----------------
__global__ void layernorm_kernel(const float* __restrict__ x,
                                 const float* __restrict__ gamma,
                                 const float* __restrict__ beta,
                                 __half* __restrict__ y) {
    int row = blockIdx.x;
    int tid = threadIdx.x;
    const float* xr = x + (size_t)row * DMODEL;

    float v0 = xr[tid];
    float v1 = xr[tid + 256];
    float v2 = xr[tid + 512];

    float sum = v0 + v1 + v2;
    float ss  = v0 * v0 + v1 * v1 + v2 * v2;

    #pragma unroll
    for (int o = 16; o > 0; o >>= 1) {
        sum += __shfl_xor_sync(0xffffffffu, sum, o);
        ss  += __shfl_xor_sync(0xffffffffu, ss, o);
    }
    __shared__ float wsum[8], wss[8];
    int warp = tid >> 5, lane = tid & 31;
    if (lane == 0) { wsum[warp] = sum; wss[warp] = ss; }
    __syncthreads();
    float tot = 0.f, tots = 0.f;
    #pragma unroll
    for (int w = 0; w < 8; w++) { tot += wsum[w]; tots += wss[w]; }

    float mean = tot * (1.0f / DMODEL);
    float var  = (tots - tot * tot * (1.0f / DMODEL)) * (1.0f / (DMODEL - 1));
    var = fmaxf(var, 0.0f);
    float inv = 1.0f / (sqrtf(var) + LN_EPS);

    __half* yr = y + (size_t)row * DMODEL;
    yr[tid]       = __float2half(gamma[tid]       * (v0 - mean) * inv + beta[tid]);
    yr[tid + 256] = __float2half(gamma[tid + 256] * (v1 - mean) * inv + beta[tid + 256]);
    yr[tid + 512] = __float2half(gamma[tid + 512] * (v2 - mean) * inv + beta[tid + 512]);
}

// ---------------- fp16 tensor-core GEMM (m16n8k16, fp32 accum) ----------------
#define HG_SA 72                     // A row stride in halves (64 + 8)
#define HG_SB 136                    // B row stride in halves (128 + 8)
#define HG_A_HALVES (128 * HG_SA)    // 9216
#define HG_B_HALVES (64 * HG_SB)     // 8704
#define HG_STAGE_HALVES (HG_A_HALVES + HG_B_HALVES)
#define HG_SMEM_BYTES (2 * HG_STAGE_HALVES * 2)    // 71680

// OUTK: 0 = float raw, 2 = half
template <bool RELU, bool ADD, int OUTK>
__device__ __forceinline__
void gemmh_core(const __half* __restrict__ A, const __half* __restrict__ B,
                const float* __restrict__ Cadd, void* __restrict__ C,
                int N, int K, int m0, int n0) {
    extern __shared__ __half smh[];
    __half* As[2] = { smh, smh + HG_STAGE_HALVES };
    __half* Bs[2] = { smh + HG_A_HALVES, smh + HG_STAGE_HALVES + HG_A_HALVES };

    int tid = threadIdx.x;              // 256
    int warp = tid >> 5, lane = tid & 31;
    int gid = lane >> 2, tig = lane & 3;
    int wm = (warp & 3) * 32, wn = (warp >> 2) * 64;
    int lr = lane & 15, lc = lane >> 4;  // ldmatrix addressing

    float acc[2][8][4] = {};

    auto fill = [&](__half* as, __half* bs, int k0) {
        #pragma unroll
        for (int i = 0; i < 4; i++) {
            int c = tid + 256 * i;          // A: 1024 chunks = 128 rows x 8
            int r = c >> 3, cc = c & 7;
            uint32_t dst = smem_u32(as + r * HG_SA + cc * 8);
            CP_ASYNC16(dst, A + (size_t)(m0 + r) * K + k0 + cc * 8);
        }
        #pragma unroll
        for (int i = 0; i < 4; i++) {
            int c = tid + 256 * i;          // B: 1024 chunks = 64 rows x 16
            int r = c >> 4, cc = c & 15;
            uint32_t dst = smem_u32(bs + r * HG_SB + cc * 8);
            CP_ASYNC16(dst, B + (size_t)(k0 + r) * N + n0 + cc * 8);
        }
    };

    fill(As[0], Bs[0], 0);
    CP_COMMIT();

    int nIter = K >> 6;                 // BK = 64
    int cur = 0;
    for (int it = 0; it < nIter; it++) {
        if (it + 1 < nIter) {
            fill(As[cur ^ 1], Bs[cur ^ 1], (it + 1) * 64);
            CP_COMMIT();
            CP_WAIT(1);
        } else {
            CP_WAIT(0);
        }
        __syncthreads();

        uint32_t abase = smem_u32(As[cur]);
        uint32_t bbase = smem_u32(Bs[cur]);
        #pragma unroll
        for (int kc16 = 0; kc16 < 4; kc16++) {
            int kc = kc16 * 16;
            uint32_t af[2][4], bf[4][4];
            #pragma unroll
            for (int i = 0; i < 2; i++)
                LDSM_X4(af[i], abase + ((wm + i * 16 + lr) * HG_SA + kc + 8 * lc) * 2);
            #pragma unroll
            for (int jj = 0; jj < 4; jj++)
                LDSM_X4_T(bf[jj], bbase + ((kc + lr) * HG_SB + wn + jj * 16 + 8 * lc) * 2);
            #pragma unroll
            for (int i = 0; i < 2; i++)
                #pragma unroll
                for (int j = 0; j < 8; j++)
                    mma_f16(acc[i][j], af[i], &bf[j >> 1][(j & 1) * 2]);
        }
        __syncthreads();
        cur ^= 1;
    }

    #pragma unroll
    for (int i = 0; i < 2; i++) {
        int r = m0 + wm + i * 16 + gid;
        #pragma unroll
        for (int j = 0; j < 8; j++) {
            int cc = n0 + wn + j * 8 + 2 * tig;
            size_t o0 = (size_t)r * N + cc;
            size_t o1 = (size_t)(r + 8) * N + cc;
            float2 v0 = make_float2(acc[i][j][0], acc[i][j][1]);
            float2 v1 = make_float2(acc[i][j][2], acc[i][j][3]);
            if (ADD) {
                float2 t0 = *(const float2*)&Cadd[o0];
                float2 t1 = *(const float2*)&Cadd[o1];
                v0.x += t0.x; v0.y += t0.y;
                v1.x += t1.x; v1.y += t1.y;
            }
            if (RELU) {
                v0.x = fmaxf(v0.x, 0.f); v0.y = fmaxf(v0.y, 0.f);
                v1.x = fmaxf(v1.x, 0.f); v1.y = fmaxf(v1.y, 0.f);
            }
            if (OUTK == 2) {
                ((__half2*)C)[o0 >> 1] = __floats2half2_rn(v0.x, v0.y);
                ((__half2*)C)[o1 >> 1] = __floats2half2_rn(v1.x, v1.y);
            } else {
                *(float2*)&((float*)C)[o0] = v0;
                *(float2*)&((float*)C)[o1] = v1;
            }
        }
    }
}

template <bool RELU, bool ADD, int OUTK>
__global__ __launch_bounds__(256, 2)
void gemmh(const __half* __restrict__ A, const __half* __restrict__ B,
           const float* __restrict__ Cadd, void* __restrict__ C,
           int N, int K) {
    gemmh_core<RELU, ADD, OUTK>(A, B, Cadd, C, N, K, blockIdx.y * 128, blockIdx.x * 128);
}

// Fused QKV: grid.x = 3 * (DMODEL/128); block picks its weight/output. fp16 outs.
__global__ __launch_bounds__(256, 2)
void gemmh_qkv(const __half* __restrict__ A,
               const __half* __restrict__ Wq, const __half* __restrict__ Wk,
               const __half* __restrict__ Wv,
               __half* __restrict__ Cq, __half* __restrict__ Ck, __half* __restrict__ Cv) {
    int nblk = DMODEL / 128;                 // 6
    int which = blockIdx.x / nblk;
    int n0 = (blockIdx.x % nblk) * 128;
    const __half* B = (which == 0) ? Wq : (which == 1) ? Wk : Wv;
    __half* C = (which == 0) ? Cq : (which == 1) ? Ck : Cv;
    gemmh_core<false, false, 2>(A, B, nullptr, C, DMODEL, DMODEL, blockIdx.y * 128, n0);
}

// ---------------- fp16 tensor-core flash attention ----------------
// grid (SEQ/128, NHEADS, BATCH), 256 threads = 8 warps; warp owns 16 q-rows.
// 128 q-rows per block => each 64-key K/V tile feeds 8 warps (2x reuse vs R8).
// QK^T: Q A-frags (preloaded), K B-frags via ldmatrix ({f0,f2},{f1,f3}).
// PV:   P A-frags via ldmatrix, V B-frags via ldmatrix.trans ({f0,f1},{f2,f3}).
#define AH_STR 72
#define AH_TILE (64 * AH_STR)               // halves per 64-row tile
#define AH_SMEM_BYTES ((4 * AH_TILE + 128 * AH_STR) * 2)   // 2xK,2xV + 128-row Q/P = 55296

__global__ __launch_bounds__(256, 2)
void attn_h(const __half* __restrict__ Q, const __half* __restrict__ K,
            const __half* __restrict__ V, __half* __restrict__ O) {
    extern __shared__ __half smah[];
    __half* Ks[2] = { smah, smah + AH_TILE };
    __half* Vs[2] = { smah + 2 * AH_TILE, smah + 3 * AH_TILE };
    __half* QP = smah + 4 * AH_TILE;         // Q tile (128 rows), then reused as P

    int tid = threadIdx.x;                   // 256
    int b = blockIdx.z, h = blockIdx.y;
    int q0 = blockIdx.x * 128;
    int warp = tid >> 5, lane = tid & 31;
    int gid = lane >> 2, tig = lane & 3;
    int lr = lane & 15, lc = lane >> 4;
    int wm = warp * 16;

    const __half* qbase = Q + (size_t)b * SEQ * DMODEL + h * DHEAD;
    const __half* kbase = K + (size_t)b * SEQ * DMODEL + h * DHEAD;
    const __half* vbase = V + (size_t)b * SEQ * DMODEL + h * DHEAD;

    // stage Q tile: 128 rows x 64 halves = 1024 16B-chunks
    for (int i = tid; i < 1024; i += 256) {
        int r = i >> 3, c8 = (i & 7) * 8;
        *(uint4*)&QP[r * AH_STR + c8] = *(const uint4*)&qbase[(size_t)(q0 + r) * DMODEL + c8];
    }
    auto loadKV = [&](int t, int buf) {
        int j0 = t * 64;
        #pragma unroll
        for (int i = 0; i < 2; i++) {
            int c = tid + 256 * i;           // 512 chunks per tensor
            int r = c >> 3, c8 = (c & 7) * 8;
            CP_ASYNC16(smem_u32(&Ks[buf][r * AH_STR + c8]), kbase + (size_t)(j0 + r) * DMODEL + c8);
            CP_ASYNC16(smem_u32(&Vs[buf][r * AH_STR + c8]), vbase + (size_t)(j0 + r) * DMODEL + c8);
        }
    };
    loadKV(0, 0);
    CP_COMMIT();
    __syncthreads();

    // preload Q fragments (4 k16 chunks)
    uint32_t qb = smem_u32(QP);
    uint32_t qf[4][4];
    #pragma unroll
    for (int kc = 0; kc < 4; kc++)
        LDSM_X4(qf[kc], qb + ((wm + lr) * AH_STR + kc * 16 + 8 * lc) * 2);
    // QP rows [wm, wm+16) now warp-private: reuse as P

    float m0r = -1e30f, m1r = -1e30f, l0 = 0.f, l1 = 0.f;
    float o[8][4] = {};

    const int NT = SEQ / 64;
    int cur = 0;
    for (int t = 0; t < NT; t++) {
        if (t + 1 < NT) {
            loadKV(t + 1, cur ^ 1);
            CP_COMMIT();
            CP_WAIT(1);
        } else {
            CP_WAIT(0);
        }
        __syncthreads();

        uint32_t kb = smem_u32(Ks[cur]);
        uint32_t vb = smem_u32(Vs[cur]);

        // S = Q * K^T (warp: 16 x 64)
        float s[8][4] = {};
        #pragma unroll
        for (int kc = 0; kc < 4; kc++) {
            #pragma unroll
            for (int nt = 0; nt < 4; nt++) {
                uint32_t kf[4];
                LDSM_X4(kf, kb + ((nt * 16 + lr) * AH_STR + kc * 16 + 8 * lc) * 2);
                uint32_t b0[2] = { kf[0], kf[2] }, b1[2] = { kf[1], kf[3] };
                mma_f16(s[2 * nt],     qf[kc], b0);
                mma_f16(s[2 * nt + 1], qf[kc], b1);
            }
        }

        float mx0 = -1e30f, mx1 = -1e30f;
        #pragma unroll
        for (int j = 0; j < 8; j++) {
            s[j][0] *= 0.125f; s[j][1] *= 0.125f; s[j][2] *= 0.125f; s[j][3] *= 0.125f;
            mx0 = fmaxf(mx0, fmaxf(s[j][0], s[j][1]));
            mx1 = fmaxf(mx1, fmaxf(s[j][2], s[j][3]));
        }
        mx0 = fmaxf(mx0, __shfl_xor_sync(0xffffffffu, mx0, 1));
        mx0 = fmaxf(mx0, __shfl_xor_sync(0xffffffffu, mx0, 2));
        mx1 = fmaxf(mx1, __shfl_xor_sync(0xffffffffu, mx1, 1));
        mx1 = fmaxf(mx1, __shfl_xor_sync(0xffffffffu, mx1, 2));

        float mn0 = fmaxf(m0r, mx0), mn1 = fmaxf(m1r, mx1);
        float al0 = __expf(m0r - mn0), al1 = __expf(m1r - mn1);
        m0r = mn0; m1r = mn1;

        float ls0 = 0.f, ls1 = 0.f;
        #pragma unroll
        for (int j = 0; j < 8; j++) {
            float p0 = __expf(s[j][0] - mn0);
            float p1 = __expf(s[j][1] - mn0);
            float p2 = __expf(s[j][2] - mn1);
            float p3 = __expf(s[j][3] - mn1);
            ls0 += p0 + p1; ls1 += p2 + p3;
            *(__half2*)&QP[(wm + gid) * AH_STR + j * 8 + 2 * tig]     = __floats2half2_rn(p0, p1);
            *(__half2*)&QP[(wm + gid + 8) * AH_STR + j * 8 + 2 * tig] = __floats2half2_rn(p2, p3);
        }
        ls0 += __shfl_xor_sync(0xffffffffu, ls0, 1);
        ls0 += __shfl_xor_sync(0xffffffffu, ls0, 2);
        ls1 += __shfl_xor_sync(0xffffffffu, ls1, 1);
        ls1 += __shfl_xor_sync(0xffffffffu, ls1, 2);
        l0 = l0 * al0 + ls0;
        l1 = l1 * al1 + ls1;

        #pragma unroll
        for (int j = 0; j < 8; j++) {
            o[j][0] *= al0; o[j][1] *= al0; o[j][2] *= al1; o[j][3] *= al1;
        }
        __syncwarp();

        // O += P * V (warp: 16 x 64; k = keys)
        #pragma unroll
        for (int kc = 0; kc < 4; kc++) {
            uint32_t pf[4];
            LDSM_X4(pf, qb + ((wm + lr) * AH_STR + kc * 16 + 8 * lc) * 2);
            #pragma unroll
            for (int nt = 0; nt < 4; nt++) {
                uint32_t vf[4];
                LDSM_X4_T(vf, vb + ((kc * 16 + lr) * AH_STR + nt * 16 + 8 * lc) * 2);
                mma_f16(o[2 * nt],     pf, vf);
                mma_f16(o[2 * nt + 1], pf, vf + 2);
            }
        }
        __syncthreads();
        cur ^= 1;
    }

    float inv0 = 1.0f / l0, inv1 = 1.0f / l1;
    __half* ob0 = O + ((size_t)b * SEQ + q0 + wm + gid) * DMODEL + h * DHEAD;
    __half* ob1 = O + ((size_t)b * SEQ + q0 + wm + gid + 8) * DMODEL + h * DHEAD;
    #pragma unroll
    for (int j = 0; j < 8; j++) {
        *(__half2*)&ob0[j * 8 + 2 * tig] = __floats2half2_rn(o[j][0] * inv0, o[j][1] * inv0);
        *(__half2*)&ob1[j * 8 + 2 * tig] = __floats2half2_rn(o[j][2] * inv1, o[j][3] * inv1);
    }
}

// ---------------- launch ----------------
extern "C" void kernel_launch(void* const* d_in, const int* in_sizes, int n_in,
                              void* d_out, int out_size) {
    const float* x      = (const float*)d_in[0];
    const float* Wq     = (const float*)d_in[1];
    const float* Wk     = (const float*)d_in[2];
    const float* Wv     = (const float*)d_in[3];
    const float* Wo     = (const float*)d_in[4];
    const float* W1     = (const float*)d_in[5];
    const float* W2     = (const float*)d_in[6];
    const float* gamma1 = (const float*)d_in[7];
    const float* beta1  = (const float*)d_in[8];
    const float* gamma2 = (const float*)d_in[9];
    const float* beta2  = (const float*)d_in[10];
    float* out = (float*)d_out;

    __half *h, *q, *k, *v, *ctx, *h2, *mid, *wqh, *wkh, *wvh, *woh, *w1h, *w2h;
    float *res1;
    cudaGetSymbolAddress((void**)&h,    g_h);
    cudaGetSymbolAddress((void**)&q,    g_q);
    cudaGetSymbolAddress((void**)&k,    g_k);
    cudaGetSymbolAddress((void**)&v,    g_v);
    cudaGetSymbolAddress((void**)&ctx,  g_ctx);
    cudaGetSymbolAddress((void**)&res1, g_res1);
    cudaGetSymbolAddress((void**)&h2,   g_h2);
    cudaGetSymbolAddress((void**)&mid,  g_mid);
    cudaGetSymbolAddress((void**)&wqh,  g_wqh);
    cudaGetSymbolAddress((void**)&wkh,  g_wkh);
    cudaGetSymbolAddress((void**)&wvh,  g_wvh);
    cudaGetSymbolAddress((void**)&woh,  g_woh);
    cudaGetSymbolAddress((void**)&w1h,  g_w1h);
    cudaGetSymbolAddress((void**)&w2h,  g_w2h);

    cudaFuncSetAttribute(attn_h, cudaFuncAttributeMaxDynamicSharedMemorySize, AH_SMEM_BYTES);
    cudaFuncSetAttribute(gemmh<false, true, 0>, cudaFuncAttributeMaxDynamicSharedMemorySize, HG_SMEM_BYTES);
    cudaFuncSetAttribute(gemmh<true, false, 2>, cudaFuncAttributeMaxDynamicSharedMemorySize, HG_SMEM_BYTES);
    cudaFuncSetAttribute(gemmh_qkv, cudaFuncAttributeMaxDynamicSharedMemorySize, HG_SMEM_BYTES);

    // 0. convert all weights fp32 -> fp16 (single launch)
    cvt_all<<<dim3((CVT_DH + 255) / 256, 6), 256>>>(Wq, Wk, Wv, Wo, W1, W2,
                                                    wqh, wkh, wvh, woh, w1h, w2h);

    // 1. LN1 -> h (fp16)
    layernorm_kernel<<<NTOK, 256>>>(x, gamma1, beta1, h);

    // 2. fused QKV projection -> q,k,v (fp16)
    gemmh_qkv<<<dim3(3 * DMODEL / 128, NTOK / 128), 256, HG_SMEM_BYTES>>>(h, wqh, wkh, wvh, q, k, v);

    // 3. attention -> ctx (fp16)
    attn_h<<<dim3(SEQ / 128, NHEADS, BATCH), 256, AH_SMEM_BYTES>>>(q, k, v, ctx);

    // 4. output projection + residual: res1 = x + ctx @ Wo (fp32)
    gemmh<false, true, 0><<<dim3(DMODEL / 128, NTOK / 128), 256, HG_SMEM_BYTES>>>(ctx, woh, x, res1, DMODEL, DMODEL);

    // 5. LN2 -> h2 (fp16)
    layernorm_kernel<<<NTOK, 256>>>(res1, gamma2, beta2, h2);

    // 6. FFN
    gemmh<true, false, 2><<<dim3(DHID / 128, NTOK / 128), 256, HG_SMEM_BYTES>>>(h2, w1h, nullptr, mid, DHID, DMODEL);
    gemmh<false, true, 0><<<dim3(DMODEL / 128, NTOK / 128), 256, HG_SMEM_BYTES>>>(mid, w2h, res1, out, DMODEL, DHID);
}

// round 13
// speedup vs baseline: 9.0793x; 1.0348x over previous
#include <cuda_runtime.h>
#include <cuda_fp16.h>
#include <math.h>
#include <stdint.h>

// Problem constants (EncoderLayer: B=2, S=2048, D=768, H=3072, 12 heads x 64)
#define BATCH 2
#define SEQ 2048
#define NTOK (BATCH * SEQ)          // 4096
#define DMODEL 768
#define DHID 3072
#define NHEADS 12
#define DHEAD 64
#define LN_EPS 1e-7f

// ---------------- scratch (no allocations allowed) ----------------
__device__ __half g_h[NTOK * DMODEL];    // ln1 output (fp16)
__device__ __half g_q[NTOK * DMODEL];    // fp16 (for attn)
__device__ __half g_k[NTOK * DMODEL];
__device__ __half g_v[NTOK * DMODEL];
__device__ __half g_ctx[NTOK * DMODEL];  // attention output (fp16)
__device__ float  g_res1[NTOK * DMODEL]; // x + attn_out (full fp32)
__device__ __half g_h2[NTOK * DMODEL];   // ln2 output (fp16)
__device__ __half g_mid[NTOK * DHID];    // relu(h2 @ W1) (fp16)
// fp16 weight copies (row-major [K][N], as given)
__device__ __half g_wqh[DMODEL * DMODEL];
__device__ __half g_wkh[DMODEL * DMODEL];
__device__ __half g_wvh[DMODEL * DMODEL];
__device__ __half g_woh[DMODEL * DMODEL];
__device__ __half g_w1h[DMODEL * DHID];
__device__ __half g_w2h[DHID * DMODEL];

// ---------------- common PTX helpers ----------------
__device__ __forceinline__ void mma_f16(float* c, const uint32_t* a, const uint32_t* b) {
    asm volatile(
        "mma.sync.aligned.m16n8k16.row.col.f32.f16.f16.f32 "
        "{%0,%1,%2,%3}, {%4,%5,%6,%7}, {%8,%9}, {%0,%1,%2,%3};"
        : "+f"(c[0]), "+f"(c[1]), "+f"(c[2]), "+f"(c[3])
        : "r"(a[0]), "r"(a[1]), "r"(a[2]), "r"(a[3]), "r"(b[0]), "r"(b[1]));
}
#define LDSM_X4(r, addr) \
    asm volatile("ldmatrix.sync.aligned.m8n8.x4.shared.b16 {%0,%1,%2,%3}, [%4];" \
                 : "=r"((r)[0]), "=r"((r)[1]), "=r"((r)[2]), "=r"((r)[3]) : "r"(addr))
#define LDSM_X4_T(r, addr) \
    asm volatile("ldmatrix.sync.aligned.m8n8.x4.trans.shared.b16 {%0,%1,%2,%3}, [%4];" \
                 : "=r"((r)[0]), "=r"((r)[1]), "=r"((r)[2]), "=r"((r)[3]) : "r"(addr))
#define CP_ASYNC16(dst, src) \
    asm volatile("cp.async.cg.shared.global [%0], [%1], 16;\n" :: "r"(dst), "l"(src))
#define CP_COMMIT() asm volatile("cp.async.commit_group;\n" ::)
#define CP_WAIT(n)  asm volatile("cp.async.wait_group %0;\n" :: "n"(n))

__device__ __forceinline__ uint32_t smem_u32(const void* p) {
    uint32_t a;
    asm("{ .reg .u64 t; cvta.to.shared.u64 t, %1; cvt.u32.u64 %0, t; }" : "=r"(a) : "l"(p));
    return a;
}
// pack two floats into one u32 holding 2 fp16 values (union-based reinterpret)
__device__ __forceinline__ uint32_t pack_h2(float a, float b) {
    union { __half2 h; uint32_t u; } cvt;
    cvt.h = __floats2half2_rn(a, b);
    return cvt.u;
}

// ---------------- fused weight fp32 -> fp16 convert (all 6 weights) ----------------
#define CVT_DD (DMODEL * DMODEL / 4)     // 147456 float4s
#define CVT_DH (DMODEL * DHID / 4)       // 589824 float4s
__global__ void cvt_all(const float* __restrict__ s0, const float* __restrict__ s1,
                        const float* __restrict__ s2, const float* __restrict__ s3,
                        const float* __restrict__ s4, const float* __restrict__ s5,
                        __half* __restrict__ d0, __half* __restrict__ d1,
                        __half* __restrict__ d2, __half* __restrict__ d3,
                        __half* __restrict__ d4, __half* __restrict__ d5) {
    int w = blockIdx.y;
    const float* src = (w == 0) ? s0 : (w == 1) ? s1 : (w == 2) ? s2
                     : (w == 3) ? s3 : (w == 4) ? s4 : s5;
    __half* dst = (w == 0) ? d0 : (w == 1) ? d1 : (w == 2) ? d2
                : (w == 3) ? d3 : (w == 4) ? d4 : d5;
    int n4 = (w < 4) ? CVT_DD : CVT_DH;
    int i = blockIdx.x * blockDim.x + threadIdx.x;
    if (i < n4) {
        float4 v = ((const float4*)src)[i];
        ((__half2*)dst)[2 * i]     = __floats2half2_rn(v.x, v.y);
        ((__half2*)dst)[2 * i + 1] = __floats2half2_rn(v.z, v.w);
    }
}

// ---------------- LayerNorm (ddof=1), output fp16 ----------------
__global__ void layernorm_kernel(const float* __restrict__ x,
                                 const float* __restrict__ gamma,
                                 const float* __restrict__ beta,
                                 __half* __restrict__ y) {
    int row = blockIdx.x;
    int tid = threadIdx.x;
    const float* xr = x + (size_t)row * DMODEL;

    float v0 = xr[tid];
    float v1 = xr[tid + 256];
    float v2 = xr[tid + 512];

    float sum = v0 + v1 + v2;
    float ss  = v0 * v0 + v1 * v1 + v2 * v2;

    #pragma unroll
    for (int o = 16; o > 0; o >>= 1) {
        sum += __shfl_xor_sync(0xffffffffu, sum, o);
        ss  += __shfl_xor_sync(0xffffffffu, ss, o);
    }
    __shared__ float wsum[8], wss[8];
    int warp = tid >> 5, lane = tid & 31;
    if (lane == 0) { wsum[warp] = sum; wss[warp] = ss; }
    __syncthreads();
    float tot = 0.f, tots = 0.f;
    #pragma unroll
    for (int w = 0; w < 8; w++) { tot += wsum[w]; tots += wss[w]; }

    float mean = tot * (1.0f / DMODEL);
    float var  = (tots - tot * tot * (1.0f / DMODEL)) * (1.0f / (DMODEL - 1));
    var = fmaxf(var, 0.0f);
    float inv = 1.0f / (sqrtf(var) + LN_EPS);

    __half* yr = y + (size_t)row * DMODEL;
    yr[tid]       = __float2half(gamma[tid]       * (v0 - mean) * inv + beta[tid]);
    yr[tid + 256] = __float2half(gamma[tid + 256] * (v1 - mean) * inv + beta[tid + 256]);
    yr[tid + 512] = __float2half(gamma[tid + 512] * (v2 - mean) * inv + beta[tid + 512]);
}

// ---------------- fp16 tensor-core GEMM (m16n8k16, fp32 accum) ----------------
#define HG_SA 72                     // A row stride in halves (64 + 8)
#define HG_SB 136                    // B row stride in halves (128 + 8)
#define HG_A_HALVES (128 * HG_SA)    // 9216
#define HG_B_HALVES (64 * HG_SB)     // 8704
#define HG_STAGE_HALVES (HG_A_HALVES + HG_B_HALVES)
#define HG_SMEM_BYTES (2 * HG_STAGE_HALVES * 2)    // 71680

// OUTK: 0 = float raw, 2 = half
template <bool RELU, bool ADD, int OUTK>
__device__ __forceinline__
void gemmh_core(const __half* __restrict__ A, const __half* __restrict__ B,
                const float* __restrict__ Cadd, void* __restrict__ C,
                int N, int K, int m0, int n0) {
    extern __shared__ __half smh[];
    __half* As[2] = { smh, smh + HG_STAGE_HALVES };
    __half* Bs[2] = { smh + HG_A_HALVES, smh + HG_STAGE_HALVES + HG_A_HALVES };

    int tid = threadIdx.x;              // 256
    int warp = tid >> 5, lane = tid & 31;
    int gid = lane >> 2, tig = lane & 3;
    int wm = (warp & 3) * 32, wn = (warp >> 2) * 64;
    int lr = lane & 15, lc = lane >> 4;  // ldmatrix addressing

    float acc[2][8][4] = {};

    auto fill = [&](__half* as, __half* bs, int k0) {
        #pragma unroll
        for (int i = 0; i < 4; i++) {
            int c = tid + 256 * i;          // A: 1024 chunks = 128 rows x 8
            int r = c >> 3, cc = c & 7;
            uint32_t dst = smem_u32(as + r * HG_SA + cc * 8);
            CP_ASYNC16(dst, A + (size_t)(m0 + r) * K + k0 + cc * 8);
        }
        #pragma unroll
        for (int i = 0; i < 4; i++) {
            int c = tid + 256 * i;          // B: 1024 chunks = 64 rows x 16
            int r = c >> 4, cc = c & 15;
            uint32_t dst = smem_u32(bs + r * HG_SB + cc * 8);
            CP_ASYNC16(dst, B + (size_t)(k0 + r) * N + n0 + cc * 8);
        }
    };

    fill(As[0], Bs[0], 0);
    CP_COMMIT();

    int nIter = K >> 6;                 // BK = 64
    int cur = 0;
    for (int it = 0; it < nIter; it++) {
        if (it + 1 < nIter) {
            fill(As[cur ^ 1], Bs[cur ^ 1], (it + 1) * 64);
            CP_COMMIT();
            CP_WAIT(1);
        } else {
            CP_WAIT(0);
        }
        __syncthreads();

        uint32_t abase = smem_u32(As[cur]);
        uint32_t bbase = smem_u32(Bs[cur]);
        #pragma unroll
        for (int kc16 = 0; kc16 < 4; kc16++) {
            int kc = kc16 * 16;
            uint32_t af[2][4], bf[4][4];
            #pragma unroll
            for (int i = 0; i < 2; i++)
                LDSM_X4(af[i], abase + ((wm + i * 16 + lr) * HG_SA + kc + 8 * lc) * 2);
            #pragma unroll
            for (int jj = 0; jj < 4; jj++)
                LDSM_X4_T(bf[jj], bbase + ((kc + lr) * HG_SB + wn + jj * 16 + 8 * lc) * 2);
            #pragma unroll
            for (int i = 0; i < 2; i++)
                #pragma unroll
                for (int j = 0; j < 8; j++)
                    mma_f16(acc[i][j], af[i], &bf[j >> 1][(j & 1) * 2]);
        }
        __syncthreads();
        cur ^= 1;
    }

    #pragma unroll
    for (int i = 0; i < 2; i++) {
        int r = m0 + wm + i * 16 + gid;
        #pragma unroll
        for (int j = 0; j < 8; j++) {
            int cc = n0 + wn + j * 8 + 2 * tig;
            size_t o0 = (size_t)r * N + cc;
            size_t o1 = (size_t)(r + 8) * N + cc;
            float2 v0 = make_float2(acc[i][j][0], acc[i][j][1]);
            float2 v1 = make_float2(acc[i][j][2], acc[i][j][3]);
            if (ADD) {
                float2 t0 = *(const float2*)&Cadd[o0];
                float2 t1 = *(const float2*)&Cadd[o1];
                v0.x += t0.x; v0.y += t0.y;
                v1.x += t1.x; v1.y += t1.y;
            }
            if (RELU) {
                v0.x = fmaxf(v0.x, 0.f); v0.y = fmaxf(v0.y, 0.f);
                v1.x = fmaxf(v1.x, 0.f); v1.y = fmaxf(v1.y, 0.f);
            }
            if (OUTK == 2) {
                ((__half2*)C)[o0 >> 1] = __floats2half2_rn(v0.x, v0.y);
                ((__half2*)C)[o1 >> 1] = __floats2half2_rn(v1.x, v1.y);
            } else {
                *(float2*)&((float*)C)[o0] = v0;
                *(float2*)&((float*)C)[o1] = v1;
            }
        }
    }
}

template <bool RELU, bool ADD, int OUTK>
__global__ __launch_bounds__(256, 2)
void gemmh(const __half* __restrict__ A, const __half* __restrict__ B,
           const float* __restrict__ Cadd, void* __restrict__ C,
           int N, int K) {
    gemmh_core<RELU, ADD, OUTK>(A, B, Cadd, C, N, K, blockIdx.y * 128, blockIdx.x * 128);
}

// Fused QKV: grid.x = 3 * (DMODEL/128); block picks its weight/output. fp16 outs.
__global__ __launch_bounds__(256, 2)
void gemmh_qkv(const __half* __restrict__ A,
               const __half* __restrict__ Wq, const __half* __restrict__ Wk,
               const __half* __restrict__ Wv,
               __half* __restrict__ Cq, __half* __restrict__ Ck, __half* __restrict__ Cv) {
    int nblk = DMODEL / 128;                 // 6
    int which = blockIdx.x / nblk;
    int n0 = (blockIdx.x % nblk) * 128;
    const __half* B = (which == 0) ? Wq : (which == 1) ? Wk : Wv;
    __half* C = (which == 0) ? Cq : (which == 1) ? Ck : Cv;
    gemmh_core<false, false, 2>(A, B, nullptr, C, DMODEL, DMODEL, blockIdx.y * 128, n0);
}

// ---------------- fp16 tensor-core flash attention (P in registers) ----------------
// grid (SEQ/128, NHEADS, BATCH), 256 threads = 8 warps; warp owns 16 q-rows.
// QK^T: Q A-frags (preloaded), K B-frags via ldmatrix ({f0,f2},{f1,f3}).
// PV:   P A-frags built IN REGISTERS from the S accumulator (m16n8 C-frag layout
//       matches the A-frag layout of the next m16n8k16), V via ldmatrix.trans.
// Softmax in exp2 domain: fold 0.125*log2e into the scale, single EX2 per element.
#define AH_STR 72
#define AH_TILE (64 * AH_STR)               // halves per 64-row tile
#define AH_SMEM_BYTES ((4 * AH_TILE + 128 * AH_STR) * 2)   // 55296
#define QK_SCALE_LOG2 0.18033688f           // 0.125 * log2(e)

__global__ __launch_bounds__(256, 2)
void attn_h(const __half* __restrict__ Q, const __half* __restrict__ K,
            const __half* __restrict__ V, __half* __restrict__ O) {
    extern __shared__ __half smah[];
    __half* Ks[2] = { smah, smah + AH_TILE };
    __half* Vs[2] = { smah + 2 * AH_TILE, smah + 3 * AH_TILE };
    __half* QP = smah + 4 * AH_TILE;         // Q staging (128 rows)

    int tid = threadIdx.x;                   // 256
    int b = blockIdx.z, h = blockIdx.y;
    int q0 = blockIdx.x * 128;
    int warp = tid >> 5, lane = tid & 31;
    int gid = lane >> 2, tig = lane & 3;
    int lr = lane & 15, lc = lane >> 4;
    int wm = warp * 16;

    const __half* qbase = Q + (size_t)b * SEQ * DMODEL + h * DHEAD;
    const __half* kbase = K + (size_t)b * SEQ * DMODEL + h * DHEAD;
    const __half* vbase = V + (size_t)b * SEQ * DMODEL + h * DHEAD;

    // stage Q tile: 128 rows x 64 halves = 1024 16B-chunks
    for (int i = tid; i < 1024; i += 256) {
        int r = i >> 3, c8 = (i & 7) * 8;
        *(uint4*)&QP[r * AH_STR + c8] = *(const uint4*)&qbase[(size_t)(q0 + r) * DMODEL + c8];
    }
    auto loadKV = [&](int t, int buf) {
        int j0 = t * 64;
        #pragma unroll
        for (int i = 0; i < 2; i++) {
            int c = tid + 256 * i;           // 512 chunks per tensor
            int r = c >> 3, c8 = (c & 7) * 8;
            CP_ASYNC16(smem_u32(&Ks[buf][r * AH_STR + c8]), kbase + (size_t)(j0 + r) * DMODEL + c8);
            CP_ASYNC16(smem_u32(&Vs[buf][r * AH_STR + c8]), vbase + (size_t)(j0 + r) * DMODEL + c8);
        }
    };
    loadKV(0, 0);
    CP_COMMIT();
    __syncthreads();

    // preload Q fragments (4 k16 chunks)
    uint32_t qb = smem_u32(QP);
    uint32_t qf[4][4];
    #pragma unroll
    for (int kc = 0; kc < 4; kc++)
        LDSM_X4(qf[kc], qb + ((wm + lr) * AH_STR + kc * 16 + 8 * lc) * 2);

    float m0r = -1e30f, m1r = -1e30f, l0 = 0.f, l1 = 0.f;  // log2-domain maxima
    float o[8][4] = {};

    const int NT = SEQ / 64;
    int cur = 0;
    for (int t = 0; t < NT; t++) {
        if (t + 1 < NT) {
            loadKV(t + 1, cur ^ 1);
            CP_COMMIT();
            CP_WAIT(1);
        } else {
            CP_WAIT(0);
        }
        __syncthreads();

        uint32_t kb = smem_u32(Ks[cur]);
        uint32_t vb = smem_u32(Vs[cur]);

        // S = Q * K^T (warp: 16 x 64)
        float s[8][4] = {};
        #pragma unroll
        for (int kc = 0; kc < 4; kc++) {
            #pragma unroll
            for (int nt = 0; nt < 4; nt++) {
                uint32_t kf[4];
                LDSM_X4(kf, kb + ((nt * 16 + lr) * AH_STR + kc * 16 + 8 * lc) * 2);
                uint32_t b0[2] = { kf[0], kf[2] }, b1[2] = { kf[1], kf[3] };
                mma_f16(s[2 * nt],     qf[kc], b0);
                mma_f16(s[2 * nt + 1], qf[kc], b1);
            }
        }

        // scale into log2 domain + row-max
        float mx0 = -1e30f, mx1 = -1e30f;
        #pragma unroll
        for (int j = 0; j < 8; j++) {
            s[j][0] *= QK_SCALE_LOG2; s[j][1] *= QK_SCALE_LOG2;
            s[j][2] *= QK_SCALE_LOG2; s[j][3] *= QK_SCALE_LOG2;
            mx0 = fmaxf(mx0, fmaxf(s[j][0], s[j][1]));
            mx1 = fmaxf(mx1, fmaxf(s[j][2], s[j][3]));
        }
        mx0 = fmaxf(mx0, __shfl_xor_sync(0xffffffffu, mx0, 1));
        mx0 = fmaxf(mx0, __shfl_xor_sync(0xffffffffu, mx0, 2));
        mx1 = fmaxf(mx1, __shfl_xor_sync(0xffffffffu, mx1, 1));
        mx1 = fmaxf(mx1, __shfl_xor_sync(0xffffffffu, mx1, 2));

        float mn0 = fmaxf(m0r, mx0), mn1 = fmaxf(m1r, mx1);
        float al0 = exp2f(m0r - mn0), al1 = exp2f(m1r - mn1);
        m0r = mn0; m1r = mn1;

        // p = 2^(s - mn); build PV A-fragments directly in registers
        uint32_t pf[4][4];
        float ls0 = 0.f, ls1 = 0.f;
        #pragma unroll
        for (int j = 0; j < 8; j++) {
            float p0 = exp2f(s[j][0] - mn0);
            float p1 = exp2f(s[j][1] - mn0);
            float p2 = exp2f(s[j][2] - mn1);
            float p3 = exp2f(s[j][3] - mn1);
            ls0 += p0 + p1; ls1 += p2 + p3;
            // j = 2*kc + half: A-frag regs {a0,a1} come from S-tile 2kc, {a2,a3} from 2kc+1
            pf[j >> 1][(j & 1) * 2]     = pack_h2(p0, p1);   // rows gid
            pf[j >> 1][(j & 1) * 2 + 1] = pack_h2(p2, p3);   // rows gid+8
        }
        ls0 += __shfl_xor_sync(0xffffffffu, ls0, 1);
        ls0 += __shfl_xor_sync(0xffffffffu, ls0, 2);
        ls1 += __shfl_xor_sync(0xffffffffu, ls1, 1);
        ls1 += __shfl_xor_sync(0xffffffffu, ls1, 2);
        l0 = l0 * al0 + ls0;
        l1 = l1 * al1 + ls1;

        #pragma unroll
        for (int j = 0; j < 8; j++) {
            o[j][0] *= al0; o[j][1] *= al0; o[j][2] *= al1; o[j][3] *= al1;
        }

        // O += P * V (warp: 16 x 64; k = keys)
        #pragma unroll
        for (int kc = 0; kc < 4; kc++) {
            #pragma unroll
            for (int nt = 0; nt < 4; nt++) {
                uint32_t vf[4];
                LDSM_X4_T(vf, vb + ((kc * 16 + lr) * AH_STR + nt * 16 + 8 * lc) * 2);
                mma_f16(o[2 * nt],     pf[kc], vf);
                mma_f16(o[2 * nt + 1], pf[kc], vf + 2);
            }
        }
        __syncthreads();
        cur ^= 1;
    }

    float inv0 = 1.0f / l0, inv1 = 1.0f / l1;
    __half* ob0 = O + ((size_t)b * SEQ + q0 + wm + gid) * DMODEL + h * DHEAD;
    __half* ob1 = O + ((size_t)b * SEQ + q0 + wm + gid + 8) * DMODEL + h * DHEAD;
    #pragma unroll
    for (int j = 0; j < 8; j++) {
        *(__half2*)&ob0[j * 8 + 2 * tig] = __floats2half2_rn(o[j][0] * inv0, o[j][1] * inv0);
        *(__half2*)&ob1[j * 8 + 2 * tig] = __floats2half2_rn(o[j][2] * inv1, o[j][3] * inv1);
    }
}

// ---------------- launch ----------------
extern "C" void kernel_launch(void* const* d_in, const int* in_sizes, int n_in,
                              void* d_out, int out_size) {
    const float* x      = (const float*)d_in[0];
    const float* Wq     = (const float*)d_in[1];
    const float* Wk     = (const float*)d_in[2];
    const float* Wv     = (const float*)d_in[3];
    const float* Wo     = (const float*)d_in[4];
    const float* W1     = (const float*)d_in[5];
    const float* W2     = (const float*)d_in[6];
    const float* gamma1 = (const float*)d_in[7];
    const float* beta1  = (const float*)d_in[8];
    const float* gamma2 = (const float*)d_in[9];
    const float* beta2  = (const float*)d_in[10];
    float* out = (float*)d_out;

    __half *h, *q, *k, *v, *ctx, *h2, *mid, *wqh, *wkh, *wvh, *woh, *w1h, *w2h;
    float *res1;
    cudaGetSymbolAddress((void**)&h,    g_h);
    cudaGetSymbolAddress((void**)&q,    g_q);
    cudaGetSymbolAddress((void**)&k,    g_k);
    cudaGetSymbolAddress((void**)&v,    g_v);
    cudaGetSymbolAddress((void**)&ctx,  g_ctx);
    cudaGetSymbolAddress((void**)&res1, g_res1);
    cudaGetSymbolAddress((void**)&h2,   g_h2);
    cudaGetSymbolAddress((void**)&mid,  g_mid);
    cudaGetSymbolAddress((void**)&wqh,  g_wqh);
    cudaGetSymbolAddress((void**)&wkh,  g_wkh);
    cudaGetSymbolAddress((void**)&wvh,  g_wvh);
    cudaGetSymbolAddress((void**)&woh,  g_woh);
    cudaGetSymbolAddress((void**)&w1h,  g_w1h);
    cudaGetSymbolAddress((void**)&w2h,  g_w2h);

    cudaFuncSetAttribute(attn_h, cudaFuncAttributeMaxDynamicSharedMemorySize, AH_SMEM_BYTES);
    cudaFuncSetAttribute(gemmh<false, true, 0>, cudaFuncAttributeMaxDynamicSharedMemorySize, HG_SMEM_BYTES);
    cudaFuncSetAttribute(gemmh<true, false, 2>, cudaFuncAttributeMaxDynamicSharedMemorySize, HG_SMEM_BYTES);
    cudaFuncSetAttribute(gemmh_qkv, cudaFuncAttributeMaxDynamicSharedMemorySize, HG_SMEM_BYTES);

    // 0. convert all weights fp32 -> fp16 (single launch)
    cvt_all<<<dim3((CVT_DH + 255) / 256, 6), 256>>>(Wq, Wk, Wv, Wo, W1, W2,
                                                    wqh, wkh, wvh, woh, w1h, w2h);

    // 1. LN1 -> h (fp16)
    layernorm_kernel<<<NTOK, 256>>>(x, gamma1, beta1, h);

    // 2. fused QKV projection -> q,k,v (fp16)
    gemmh_qkv<<<dim3(3 * DMODEL / 128, NTOK / 128), 256, HG_SMEM_BYTES>>>(h, wqh, wkh, wvh, q, k, v);

    // 3. attention -> ctx (fp16)
    attn_h<<<dim3(SEQ / 128, NHEADS, BATCH), 256, AH_SMEM_BYTES>>>(q, k, v, ctx);

    // 4. output projection + residual: res1 = x + ctx @ Wo (fp32)
    gemmh<false, true, 0><<<dim3(DMODEL / 128, NTOK / 128), 256, HG_SMEM_BYTES>>>(ctx, woh, x, res1, DMODEL, DMODEL);

    // 5. LN2 -> h2 (fp16)
    layernorm_kernel<<<NTOK, 256>>>(res1, gamma2, beta2, h2);

    // 6. FFN
    gemmh<true, false, 2><<<dim3(DHID / 128, NTOK / 128), 256, HG_SMEM_BYTES>>>(h2, w1h, nullptr, mid, DHID, DMODEL);
    gemmh<false, true, 0><<<dim3(DMODEL / 128, NTOK / 128), 256, HG_SMEM_BYTES>>>(mid, w2h, res1, out, DMODEL, DHID);
}

// round 15
// speedup vs baseline: 9.4069x; 1.0361x over previous
#include <cuda_runtime.h>
#include <cuda_fp16.h>
#include <math.h>
#include <stdint.h>

// Problem constants (EncoderLayer: B=2, S=2048, D=768, H=3072, 12 heads x 64)
#define BATCH 2
#define SEQ 2048
#define NTOK (BATCH * SEQ)          // 4096
#define DMODEL 768
#define DHID 3072
#define NHEADS 12
#define DHEAD 64
#define LN_EPS 1e-7f
#define PIPE_DEPTH 3
#define QK_SCALE_LOG2 0.18033688f   // 0.125 * log2(e)

// ---------------- scratch (no allocations allowed) ----------------
__device__ __half g_h[NTOK * DMODEL];    // ln1 output (fp16)
__device__ __half g_q[NTOK * DMODEL];    // fp16, pre-scaled by 0.125*log2e
__device__ __half g_k[NTOK * DMODEL];
__device__ __half g_v[NTOK * DMODEL];
__device__ __half g_ctx[NTOK * DMODEL];  // attention output (fp16)
__device__ float  g_res1[NTOK * DMODEL]; // x + attn_out (full fp32)
__device__ __half g_h2[NTOK * DMODEL];   // ln2 output (fp16)
__device__ __half g_mid[NTOK * DHID];    // relu(h2 @ W1) (fp16)
// fp16 weight copies (row-major [K][N], as given)
__device__ __half g_wqh[DMODEL * DMODEL];
__device__ __half g_wkh[DMODEL * DMODEL];
__device__ __half g_wvh[DMODEL * DMODEL];
__device__ __half g_woh[DMODEL * DMODEL];
__device__ __half g_w1h[DMODEL * DHID];
__device__ __half g_w2h[DHID * DMODEL];

// ---------------- common PTX helpers ----------------
__device__ __forceinline__ void mma_f16(float* c, const uint32_t* a, const uint32_t* b) {
    asm volatile(
        "mma.sync.aligned.m16n8k16.row.col.f32.f16.f16.f32 "
        "{%0,%1,%2,%3}, {%4,%5,%6,%7}, {%8,%9}, {%0,%1,%2,%3};"
        : "+f"(c[0]), "+f"(c[1]), "+f"(c[2]), "+f"(c[3])
        : "r"(a[0]), "r"(a[1]), "r"(a[2]), "r"(a[3]), "r"(b[0]), "r"(b[1]));
}
#define LDSM_X4(r, addr) \
    asm volatile("ldmatrix.sync.aligned.m8n8.x4.shared.b16 {%0,%1,%2,%3}, [%4];" \
                 : "=r"((r)[0]), "=r"((r)[1]), "=r"((r)[2]), "=r"((r)[3]) : "r"(addr))
#define LDSM_X4_T(r, addr) \
    asm volatile("ldmatrix.sync.aligned.m8n8.x4.trans.shared.b16 {%0,%1,%2,%3}, [%4];" \
                 : "=r"((r)[0]), "=r"((r)[1]), "=r"((r)[2]), "=r"((r)[3]) : "r"(addr))
#define CP_ASYNC16(dst, src) \
    asm volatile("cp.async.cg.shared.global [%0], [%1], 16;\n" :: "r"(dst), "l"(src))
#define CP_COMMIT() asm volatile("cp.async.commit_group;\n" ::)
#define CP_WAIT(n)  asm volatile("cp.async.wait_group %0;\n" :: "n"(n))

__device__ __forceinline__ uint32_t smem_u32(const void* p) {
    uint32_t a;
    asm("{ .reg .u64 t; cvta.to.shared.u64 t, %1; cvt.u32.u64 %0, t; }" : "=r"(a) : "l"(p));
    return a;
}
// pack two floats into one u32 holding 2 fp16 values (union-based reinterpret)
__device__ __forceinline__ uint32_t pack_h2(float a, float b) {
    union { __half2 h; uint32_t u; } cvt;
    cvt.h = __floats2half2_rn(a, b);
    return cvt.u;
}

// ---------------- fused weight fp32 -> fp16 convert (all 6 weights) ----------------
#define CVT_DD (DMODEL * DMODEL / 4)     // 147456 float4s
#define CVT_DH (DMODEL * DHID / 4)       // 589824 float4s
__global__ void cvt_all(const float* __restrict__ s0, const float* __restrict__ s1,
                        const float* __restrict__ s2, const float* __restrict__ s3,
                        const float* __restrict__ s4, const float* __restrict__ s5,
                        __half* __restrict__ d0, __half* __restrict__ d1,
                        __half* __restrict__ d2, __half* __restrict__ d3,
                        __half* __restrict__ d4, __half* __restrict__ d5) {
    int wsel = blockIdx.y;
    const float* src = (wsel == 0) ? s0 : (wsel == 1) ? s1 : (wsel == 2) ? s2
                     : (wsel == 3) ? s3 : (wsel == 4) ? s4 : s5;
    __half* dst = (wsel == 0) ? d0 : (wsel == 1) ? d1 : (wsel == 2) ? d2
                : (wsel == 3) ? d3 : (wsel == 4) ? d4 : d5;
    int n4 = (wsel < 4) ? CVT_DD : CVT_DH;
    int i = blockIdx.x * blockDim.x + threadIdx.x;
    if (i < n4) {
        float4 v = ((const float4*)src)[i];
        ((__half2*)dst)[2 * i]     = __floats2half2_rn(v.x, v.y);
        ((__half2*)dst)[2 * i + 1] = __floats2half2_rn(v.z, v.w);
    }
}

// ---------------- LayerNorm (ddof=1), output fp16 ----------------
__global__ void layernorm_kernel(const float* __restrict__ x,
                                 const float* __restrict__ gamma,
                                 const float* __restrict__ beta,
                                 __half* __restrict__ y) {
    int row = blockIdx.x;
    int tid = threadIdx.x;
    const float* xr = x + (size_t)row * DMODEL;

    float v0 = xr[tid];
    float v1 = xr[tid + 256];
    float v2 = xr[tid + 512];

    float sum = v0 + v1 + v2;
    float ss  = v0 * v0 + v1 * v1 + v2 * v2;

    #pragma unroll
    for (int o = 16; o > 0; o >>= 1) {
        sum += __shfl_xor_sync(0xffffffffu, sum, o);
        ss  += __shfl_xor_sync(0xffffffffu, ss, o);
    }
    __shared__ float wsum[8], wss[8];
    int warp = tid >> 5, lane = tid & 31;
    if (lane == 0) { wsum[warp] = sum; wss[warp] = ss; }
    __syncthreads();
    float tot = 0.f, tots = 0.f;
    #pragma unroll
    for (int w = 0; w < 8; w++) { tot += wsum[w]; tots += wss[w]; }

    float mean = tot * (1.0f / DMODEL);
    float var  = (tots - tot * tot * (1.0f / DMODEL)) * (1.0f / (DMODEL - 1));
    var = fmaxf(var, 0.0f);
    float inv = 1.0f / (sqrtf(var) + LN_EPS);

    __half* yr = y + (size_t)row * DMODEL;
    yr[tid]       = __float2half(gamma[tid]       * (v0 - mean) * inv + beta[tid]);
    yr[tid + 256] = __float2half(gamma[tid + 256] * (v1 - mean) * inv + beta[tid + 256]);
    yr[tid + 512] = __float2half(gamma[tid + 512] * (v2 - mean) * inv + beta[tid + 512]);
}

// ---------------- fp16 tensor-core GEMM (m16n8k16, fp32 accum) ----------------
// 3-stage cp.async pipeline, ONE __syncthreads per K-iter.
#define HG_SA 72                     // A row stride in halves (64 + 8)
#define HG_SB 136                    // B row stride in halves (128 + 8)
#define HG_A_HALVES (128 * HG_SA)    // 9216
#define HG_B_HALVES (64 * HG_SB)     // 8704
#define HG_STAGE_HALVES (HG_A_HALVES + HG_B_HALVES)        // 17920
#define HG_SMEM_BYTES (PIPE_DEPTH * HG_STAGE_HALVES * 2)   // 107520

// OUTK: 0 = float raw, 2 = half (scaled by 'scale')
template <bool RELU, bool ADD, int OUTK>
__device__ __forceinline__
void gemmh_core(const __half* __restrict__ A, const __half* __restrict__ B,
                const float* __restrict__ Cadd, void* __restrict__ C,
                int N, int K, int m0, int n0, float scale) {
    extern __shared__ __half smh[];

    const int tid = threadIdx.x;              // 256
    const int warp = tid >> 5, lane = tid & 31;
    const int gid = lane >> 2, tig = lane & 3;
    const int wm = (warp & 3) * 32, wn = (warp >> 2) * 64;
    const int lr = lane & 15, lc = lane >> 4;  // ldmatrix addressing

    float acc[2][8][4] = {};

    auto fill = [&](int it, int st) {
        __half* as = smh + st * HG_STAGE_HALVES;
        __half* bs = as + HG_A_HALVES;
        const int k0 = it * 64;
        #pragma unroll
        for (int i = 0; i < 4; i++) {
            int c = tid + 256 * i;          // A: 1024 chunks = 128 rows x 8
            int r = c >> 3, cc = c & 7;
            CP_ASYNC16(smem_u32(as + r * HG_SA + cc * 8), A + (size_t)(m0 + r) * K + k0 + cc * 8);
        }
        #pragma unroll
        for (int i = 0; i < 4; i++) {
            int c = tid + 256 * i;          // B: 1024 chunks = 64 rows x 16
            int r = c >> 4, cc = c & 15;
            CP_ASYNC16(smem_u32(bs + r * HG_SB + cc * 8), B + (size_t)(k0 + r) * N + n0 + cc * 8);
        }
    };

    const int nIter = K >> 6;                 // BK = 64
    fill(0, 0); CP_COMMIT();
    fill(1, 1); CP_COMMIT();

    for (int it = 0; it < nIter; it++) {
        const int st = it % PIPE_DEPTH;
        if (it < nIter - 1) { CP_WAIT(1); } else { CP_WAIT(0); }
        __syncthreads();
        if (it + 2 < nIter) { fill(it + 2, (it + 2) % PIPE_DEPTH); CP_COMMIT(); }

        const uint32_t abase = smem_u32(smh + st * HG_STAGE_HALVES);
        const uint32_t bbase = abase + HG_A_HALVES * 2;
        #pragma unroll
        for (int kc16 = 0; kc16 < 4; kc16++) {
            const int kc = kc16 * 16;
            uint32_t af[2][4], bf[4][4];
            #pragma unroll
            for (int i = 0; i < 2; i++)
                LDSM_X4(af[i], abase + ((wm + i * 16 + lr) * HG_SA + kc + 8 * lc) * 2);
            #pragma unroll
            for (int jj = 0; jj < 4; jj++)
                LDSM_X4_T(bf[jj], bbase + ((kc + lr) * HG_SB + wn + jj * 16 + 8 * lc) * 2);
            #pragma unroll
            for (int i = 0; i < 2; i++)
                #pragma unroll
                for (int j = 0; j < 8; j++)
                    mma_f16(acc[i][j], af[i], &bf[j >> 1][(j & 1) * 2]);
        }
    }

    #pragma unroll
    for (int i = 0; i < 2; i++) {
        const int r = m0 + wm + i * 16 + gid;
        #pragma unroll
        for (int j = 0; j < 8; j++) {
            const int cc = n0 + wn + j * 8 + 2 * tig;
            const size_t o0 = (size_t)r * N + cc;
            const size_t o1 = (size_t)(r + 8) * N + cc;
            float2 v0 = make_float2(acc[i][j][0], acc[i][j][1]);
            float2 v1 = make_float2(acc[i][j][2], acc[i][j][3]);
            if (ADD) {
                float2 t0 = *(const float2*)&Cadd[o0];
                float2 t1 = *(const float2*)&Cadd[o1];
                v0.x += t0.x; v0.y += t0.y;
                v1.x += t1.x; v1.y += t1.y;
            }
            if (RELU) {
                v0.x = fmaxf(v0.x, 0.f); v0.y = fmaxf(v0.y, 0.f);
                v1.x = fmaxf(v1.x, 0.f); v1.y = fmaxf(v1.y, 0.f);
            }
            if (OUTK == 2) {
                ((__half2*)C)[o0 >> 1] = __floats2half2_rn(v0.x * scale, v0.y * scale);
                ((__half2*)C)[o1 >> 1] = __floats2half2_rn(v1.x * scale, v1.y * scale);
            } else {
                *(float2*)&((float*)C)[o0] = v0;
                *(float2*)&((float*)C)[o1] = v1;
            }
        }
    }
}

template <bool RELU, bool ADD, int OUTK>
__global__ __launch_bounds__(256, 2)
void gemmh(const __half* __restrict__ A, const __half* __restrict__ B,
           const float* __restrict__ Cadd, void* __restrict__ C,
           int N, int K) {
    gemmh_core<RELU, ADD, OUTK>(A, B, Cadd, C, N, K, blockIdx.y * 128, blockIdx.x * 128, 1.0f);
}

// Fused QKV: grid.x = 3 * (DMODEL/128); block picks its weight/output. fp16 outs.
// q output pre-scaled by QK_SCALE_LOG2 (folds softmax scale into the GEMM).
__global__ __launch_bounds__(256, 2)
void gemmh_qkv(const __half* __restrict__ A,
               const __half* __restrict__ Wq, const __half* __restrict__ Wk,
               const __half* __restrict__ Wv,
               __half* __restrict__ Cq, __half* __restrict__ Ck, __half* __restrict__ Cv) {
    const int nblk = DMODEL / 128;           // 6
    const int which = blockIdx.x / nblk;
    const int n0 = (blockIdx.x % nblk) * 128;
    const __half* B = (which == 0) ? Wq : (which == 1) ? Wk : Wv;
    __half* C = (which == 0) ? Cq : (which == 1) ? Ck : Cv;
    const float scale = (which == 0) ? QK_SCALE_LOG2 : 1.0f;
    gemmh_core<false, false, 2>(A, B, nullptr, C, DMODEL, DMODEL, blockIdx.y * 128, n0, scale);
}

// ---------------- fp16 tensor-core flash attention ----------------
// grid (SEQ/128, NHEADS, BATCH), 256 threads = 8 warps; warp owns 16 q-rows.
// 3-stage K/V cp.async pipeline, ONE __syncthreads per key tile.
// P built in registers from the S accumulator; q pre-scaled (no in-loop scale).
#define AH_STR 72
#define AH_TILE (64 * AH_STR)               // halves per 64-row K or V tile
#define AH_Q_OFF (2 * PIPE_DEPTH * AH_TILE) // after PIPE_DEPTH x (K,V)
#define AH_SMEM_BYTES ((2 * PIPE_DEPTH * AH_TILE + 128 * AH_STR) * 2)   // 73728

__global__ __launch_bounds__(256, 2)
void attn_h(const __half* __restrict__ Q, const __half* __restrict__ K,
            const __half* __restrict__ V, __half* __restrict__ O) {
    extern __shared__ __half smah[];
    __half* QP = smah + AH_Q_OFF;            // Q staging (128 rows)

    const int tid = threadIdx.x;             // 256
    const int b = blockIdx.z, h = blockIdx.y;
    const int q0 = blockIdx.x * 128;
    const int warp = tid >> 5, lane = tid & 31;
    const int gid = lane >> 2, tig = lane & 3;
    const int lr = lane & 15, lc = lane >> 4;
    const int wm = warp * 16;

    const __half* qbase = Q + (size_t)b * SEQ * DMODEL + h * DHEAD;
    const __half* kbase = K + (size_t)b * SEQ * DMODEL + h * DHEAD;
    const __half* vbase = V + (size_t)b * SEQ * DMODEL + h * DHEAD;

    // stage Q tile: 128 rows x 64 halves = 1024 16B-chunks
    for (int i = tid; i < 1024; i += 256) {
        int r = i >> 3, c8 = (i & 7) * 8;
        *(uint4*)&QP[r * AH_STR + c8] = *(const uint4*)&qbase[(size_t)(q0 + r) * DMODEL + c8];
    }
    auto loadKV = [&](int t, int st) {
        __half* ks = smah + 2 * st * AH_TILE;
        __half* vs = ks + AH_TILE;
        const int j0 = t * 64;
        #pragma unroll
        for (int i = 0; i < 2; i++) {
            int c = tid + 256 * i;           // 512 chunks per tensor
            int r = c >> 3, c8 = (c & 7) * 8;
            CP_ASYNC16(smem_u32(ks + r * AH_STR + c8), kbase + (size_t)(j0 + r) * DMODEL + c8);
            CP_ASYNC16(smem_u32(vs + r * AH_STR + c8), vbase + (size_t)(j0 + r) * DMODEL + c8);
        }
    };
    loadKV(0, 0); CP_COMMIT();
    loadKV(1, 1); CP_COMMIT();
    __syncthreads();                          // Q tile visible

    // preload Q fragments (4 k16 chunks); values already scaled by 0.125*log2e
    const uint32_t qb = smem_u32(QP);
    uint32_t qf[4][4];
    #pragma unroll
    for (int kc = 0; kc < 4; kc++)
        LDSM_X4(qf[kc], qb + ((wm + lr) * AH_STR + kc * 16 + 8 * lc) * 2);

    float m0r = -1e30f, m1r = -1e30f, l0 = 0.f, l1 = 0.f;  // log2-domain maxima
    float o[8][4] = {};

    const int NT = SEQ / 64;
    for (int t = 0; t < NT; t++) {
        const int st = t % PIPE_DEPTH;
        if (t < NT - 1) { CP_WAIT(1); } else { CP_WAIT(0); }
        __syncthreads();
        if (t + 2 < NT) { loadKV(t + 2, (t + 2) % PIPE_DEPTH); CP_COMMIT(); }

        const uint32_t kb = smem_u32(smah + 2 * st * AH_TILE);
        const uint32_t vb = kb + AH_TILE * 2;

        // S = Q * K^T (warp: 16 x 64), already in log2 domain
        float s[8][4] = {};
        #pragma unroll
        for (int kc = 0; kc < 4; kc++) {
            #pragma unroll
            for (int nt = 0; nt < 4; nt++) {
                uint32_t kf[4];
                LDSM_X4(kf, kb + ((nt * 16 + lr) * AH_STR + kc * 16 + 8 * lc) * 2);
                uint32_t b0[2] = { kf[0], kf[2] }, b1[2] = { kf[1], kf[3] };
                mma_f16(s[2 * nt],     qf[kc], b0);
                mma_f16(s[2 * nt + 1], qf[kc], b1);
            }
        }

        // row-max
        float mx0 = -1e30f, mx1 = -1e30f;
        #pragma unroll
        for (int j = 0; j < 8; j++) {
            mx0 = fmaxf(mx0, fmaxf(s[j][0], s[j][1]));
            mx1 = fmaxf(mx1, fmaxf(s[j][2], s[j][3]));
        }
        mx0 = fmaxf(mx0, __shfl_xor_sync(0xffffffffu, mx0, 1));
        mx0 = fmaxf(mx0, __shfl_xor_sync(0xffffffffu, mx0, 2));
        mx1 = fmaxf(mx1, __shfl_xor_sync(0xffffffffu, mx1, 1));
        mx1 = fmaxf(mx1, __shfl_xor_sync(0xffffffffu, mx1, 2));

        const float mn0 = fmaxf(m0r, mx0), mn1 = fmaxf(m1r, mx1);
        const float al0 = exp2f(m0r - mn0), al1 = exp2f(m1r - mn1);
        m0r = mn0; m1r = mn1;

        // p = 2^(s - mn); build PV A-fragments directly in registers
        uint32_t pf[4][4];
        float ls0 = 0.f, ls1 = 0.f;
        #pragma unroll
        for (int j = 0; j < 8; j++) {
            float p0 = exp2f(s[j][0] - mn0);
            float p1 = exp2f(s[j][1] - mn0);
            float p2 = exp2f(s[j][2] - mn1);
            float p3 = exp2f(s[j][3] - mn1);
            ls0 += p0 + p1; ls1 += p2 + p3;
            pf[j >> 1][(j & 1) * 2]     = pack_h2(p0, p1);   // rows gid
            pf[j >> 1][(j & 1) * 2 + 1] = pack_h2(p2, p3);   // rows gid+8
        }
        ls0 += __shfl_xor_sync(0xffffffffu, ls0, 1);
        ls0 += __shfl_xor_sync(0xffffffffu, ls0, 2);
        ls1 += __shfl_xor_sync(0xffffffffu, ls1, 1);
        ls1 += __shfl_xor_sync(0xffffffffu, ls1, 2);
        l0 = l0 * al0 + ls0;
        l1 = l1 * al1 + ls1;

        #pragma unroll
        for (int j = 0; j < 8; j++) {
            o[j][0] *= al0; o[j][1] *= al0; o[j][2] *= al1; o[j][3] *= al1;
        }

        // O += P * V (warp: 16 x 64; k = keys)
        #pragma unroll
        for (int kc = 0; kc < 4; kc++) {
            #pragma unroll
            for (int nt = 0; nt < 4; nt++) {
                uint32_t vf[4];
                LDSM_X4_T(vf, vb + ((kc * 16 + lr) * AH_STR + nt * 16 + 8 * lc) * 2);
                mma_f16(o[2 * nt],     pf[kc], vf);
                mma_f16(o[2 * nt + 1], pf[kc], vf + 2);
            }
        }
    }

    const float inv0 = 1.0f / l0, inv1 = 1.0f / l1;
    __half* ob0 = O + ((size_t)b * SEQ + q0 + wm + gid) * DMODEL + h * DHEAD;
    __half* ob1 = O + ((size_t)b * SEQ + q0 + wm + gid + 8) * DMODEL + h * DHEAD;
    #pragma unroll
    for (int j = 0; j < 8; j++) {
        *(__half2*)&ob0[j * 8 + 2 * tig] = __floats2half2_rn(o[j][0] * inv0, o[j][1] * inv0);
        *(__half2*)&ob1[j * 8 + 2 * tig] = __floats2half2_rn(o[j][2] * inv1, o[j][3] * inv1);
    }
}

// ---------------- launch ----------------
extern "C" void kernel_launch(void* const* d_in, const int* in_sizes, int n_in,
                              void* d_out, int out_size) {
    const float* x      = (const float*)d_in[0];
    const float* Wq     = (const float*)d_in[1];
    const float* Wk     = (const float*)d_in[2];
    const float* Wv     = (const float*)d_in[3];
    const float* Wo     = (const float*)d_in[4];
    const float* W1     = (const float*)d_in[5];
    const float* W2     = (const float*)d_in[6];
    const float* gamma1 = (const float*)d_in[7];
    const float* beta1  = (const float*)d_in[8];
    const float* gamma2 = (const float*)d_in[9];
    const float* beta2  = (const float*)d_in[10];
    float* out = (float*)d_out;

    __half *h, *q, *k, *v, *ctx, *h2, *mid, *wqh, *wkh, *wvh, *woh, *w1h, *w2h;
    float *res1;
    cudaGetSymbolAddress((void**)&h,    g_h);
    cudaGetSymbolAddress((void**)&q,    g_q);
    cudaGetSymbolAddress((void**)&k,    g_k);
    cudaGetSymbolAddress((void**)&v,    g_v);
    cudaGetSymbolAddress((void**)&ctx,  g_ctx);
    cudaGetSymbolAddress((void**)&res1, g_res1);
    cudaGetSymbolAddress((void**)&h2,   g_h2);
    cudaGetSymbolAddress((void**)&mid,  g_mid);
    cudaGetSymbolAddress((void**)&wqh,  g_wqh);
    cudaGetSymbolAddress((void**)&wkh,  g_wkh);
    cudaGetSymbolAddress((void**)&wvh,  g_wvh);
    cudaGetSymbolAddress((void**)&woh,  g_woh);
    cudaGetSymbolAddress((void**)&w1h,  g_w1h);
    cudaGetSymbolAddress((void**)&w2h,  g_w2h);

    cudaFuncSetAttribute(attn_h, cudaFuncAttributeMaxDynamicSharedMemorySize, AH_SMEM_BYTES);
    cudaFuncSetAttribute(gemmh<false, true, 0>, cudaFuncAttributeMaxDynamicSharedMemorySize, HG_SMEM_BYTES);
    cudaFuncSetAttribute(gemmh<true, false, 2>, cudaFuncAttributeMaxDynamicSharedMemorySize, HG_SMEM_BYTES);
    cudaFuncSetAttribute(gemmh_qkv, cudaFuncAttributeMaxDynamicSharedMemorySize, HG_SMEM_BYTES);

    // 0. convert all weights fp32 -> fp16 (single launch)
    cvt_all<<<dim3((CVT_DH + 255) / 256, 6), 256>>>(Wq, Wk, Wv, Wo, W1, W2,
                                                    wqh, wkh, wvh, woh, w1h, w2h);

    // 1. LN1 -> h (fp16)
    layernorm_kernel<<<NTOK, 256>>>(x, gamma1, beta1, h);

    // 2. fused QKV projection -> q,k,v (fp16; q pre-scaled)
    gemmh_qkv<<<dim3(3 * DMODEL / 128, NTOK / 128), 256, HG_SMEM_BYTES>>>(h, wqh, wkh, wvh, q, k, v);

    // 3. attention -> ctx (fp16)
    attn_h<<<dim3(SEQ / 128, NHEADS, BATCH), 256, AH_SMEM_BYTES>>>(q, k, v, ctx);

    // 4. output projection + residual: res1 = x + ctx @ Wo (fp32)
    gemmh<false, true, 0><<<dim3(DMODEL / 128, NTOK / 128), 256, HG_SMEM_BYTES>>>(ctx, woh, x, res1, DMODEL, DMODEL);

    // 5. LN2 -> h2 (fp16)
    layernorm_kernel<<<NTOK, 256>>>(res1, gamma2, beta2, h2);

    // 6. FFN
    gemmh<true, false, 2><<<dim3(DHID / 128, NTOK / 128), 256, HG_SMEM_BYTES>>>(h2, w1h, nullptr, mid, DHID, DMODEL);
    gemmh<false, true, 0><<<dim3(DMODEL / 128, NTOK / 128), 256, HG_SMEM_BYTES>>>(mid, w2h, res1, out, DMODEL, DHID);
}